// round 1
// baseline (speedup 1.0000x reference)
#include <cuda_runtime.h>
#include <cuda_bf16.h>
#include <math.h>

#define NODES_MAX 100000
#define EDGES_MAX 1600000
#define D 128
#define H 8
#define F 512

// ---------------- scratch (static device globals; no allocation allowed) ----
__device__ float g_q[NODES_MAX * D];
__device__ float g_k[NODES_MAX * D];
__device__ float g_v[NODES_MAX * D];
__device__ float g_e[EDGES_MAX * H];
__device__ float g_emax[NODES_MAX * H];
__device__ float g_denom[NODES_MAX * H];
__device__ float g_rst[NODES_MAX * D];
__device__ float g_rstln[NODES_MAX * D];
__device__ float g_h[NODES_MAX * F];
__device__ float g_ffn[NODES_MAX * D];

// ---------------- SGEMM: C[M,N] = A[M,K] @ B[K,N] + bias, optional PReLU ----
#define BM 64
#define BN 64
#define BK 16

__global__ void sgemm_bias(const float* __restrict__ A, const float* __restrict__ B,
                           const float* __restrict__ bias, const float* __restrict__ alpha,
                           float* __restrict__ C, int M, int N, int K) {
    __shared__ float As[BK][BM + 4];
    __shared__ float Bs[BK][BN];
    const int tid = threadIdx.x;           // 128 threads
    const int row0 = blockIdx.x * BM;
    const int col0 = blockIdx.y * BN;
    const int ty = tid >> 3;               // 0..15
    const int tx = tid & 7;                // 0..7

    const int a_r = tid >> 2;              // 0..31
    const int a_c = (tid & 3) * 4;         // 0,4,8,12
    const int b_r = tid >> 4;              // 0..7
    const int b_c = (tid & 15) * 4;        // 0..60

    float acc[4][8];
#pragma unroll
    for (int i = 0; i < 4; i++)
#pragma unroll
        for (int j = 0; j < 8; j++) acc[i][j] = 0.0f;

    for (int k0 = 0; k0 < K; k0 += BK) {
#pragma unroll
        for (int i = 0; i < 2; i++) {
            int r = a_r + i * 32;
            int gr = row0 + r;
            float4 av = make_float4(0.f, 0.f, 0.f, 0.f);
            if (gr < M) av = *(const float4*)(A + (size_t)gr * K + k0 + a_c);
            As[a_c + 0][r] = av.x;
            As[a_c + 1][r] = av.y;
            As[a_c + 2][r] = av.z;
            As[a_c + 3][r] = av.w;
        }
#pragma unroll
        for (int i = 0; i < 2; i++) {
            int r = b_r + i * 8;
            float4 bv = *(const float4*)(B + (size_t)(k0 + r) * N + col0 + b_c);
            *(float4*)&Bs[r][b_c] = bv;
        }
        __syncthreads();
#pragma unroll
        for (int k = 0; k < BK; k++) {
            float4 a4 = *(const float4*)&As[k][ty * 4];
            float4 b0 = *(const float4*)&Bs[k][tx * 8];
            float4 b1 = *(const float4*)&Bs[k][tx * 8 + 4];
            float a[4] = {a4.x, a4.y, a4.z, a4.w};
            float b[8] = {b0.x, b0.y, b0.z, b0.w, b1.x, b1.y, b1.z, b1.w};
#pragma unroll
            for (int i = 0; i < 4; i++)
#pragma unroll
                for (int j = 0; j < 8; j++) acc[i][j] += a[i] * b[j];
        }
        __syncthreads();
    }

#pragma unroll
    for (int i = 0; i < 4; i++) {
        int gr = row0 + ty * 4 + i;
        if (gr >= M) continue;
#pragma unroll
        for (int j = 0; j < 8; j += 4) {
            int gc = col0 + tx * 8 + j;
            float4 o;
            o.x = acc[i][j + 0] + bias[gc + 0];
            o.y = acc[i][j + 1] + bias[gc + 1];
            o.z = acc[i][j + 2] + bias[gc + 2];
            o.w = acc[i][j + 3] + bias[gc + 3];
            if (alpha) {
                o.x = o.x > 0.f ? o.x : alpha[gc + 0] * o.x;
                o.y = o.y > 0.f ? o.y : alpha[gc + 1] * o.y;
                o.z = o.z > 0.f ? o.z : alpha[gc + 2] * o.z;
                o.w = o.w > 0.f ? o.w : alpha[gc + 3] * o.w;
            }
            *(float4*)(C + (size_t)gr * N + gc) = o;
        }
    }
}

// ---------------- edge kernels --------------------------------------------
__device__ __forceinline__ void atomicMaxFloat(float* addr, float val) {
    if (val >= 0.0f)
        atomicMax((int*)addr, __float_as_int(val));
    else
        atomicMin((unsigned int*)addr, __float_as_uint(val));
}

__global__ void init_softmax(float* __restrict__ emax, float* __restrict__ denom, int n) {
    int i = blockIdx.x * blockDim.x + threadIdx.x;
    if (i < n) {
        emax[i] = -INFINITY;
        denom[i] = 0.0f;
    }
}

// score per (edge, head): e = <k[src], q[dst]>_head / sqrt(D); atomicMax into emax[dst]
__global__ void edge_scores(const float* __restrict__ q, const float* __restrict__ k,
                            const int* __restrict__ src, const int* __restrict__ dst,
                            float* __restrict__ eb, float* __restrict__ emax, int E) {
    int idx = blockIdx.x * blockDim.x + threadIdx.x;
    if (idx >= E * H) return;
    int e = idx >> 3;
    int h = idx & 7;
    int s = src[e];
    int d = dst[e];
    const float4* kp = (const float4*)(k + (size_t)s * D + h * 16);
    const float4* qp = (const float4*)(q + (size_t)d * D + h * 16);
    float acc = 0.0f;
#pragma unroll
    for (int i = 0; i < 4; i++) {
        float4 kv = kp[i];
        float4 qv = qp[i];
        acc += kv.x * qv.x + kv.y * qv.y + kv.z * qv.z + kv.w * qv.w;
    }
    acc *= 0.08838834764831843f;  // 1/sqrt(128)
    eb[idx] = acc;
    atomicMaxFloat(&emax[(size_t)d * H + h], acc);
}

__global__ void edge_exp(float* __restrict__ eb, const float* __restrict__ emax,
                         float* __restrict__ denom, const int* __restrict__ dst, int E) {
    int idx = blockIdx.x * blockDim.x + threadIdx.x;
    if (idx >= E * H) return;
    int e = idx >> 3;
    int h = idx & 7;
    int d = dst[e];
    float ex = expf(eb[idx] - emax[(size_t)d * H + h]);
    eb[idx] = ex;
    atomicAdd(&denom[(size_t)d * H + h], ex);
}

// weighted scatter: rst[dst] += v[src] * (ex / denom[dst]); 32 threads per edge
__global__ void edge_agg(const float* __restrict__ eb, const float* __restrict__ denom,
                         const float* __restrict__ v, const int* __restrict__ src,
                         const int* __restrict__ dst, float* __restrict__ rst, int E) {
    int idx = blockIdx.x * blockDim.x + threadIdx.x;
    int e = idx >> 5;
    if (e >= E) return;
    int lane = idx & 31;
    int h = lane >> 2;
    int s = src[e];
    int d = dst[e];
    float a = eb[(size_t)e * H + h] / denom[(size_t)d * H + h];
    float4 vv = *(const float4*)(v + (size_t)s * D + lane * 4);
    float* p = rst + (size_t)d * D + lane * 4;
    asm volatile("red.global.add.v4.f32 [%0], {%1,%2,%3,%4};" ::"l"(p), "f"(vv.x * a),
                 "f"(vv.y * a), "f"(vv.z * a), "f"(vv.w * a)
                 : "memory");
}

// ---------------- layernorm (warp per row, optional residual add) ----------
__global__ void ln_kernel(const float* __restrict__ x, const float* __restrict__ add,
                          const float* __restrict__ g, const float* __restrict__ b,
                          float* __restrict__ out, int n) {
    int row = blockIdx.x * 4 + (threadIdx.x >> 5);
    if (row >= n) return;
    int lane = threadIdx.x & 31;
    float4 vx = *(const float4*)(x + (size_t)row * D + lane * 4);
    if (add) {
        float4 av = *(const float4*)(add + (size_t)row * D + lane * 4);
        vx.x += av.x;
        vx.y += av.y;
        vx.z += av.z;
        vx.w += av.w;
    }
    float s = vx.x + vx.y + vx.z + vx.w;
    float s2 = vx.x * vx.x + vx.y * vx.y + vx.z * vx.z + vx.w * vx.w;
#pragma unroll
    for (int o = 16; o > 0; o >>= 1) {
        s += __shfl_xor_sync(0xffffffffu, s, o);
        s2 += __shfl_xor_sync(0xffffffffu, s2, o);
    }
    float mean = s * (1.0f / D);
    float var = s2 * (1.0f / D) - mean * mean;
    float rstd = rsqrtf(var + 1e-5f);
    float4 gv = *(const float4*)(g + lane * 4);
    float4 bv = *(const float4*)(b + lane * 4);
    float4 o;
    o.x = (vx.x - mean) * rstd * gv.x + bv.x;
    o.y = (vx.y - mean) * rstd * gv.y + bv.y;
    o.z = (vx.z - mean) * rstd * gv.z + bv.z;
    o.w = (vx.w - mean) * rstd * gv.w + bv.w;
    *(float4*)(out + (size_t)row * D + lane * 4) = o;
}

// ---------------- launch ----------------------------------------------------
extern "C" void kernel_launch(void* const* d_in, const int* in_sizes, int n_in,
                              void* d_out, int out_size) {
    const float* feat = (const float*)d_in[0];
    const int* src = (const int*)d_in[1];
    const int* dst = (const int*)d_in[2];
    const float* Wq = (const float*)d_in[3];
    const float* bq = (const float*)d_in[4];
    const float* Wk = (const float*)d_in[5];
    const float* bk = (const float*)d_in[6];
    const float* Wv = (const float*)d_in[7];
    const float* bv = (const float*)d_in[8];
    const float* ln_g = (const float*)d_in[9];
    const float* ln_b = (const float*)d_in[10];
    const float* W1 = (const float*)d_in[11];
    const float* b1 = (const float*)d_in[12];
    const float* alpha = (const float*)d_in[13];
    const float* W2 = (const float*)d_in[14];
    const float* b2 = (const float*)d_in[15];

    const int N = in_sizes[0] / D;
    const int E = in_sizes[1];

    float *q, *k, *v, *eb, *emax, *denom, *rst, *rstln, *hb, *ffn;
    cudaGetSymbolAddress((void**)&q, g_q);
    cudaGetSymbolAddress((void**)&k, g_k);
    cudaGetSymbolAddress((void**)&v, g_v);
    cudaGetSymbolAddress((void**)&eb, g_e);
    cudaGetSymbolAddress((void**)&emax, g_emax);
    cudaGetSymbolAddress((void**)&denom, g_denom);
    cudaGetSymbolAddress((void**)&rst, g_rst);
    cudaGetSymbolAddress((void**)&rstln, g_rstln);
    cudaGetSymbolAddress((void**)&hb, g_h);
    cudaGetSymbolAddress((void**)&ffn, g_ffn);

    dim3 blk(128);
    int mgrid = (N + BM - 1) / BM;

    // q/k/v projections
    sgemm_bias<<<dim3(mgrid, D / BN), blk>>>(feat, Wq, bq, nullptr, q, N, D, D);
    sgemm_bias<<<dim3(mgrid, D / BN), blk>>>(feat, Wk, bk, nullptr, k, N, D, D);
    sgemm_bias<<<dim3(mgrid, D / BN), blk>>>(feat, Wv, bv, nullptr, v, N, D, D);

    // softmax state init + rst = feat (absorbs residual into scatter target)
    init_softmax<<<(N * H + 255) / 256, 256>>>(emax, denom, N * H);
    cudaMemcpyAsync(rst, feat, (size_t)N * D * sizeof(float), cudaMemcpyDeviceToDevice, 0);

    // edge attention
    edge_scores<<<((size_t)E * H + 255) / 256, 256>>>(q, k, src, dst, eb, emax, E);
    edge_exp<<<((size_t)E * H + 255) / 256, 256>>>(eb, emax, denom, dst, E);
    edge_agg<<<((size_t)E * 32 + 255) / 256, 256>>>(eb, denom, v, src, dst, rst, E);

    // LN1
    ln_kernel<<<(N + 3) / 4, 128>>>(rst, nullptr, ln_g, ln_b, rstln, N);

    // FFN
    sgemm_bias<<<dim3(mgrid, F / BN), blk>>>(rstln, W1, b1, alpha, hb, N, F, D);
    sgemm_bias<<<dim3(mgrid, D / BN), blk>>>(hb, W2, b2, nullptr, ffn, N, D, F);

    // out = LN(rstln + ffn)
    ln_kernel<<<(N + 3) / 4, 128>>>(rstln, ffn, ln_g, ln_b, (float*)d_out, N);
}

// round 2
// speedup vs baseline: 2.1143x; 2.1143x over previous
#include <cuda_runtime.h>
#include <cuda_bf16.h>
#include <math.h>
#include <stdint.h>

#define NODES_MAX 100000
#define EDGES_MAX 1600000
#define D 128
#define H 8
#define F 512

// ---------------- scratch (static device globals; no allocation allowed) ----
__device__ float g_q[NODES_MAX * D];
__device__ float g_k[NODES_MAX * D];
__device__ float g_v[NODES_MAX * D];
__device__ float g_e[EDGES_MAX * H];
__device__ float g_denom[NODES_MAX * H];
__device__ float g_rst[NODES_MAX * D];
__device__ float g_rstln[NODES_MAX * D];
__device__ float g_h[NODES_MAX * F];
__device__ float g_ffn[NODES_MAX * D];

// ---------------- tf32 tensor-core GEMM ------------------------------------
// C[M,N] = A[M,K] @ B[K,N] + bias, optional per-channel PReLU.
// CTA tile 128x128x32, 8 warps (2x4), warp tile 64x32, mma.m16n8k8.tf32.

#define TBM 128
#define TBN 128
#define TBK 32
#define ASTRIDE 36   // (4*row + col) % 32 distinct for frag loads
#define BSTRIDE 136  // (8*k + n) % 32 distinct for frag loads

__device__ __forceinline__ uint32_t f2tf32(float x) {
    uint32_t r;
    asm("cvt.rna.tf32.f32 %0, %1;" : "=r"(r) : "f"(x));
    return r;
}

__device__ __forceinline__ void mma_tf32(float* c, const uint32_t* a, const uint32_t* b) {
    asm volatile(
        "mma.sync.aligned.m16n8k8.row.col.f32.tf32.tf32.f32 "
        "{%0,%1,%2,%3}, {%4,%5,%6,%7}, {%8,%9}, {%0,%1,%2,%3};\n"
        : "+f"(c[0]), "+f"(c[1]), "+f"(c[2]), "+f"(c[3])
        : "r"(a[0]), "r"(a[1]), "r"(a[2]), "r"(a[3]), "r"(b[0]), "r"(b[1]));
}

__global__ __launch_bounds__(256, 2) void mma_gemm(
    const float* __restrict__ A, const float* __restrict__ B,
    const float* __restrict__ bias, const float* __restrict__ alpha,
    float* __restrict__ C, int M, int N, int K) {
    __shared__ uint32_t As[TBM * ASTRIDE];
    __shared__ uint32_t Bs[TBK * BSTRIDE];

    const int tid = threadIdx.x;
    const int lane = tid & 31;
    const int wid = tid >> 5;
    const int wm = wid & 1;   // 0..1 -> 64-row half
    const int wn = wid >> 1;  // 0..3 -> 32-col quarter
    const int tg = lane >> 2; // 0..7
    const int tc = lane & 3;  // 0..3

    const int row0 = blockIdx.x * TBM;
    const int col0 = blockIdx.y * TBN;

    float acc[4][4][4];
#pragma unroll
    for (int mt = 0; mt < 4; mt++)
#pragma unroll
        for (int nt = 0; nt < 4; nt++)
#pragma unroll
            for (int r = 0; r < 4; r++) acc[mt][nt][r] = 0.0f;

    for (int k0 = 0; k0 < K; k0 += TBK) {
        // A tile: 128 rows x 32 cols
#pragma unroll
        for (int p = 0; p < 4; p++) {
            int idx = p * 1024 + tid * 4;
            int r = idx >> 5;
            int c = idx & 31;
            int gr = row0 + r;
            float4 v = make_float4(0.f, 0.f, 0.f, 0.f);
            if (gr < M) v = *(const float4*)(A + (size_t)gr * K + k0 + c);
            uint32_t* p4 = &As[r * ASTRIDE + c];
            p4[0] = f2tf32(v.x);
            p4[1] = f2tf32(v.y);
            p4[2] = f2tf32(v.z);
            p4[3] = f2tf32(v.w);
        }
        // B tile: 32 rows x 128 cols
#pragma unroll
        for (int p = 0; p < 4; p++) {
            int idx = p * 1024 + tid * 4;
            int r = idx >> 7;
            int c = idx & 127;
            float4 v = *(const float4*)(B + (size_t)(k0 + r) * N + col0 + c);
            uint32_t* p4 = &Bs[r * BSTRIDE + c];
            p4[0] = f2tf32(v.x);
            p4[1] = f2tf32(v.y);
            p4[2] = f2tf32(v.z);
            p4[3] = f2tf32(v.w);
        }
        __syncthreads();

#pragma unroll
        for (int ks = 0; ks < 4; ks++) {
            const int kb = ks * 8;
            uint32_t af[4][4], bf[4][2];
#pragma unroll
            for (int mt = 0; mt < 4; mt++) {
                int mrow = wm * 64 + mt * 16;
                af[mt][0] = As[(mrow + tg) * ASTRIDE + kb + tc];
                af[mt][1] = As[(mrow + tg + 8) * ASTRIDE + kb + tc];
                af[mt][2] = As[(mrow + tg) * ASTRIDE + kb + tc + 4];
                af[mt][3] = As[(mrow + tg + 8) * ASTRIDE + kb + tc + 4];
            }
#pragma unroll
            for (int nt = 0; nt < 4; nt++) {
                int ncol = wn * 32 + nt * 8;
                bf[nt][0] = Bs[(kb + tc) * BSTRIDE + ncol + tg];
                bf[nt][1] = Bs[(kb + tc + 4) * BSTRIDE + ncol + tg];
            }
#pragma unroll
            for (int mt = 0; mt < 4; mt++)
#pragma unroll
                for (int nt = 0; nt < 4; nt++) mma_tf32(acc[mt][nt], af[mt], bf[nt]);
        }
        __syncthreads();
    }

    // epilogue: bias (+PReLU), guarded stores
#pragma unroll
    for (int mt = 0; mt < 4; mt++) {
#pragma unroll
        for (int nt = 0; nt < 4; nt++) {
            int gc = col0 + wn * 32 + nt * 8 + tc * 2;
            float b0 = bias[gc], b1 = bias[gc + 1];
            float v0 = acc[mt][nt][0] + b0;
            float v1 = acc[mt][nt][1] + b1;
            float v2 = acc[mt][nt][2] + b0;
            float v3 = acc[mt][nt][3] + b1;
            if (alpha) {
                float a0 = alpha[gc], a1 = alpha[gc + 1];
                v0 = v0 > 0.f ? v0 : a0 * v0;
                v1 = v1 > 0.f ? v1 : a1 * v1;
                v2 = v2 > 0.f ? v2 : a0 * v2;
                v3 = v3 > 0.f ? v3 : a1 * v3;
            }
            int gr = row0 + wm * 64 + mt * 16 + tg;
            if (gr < M) *(float2*)(C + (size_t)gr * N + gc) = make_float2(v0, v1);
            if (gr + 8 < M) *(float2*)(C + (size_t)(gr + 8) * N + gc) = make_float2(v2, v3);
        }
    }
}

// ---------------- edge kernels --------------------------------------------
__global__ void init_denom(float* __restrict__ denom, int n) {
    int i = blockIdx.x * blockDim.x + threadIdx.x;
    if (i < n) denom[i] = 0.0f;
}

// fused: score -> exp -> denom accumulate (softmax is shift-invariant; scores
// are O(1) so no max subtraction needed)
__global__ void edge_score_exp(const float* __restrict__ q, const float* __restrict__ k,
                               const int* __restrict__ src, const int* __restrict__ dst,
                               float* __restrict__ eb, float* __restrict__ denom, int E) {
    int idx = blockIdx.x * blockDim.x + threadIdx.x;
    if (idx >= E * H) return;
    int e = idx >> 3;
    int h = idx & 7;
    int s = src[e];
    int d = dst[e];
    const float4* kp = (const float4*)(k + (size_t)s * D + h * 16);
    const float4* qp = (const float4*)(q + (size_t)d * D + h * 16);
    float acc = 0.0f;
#pragma unroll
    for (int i = 0; i < 4; i++) {
        float4 kv = kp[i];
        float4 qv = qp[i];
        acc += kv.x * qv.x + kv.y * qv.y + kv.z * qv.z + kv.w * qv.w;
    }
    float ex = expf(acc * 0.08838834764831843f);  // 1/sqrt(128)
    eb[idx] = ex;
    atomicAdd(&denom[(size_t)d * H + h], ex);
}

// weighted scatter: rst[dst] += v[src] * (ex / denom[dst]); 32 threads per edge
__global__ void edge_agg(const float* __restrict__ eb, const float* __restrict__ denom,
                         const float* __restrict__ v, const int* __restrict__ src,
                         const int* __restrict__ dst, float* __restrict__ rst, int E) {
    int idx = blockIdx.x * blockDim.x + threadIdx.x;
    int e = idx >> 5;
    if (e >= E) return;
    int lane = idx & 31;
    int h = lane >> 2;
    int s = src[e];
    int d = dst[e];
    float a = eb[(size_t)e * H + h] / denom[(size_t)d * H + h];
    float4 vv = *(const float4*)(v + (size_t)s * D + lane * 4);
    float* p = rst + (size_t)d * D + lane * 4;
    asm volatile("red.global.add.v4.f32 [%0], {%1,%2,%3,%4};" ::"l"(p), "f"(vv.x * a),
                 "f"(vv.y * a), "f"(vv.z * a), "f"(vv.w * a)
                 : "memory");
}

// ---------------- layernorm (warp per row, optional residual add) ----------
__global__ void ln_kernel(const float* __restrict__ x, const float* __restrict__ add,
                          const float* __restrict__ g, const float* __restrict__ b,
                          float* __restrict__ out, int n) {
    int row = blockIdx.x * 4 + (threadIdx.x >> 5);
    if (row >= n) return;
    int lane = threadIdx.x & 31;
    float4 vx = *(const float4*)(x + (size_t)row * D + lane * 4);
    if (add) {
        float4 av = *(const float4*)(add + (size_t)row * D + lane * 4);
        vx.x += av.x;
        vx.y += av.y;
        vx.z += av.z;
        vx.w += av.w;
    }
    float s = vx.x + vx.y + vx.z + vx.w;
    float s2 = vx.x * vx.x + vx.y * vx.y + vx.z * vx.z + vx.w * vx.w;
#pragma unroll
    for (int o = 16; o > 0; o >>= 1) {
        s += __shfl_xor_sync(0xffffffffu, s, o);
        s2 += __shfl_xor_sync(0xffffffffu, s2, o);
    }
    float mean = s * (1.0f / D);
    float var = s2 * (1.0f / D) - mean * mean;
    float rstd = rsqrtf(var + 1e-5f);
    float4 gv = *(const float4*)(g + lane * 4);
    float4 bv = *(const float4*)(b + lane * 4);
    float4 o;
    o.x = (vx.x - mean) * rstd * gv.x + bv.x;
    o.y = (vx.y - mean) * rstd * gv.y + bv.y;
    o.z = (vx.z - mean) * rstd * gv.z + bv.z;
    o.w = (vx.w - mean) * rstd * gv.w + bv.w;
    *(float4*)(out + (size_t)row * D + lane * 4) = o;
}

// ---------------- launch ----------------------------------------------------
extern "C" void kernel_launch(void* const* d_in, const int* in_sizes, int n_in,
                              void* d_out, int out_size) {
    const float* feat = (const float*)d_in[0];
    const int* src = (const int*)d_in[1];
    const int* dst = (const int*)d_in[2];
    const float* Wq = (const float*)d_in[3];
    const float* bq = (const float*)d_in[4];
    const float* Wk = (const float*)d_in[5];
    const float* bk = (const float*)d_in[6];
    const float* Wv = (const float*)d_in[7];
    const float* bv = (const float*)d_in[8];
    const float* ln_g = (const float*)d_in[9];
    const float* ln_b = (const float*)d_in[10];
    const float* W1 = (const float*)d_in[11];
    const float* b1 = (const float*)d_in[12];
    const float* alpha = (const float*)d_in[13];
    const float* W2 = (const float*)d_in[14];
    const float* b2 = (const float*)d_in[15];

    const int N = in_sizes[0] / D;
    const int E = in_sizes[1];

    float *q, *k, *v, *eb, *denom, *rst, *rstln, *hb, *ffn;
    cudaGetSymbolAddress((void**)&q, g_q);
    cudaGetSymbolAddress((void**)&k, g_k);
    cudaGetSymbolAddress((void**)&v, g_v);
    cudaGetSymbolAddress((void**)&eb, g_e);
    cudaGetSymbolAddress((void**)&denom, g_denom);
    cudaGetSymbolAddress((void**)&rst, g_rst);
    cudaGetSymbolAddress((void**)&rstln, g_rstln);
    cudaGetSymbolAddress((void**)&hb, g_h);
    cudaGetSymbolAddress((void**)&ffn, g_ffn);

    const int mgrid = (N + TBM - 1) / TBM;

    // softmax denom init + rst = feat (absorbs residual into scatter target)
    init_denom<<<(N * H + 255) / 256, 256>>>(denom, N * H);
    cudaMemcpyAsync(rst, feat, (size_t)N * D * sizeof(float), cudaMemcpyDeviceToDevice, 0);

    // q/k/v projections (tf32 tensor cores)
    mma_gemm<<<dim3(mgrid, 1), 256>>>(feat, Wq, bq, nullptr, q, N, D, D);
    mma_gemm<<<dim3(mgrid, 1), 256>>>(feat, Wk, bk, nullptr, k, N, D, D);
    mma_gemm<<<dim3(mgrid, 1), 256>>>(feat, Wv, bv, nullptr, v, N, D, D);

    // edge attention (fused score+exp+denom, then weighted scatter)
    edge_score_exp<<<((size_t)E * H + 255) / 256, 256>>>(q, k, src, dst, eb, denom, E);
    edge_agg<<<((size_t)E * 32 + 255) / 256, 256>>>(eb, denom, v, src, dst, rst, E);

    // LN1
    ln_kernel<<<(N + 3) / 4, 128>>>(rst, nullptr, ln_g, ln_b, rstln, N);

    // FFN
    mma_gemm<<<dim3(mgrid, F / TBN), 256>>>(rstln, W1, b1, alpha, hb, N, F, D);
    mma_gemm<<<dim3(mgrid, 1), 256>>>(hb, W2, b2, nullptr, ffn, N, D, F);

    // out = LN(rstln + ffn)
    ln_kernel<<<(N + 3) / 4, 128>>>(rstln, ffn, ln_g, ln_b, (float*)d_out, N);
}

// round 3
// speedup vs baseline: 2.6037x; 1.2315x over previous
#include <cuda_runtime.h>
#include <cuda_bf16.h>
#include <math.h>
#include <stdint.h>

#define NODES_MAX 100000
#define EDGES_MAX 1600000
#define D 128
#define H 8
#define F 512

// ---------------- scratch (static device globals; no allocation allowed) ----
__device__ float g_q[NODES_MAX * D];
__device__ float g_k[NODES_MAX * D];
__device__ float g_v[NODES_MAX * D];
__device__ float g_denom[NODES_MAX * H];
__device__ float g_acc[NODES_MAX * D];
__device__ float g_rstln[NODES_MAX * D];
__device__ float g_h[NODES_MAX * F];
__device__ float g_ffn[NODES_MAX * D];

// ---------------- tf32 tensor-core GEMM, cp.async double-buffered ----------
// C[M,N] = A[M,K] @ B[K,N] + bias, optional per-channel PReLU.
// CTA tile 128x128x32, 8 warps (2x4), warp tile 64x32, mma.m16n8k8.tf32.

#define TBM 128
#define TBN 128
#define TBK 32
#define ASTRIDE 36    // conflict-free frag loads; 36*4B rows stay 16B-aligned
#define BSTRIDE 136   // 136*4B rows stay 16B-aligned
#define A_WORDS (TBM * ASTRIDE)
#define B_WORDS (TBK * BSTRIDE)
#define STAGE_WORDS (A_WORDS + B_WORDS)
#define GEMM_SMEM (2 * STAGE_WORDS * 4)

__device__ __forceinline__ uint32_t f2tf32(float x) {
    uint32_t r;
    asm("cvt.rna.tf32.f32 %0, %1;" : "=r"(r) : "f"(x));
    return r;
}

__device__ __forceinline__ void mma_tf32(float* c, const uint32_t* a, const uint32_t* b) {
    asm volatile(
        "mma.sync.aligned.m16n8k8.row.col.f32.tf32.tf32.f32 "
        "{%0,%1,%2,%3}, {%4,%5,%6,%7}, {%8,%9}, {%0,%1,%2,%3};\n"
        : "+f"(c[0]), "+f"(c[1]), "+f"(c[2]), "+f"(c[3])
        : "r"(a[0]), "r"(a[1]), "r"(a[2]), "r"(a[3]), "r"(b[0]), "r"(b[1]));
}

__device__ __forceinline__ void cp16(float* s, const float* g, bool valid) {
    uint32_t sa = (uint32_t)__cvta_generic_to_shared(s);
    int sz = valid ? 16 : 0;
    asm volatile("cp.async.cg.shared.global [%0], [%1], 16, %2;" ::"r"(sa), "l"(g), "r"(sz));
}

__global__ __launch_bounds__(256, 2) void mma_gemm(
    const float* __restrict__ A, const float* __restrict__ B,
    const float* __restrict__ bias, const float* __restrict__ alpha,
    float* __restrict__ C, int M, int N, int K) {
    extern __shared__ float sm[];

    const int tid = threadIdx.x;
    const int lane = tid & 31;
    const int wid = tid >> 5;
    const int wm = wid & 1;
    const int wn = wid >> 1;
    const int tg = lane >> 2;
    const int tc = lane & 3;

    const int row0 = blockIdx.x * TBM;
    const int col0 = blockIdx.y * TBN;

    // per-thread load coordinates (16B chunks)
    const int a_r[4] = {(tid * 4) >> 5, (1024 + tid * 4) >> 5, (2048 + tid * 4) >> 5,
                        (3072 + tid * 4) >> 5};
    const int a_c = (tid * 4) & 31;
    const int b_r[4] = {(tid * 4) >> 7, (1024 + tid * 4) >> 7, (2048 + tid * 4) >> 7,
                        (3072 + tid * 4) >> 7};
    const int b_c = (tid * 4) & 127;

    const int T = K / TBK;

    float acc[4][4][4];
#pragma unroll
    for (int mt = 0; mt < 4; mt++)
#pragma unroll
        for (int nt = 0; nt < 4; nt++)
#pragma unroll
            for (int r = 0; r < 4; r++) acc[mt][nt][r] = 0.0f;

    // prologue: stage tile 0 into buffer 0
    {
        float* sA = sm;
        float* sB = sm + A_WORDS;
#pragma unroll
        for (int p = 0; p < 4; p++) {
            int gr = row0 + a_r[p];
            cp16(&sA[a_r[p] * ASTRIDE + a_c], A + (size_t)gr * K + a_c, gr < M);
            cp16(&sB[b_r[p] * BSTRIDE + b_c], B + (size_t)b_r[p] * N + col0 + b_c, true);
        }
        asm volatile("cp.async.commit_group;");
    }

    for (int t = 0; t < T; t++) {
        // prefetch next tile into the other buffer
        if (t + 1 < T) {
            float* sA = sm + ((t + 1) & 1) * STAGE_WORDS;
            float* sB = sA + A_WORDS;
            int k0 = (t + 1) * TBK;
#pragma unroll
            for (int p = 0; p < 4; p++) {
                int gr = row0 + a_r[p];
                cp16(&sA[a_r[p] * ASTRIDE + a_c], A + (size_t)gr * K + k0 + a_c, gr < M);
                cp16(&sB[b_r[p] * BSTRIDE + b_c], B + (size_t)(k0 + b_r[p]) * N + col0 + b_c,
                     true);
            }
            asm volatile("cp.async.commit_group;");
            asm volatile("cp.async.wait_group 1;");
        } else {
            asm volatile("cp.async.wait_group 0;");
        }
        __syncthreads();

        const float* sA = sm + (t & 1) * STAGE_WORDS;
        const float* sB = sA + A_WORDS;

#pragma unroll
        for (int ks = 0; ks < 4; ks++) {
            const int kb = ks * 8;
            uint32_t af[4][4], bf[4][2];
#pragma unroll
            for (int mt = 0; mt < 4; mt++) {
                int mrow = wm * 64 + mt * 16;
                af[mt][0] = f2tf32(sA[(mrow + tg) * ASTRIDE + kb + tc]);
                af[mt][1] = f2tf32(sA[(mrow + tg + 8) * ASTRIDE + kb + tc]);
                af[mt][2] = f2tf32(sA[(mrow + tg) * ASTRIDE + kb + tc + 4]);
                af[mt][3] = f2tf32(sA[(mrow + tg + 8) * ASTRIDE + kb + tc + 4]);
            }
#pragma unroll
            for (int nt = 0; nt < 4; nt++) {
                int ncol = wn * 32 + nt * 8;
                bf[nt][0] = f2tf32(sB[(kb + tc) * BSTRIDE + ncol + tg]);
                bf[nt][1] = f2tf32(sB[(kb + tc + 4) * BSTRIDE + ncol + tg]);
            }
#pragma unroll
            for (int mt = 0; mt < 4; mt++)
#pragma unroll
                for (int nt = 0; nt < 4; nt++) mma_tf32(acc[mt][nt], af[mt], bf[nt]);
        }
        __syncthreads();
    }

    // epilogue: bias (+PReLU), guarded stores
#pragma unroll
    for (int mt = 0; mt < 4; mt++) {
#pragma unroll
        for (int nt = 0; nt < 4; nt++) {
            int gc = col0 + wn * 32 + nt * 8 + tc * 2;
            float b0 = bias[gc], b1 = bias[gc + 1];
            float v0 = acc[mt][nt][0] + b0;
            float v1 = acc[mt][nt][1] + b1;
            float v2 = acc[mt][nt][2] + b0;
            float v3 = acc[mt][nt][3] + b1;
            if (alpha) {
                float a0 = alpha[gc], a1 = alpha[gc + 1];
                v0 = v0 > 0.f ? v0 : a0 * v0;
                v1 = v1 > 0.f ? v1 : a1 * v1;
                v2 = v2 > 0.f ? v2 : a0 * v2;
                v3 = v3 > 0.f ? v3 : a1 * v3;
            }
            int gr = row0 + wm * 64 + mt * 16 + tg;
            if (gr < M) *(float2*)(C + (size_t)gr * N + gc) = make_float2(v0, v1);
            if (gr + 8 < M) *(float2*)(C + (size_t)(gr + 8) * N + gc) = make_float2(v2, v3);
        }
    }
}

// ---------------- fused edge kernel ----------------------------------------
// One warp per edge: score (8 heads, 4-lane groups) -> exp -> denom atomic
// -> unnormalized weighted scatter into acc. Normalization happens in LN1.
__global__ void edge_fused(const float* __restrict__ q, const float* __restrict__ k,
                           const float* __restrict__ v, const int* __restrict__ src,
                           const int* __restrict__ dst, float* __restrict__ denom,
                           float* __restrict__ acc, int E) {
    int e = (blockIdx.x * blockDim.x + threadIdx.x) >> 5;
    if (e >= E) return;
    int lane = threadIdx.x & 31;
    int h = lane >> 2;
    int s = src[e];
    int d = dst[e];
    float4 kv = *(const float4*)(k + (size_t)s * D + lane * 4);
    float4 qv = *(const float4*)(q + (size_t)d * D + lane * 4);
    float p = kv.x * qv.x + kv.y * qv.y + kv.z * qv.z + kv.w * qv.w;
    p += __shfl_xor_sync(0xffffffffu, p, 1);
    p += __shfl_xor_sync(0xffffffffu, p, 2);
    float ex = __expf(p * 0.08838834764831843f);  // 1/sqrt(128)
    if ((lane & 3) == 0) atomicAdd(&denom[(size_t)d * H + h], ex);
    float4 vv = *(const float4*)(v + (size_t)s * D + lane * 4);
    float* pp = acc + (size_t)d * D + lane * 4;
    asm volatile("red.global.add.v4.f32 [%0], {%1,%2,%3,%4};" ::"l"(pp), "f"(vv.x * ex),
                 "f"(vv.y * ex), "f"(vv.z * ex), "f"(vv.w * ex)
                 : "memory");
}

// ---------------- LN1: out = LN(acc/denom + feat) ---------------------------
__global__ void ln_norm_kernel(const float* __restrict__ acc, const float* __restrict__ denom,
                               const float* __restrict__ feat, const float* __restrict__ g,
                               const float* __restrict__ b, float* __restrict__ out, int n) {
    int row = blockIdx.x * 4 + (threadIdx.x >> 5);
    if (row >= n) return;
    int lane = threadIdx.x & 31;
    float inv = 1.0f / denom[(size_t)row * H + (lane >> 2)];
    float4 vx = *(const float4*)(acc + (size_t)row * D + lane * 4);
    float4 fv = *(const float4*)(feat + (size_t)row * D + lane * 4);
    vx.x = vx.x * inv + fv.x;
    vx.y = vx.y * inv + fv.y;
    vx.z = vx.z * inv + fv.z;
    vx.w = vx.w * inv + fv.w;
    float s = vx.x + vx.y + vx.z + vx.w;
    float s2 = vx.x * vx.x + vx.y * vx.y + vx.z * vx.z + vx.w * vx.w;
#pragma unroll
    for (int o = 16; o > 0; o >>= 1) {
        s += __shfl_xor_sync(0xffffffffu, s, o);
        s2 += __shfl_xor_sync(0xffffffffu, s2, o);
    }
    float mean = s * (1.0f / D);
    float var = s2 * (1.0f / D) - mean * mean;
    float rstd = rsqrtf(var + 1e-5f);
    float4 gv = *(const float4*)(g + lane * 4);
    float4 bv = *(const float4*)(b + lane * 4);
    float4 o;
    o.x = (vx.x - mean) * rstd * gv.x + bv.x;
    o.y = (vx.y - mean) * rstd * gv.y + bv.y;
    o.z = (vx.z - mean) * rstd * gv.z + bv.z;
    o.w = (vx.w - mean) * rstd * gv.w + bv.w;
    *(float4*)(out + (size_t)row * D + lane * 4) = o;
}

// ---------------- LN2: out = LN(x + add) ------------------------------------
__global__ void ln_kernel(const float* __restrict__ x, const float* __restrict__ add,
                          const float* __restrict__ g, const float* __restrict__ b,
                          float* __restrict__ out, int n) {
    int row = blockIdx.x * 4 + (threadIdx.x >> 5);
    if (row >= n) return;
    int lane = threadIdx.x & 31;
    float4 vx = *(const float4*)(x + (size_t)row * D + lane * 4);
    float4 av = *(const float4*)(add + (size_t)row * D + lane * 4);
    vx.x += av.x;
    vx.y += av.y;
    vx.z += av.z;
    vx.w += av.w;
    float s = vx.x + vx.y + vx.z + vx.w;
    float s2 = vx.x * vx.x + vx.y * vx.y + vx.z * vx.z + vx.w * vx.w;
#pragma unroll
    for (int o = 16; o > 0; o >>= 1) {
        s += __shfl_xor_sync(0xffffffffu, s, o);
        s2 += __shfl_xor_sync(0xffffffffu, s2, o);
    }
    float mean = s * (1.0f / D);
    float var = s2 * (1.0f / D) - mean * mean;
    float rstd = rsqrtf(var + 1e-5f);
    float4 gv = *(const float4*)(g + lane * 4);
    float4 bv = *(const float4*)(b + lane * 4);
    float4 o;
    o.x = (vx.x - mean) * rstd * gv.x + bv.x;
    o.y = (vx.y - mean) * rstd * gv.y + bv.y;
    o.z = (vx.z - mean) * rstd * gv.z + bv.z;
    o.w = (vx.w - mean) * rstd * gv.w + bv.w;
    *(float4*)(out + (size_t)row * D + lane * 4) = o;
}

// ---------------- launch ----------------------------------------------------
extern "C" void kernel_launch(void* const* d_in, const int* in_sizes, int n_in,
                              void* d_out, int out_size) {
    const float* feat = (const float*)d_in[0];
    const int* src = (const int*)d_in[1];
    const int* dst = (const int*)d_in[2];
    const float* Wq = (const float*)d_in[3];
    const float* bq = (const float*)d_in[4];
    const float* Wk = (const float*)d_in[5];
    const float* bk = (const float*)d_in[6];
    const float* Wv = (const float*)d_in[7];
    const float* bv = (const float*)d_in[8];
    const float* ln_g = (const float*)d_in[9];
    const float* ln_b = (const float*)d_in[10];
    const float* W1 = (const float*)d_in[11];
    const float* b1 = (const float*)d_in[12];
    const float* alpha = (const float*)d_in[13];
    const float* W2 = (const float*)d_in[14];
    const float* b2 = (const float*)d_in[15];

    const int N = in_sizes[0] / D;
    const int E = in_sizes[1];

    float *q, *k, *v, *denom, *acc, *rstln, *hb, *ffn;
    cudaGetSymbolAddress((void**)&q, g_q);
    cudaGetSymbolAddress((void**)&k, g_k);
    cudaGetSymbolAddress((void**)&v, g_v);
    cudaGetSymbolAddress((void**)&denom, g_denom);
    cudaGetSymbolAddress((void**)&acc, g_acc);
    cudaGetSymbolAddress((void**)&rstln, g_rstln);
    cudaGetSymbolAddress((void**)&hb, g_h);
    cudaGetSymbolAddress((void**)&ffn, g_ffn);

    static int smem_set = 0;
    if (!smem_set) {
        cudaFuncSetAttribute(mma_gemm, cudaFuncAttributeMaxDynamicSharedMemorySize, GEMM_SMEM);
        smem_set = 1;
    }

    const int mgrid = (N + TBM - 1) / TBM;

    // zero softmax denom + scatter accumulator
    cudaMemsetAsync(denom, 0, (size_t)N * H * sizeof(float), 0);
    cudaMemsetAsync(acc, 0, (size_t)N * D * sizeof(float), 0);

    // q/k/v projections (tf32 tensor cores, double-buffered cp.async)
    mma_gemm<<<dim3(mgrid, 1), 256, GEMM_SMEM>>>(feat, Wq, bq, nullptr, q, N, D, D);
    mma_gemm<<<dim3(mgrid, 1), 256, GEMM_SMEM>>>(feat, Wk, bk, nullptr, k, N, D, D);
    mma_gemm<<<dim3(mgrid, 1), 256, GEMM_SMEM>>>(feat, Wv, bv, nullptr, v, N, D, D);

    // fused edge attention (score+exp+denom+scatter in one pass)
    edge_fused<<<((size_t)E * 32 + 255) / 256, 256>>>(q, k, v, src, dst, denom, acc, E);

    // LN1 with per-head normalization + residual
    ln_norm_kernel<<<(N + 3) / 4, 128>>>(acc, denom, feat, ln_g, ln_b, rstln, N);

    // FFN
    mma_gemm<<<dim3(mgrid, F / TBN), 256, GEMM_SMEM>>>(rstln, W1, b1, alpha, hb, N, F, D);
    mma_gemm<<<dim3(mgrid, 1), 256, GEMM_SMEM>>>(hb, W2, b2, nullptr, ffn, N, D, F);

    // out = LN(rstln + ffn)
    ln_kernel<<<(N + 3) / 4, 128>>>(rstln, ffn, ln_g, ln_b, (float*)d_out, N);
}

// round 4
// speedup vs baseline: 2.8621x; 1.0992x over previous
#include <cuda_runtime.h>
#include <cuda_bf16.h>
#include <math.h>
#include <stdint.h>

#define NODES_MAX 100000
#define EDGES_MAX 1600000
#define D 128
#define H 8
#define F 512

// ---------------- scratch (static device globals; no allocation allowed) ----
__device__ __nv_bfloat16 g_q16[NODES_MAX * D];
__device__ __nv_bfloat16 g_k16[NODES_MAX * D];
__device__ float g_v[NODES_MAX * D];
__device__ float g_denom[NODES_MAX * H];
__device__ float g_acc[NODES_MAX * D];
__device__ float g_rstln[NODES_MAX * D];
__device__ float g_h[NODES_MAX * F];
__device__ float g_ffn[NODES_MAX * D];

// ---------------- tf32 tensor-core GEMM, cp.async double-buffered ----------
// C[M,N] = A[M,K] @ B[K,N] + bias, optional per-channel PReLU.
// CTA tile 128x128x32, 8 warps (2x4), warp tile 64x32, mma.m16n8k8.tf32.
// out_bf16: store C as bf16 (for q/k consumed only by the edge phase).

#define TBM 128
#define TBN 128
#define TBK 32
#define ASTRIDE 36
#define BSTRIDE 136
#define A_WORDS (TBM * ASTRIDE)
#define B_WORDS (TBK * BSTRIDE)
#define STAGE_WORDS (A_WORDS + B_WORDS)
#define GEMM_SMEM (2 * STAGE_WORDS * 4)

__device__ __forceinline__ uint32_t f2tf32(float x) {
    uint32_t r;
    asm("cvt.rna.tf32.f32 %0, %1;" : "=r"(r) : "f"(x));
    return r;
}

__device__ __forceinline__ void mma_tf32(float* c, const uint32_t* a, const uint32_t* b) {
    asm volatile(
        "mma.sync.aligned.m16n8k8.row.col.f32.tf32.tf32.f32 "
        "{%0,%1,%2,%3}, {%4,%5,%6,%7}, {%8,%9}, {%0,%1,%2,%3};\n"
        : "+f"(c[0]), "+f"(c[1]), "+f"(c[2]), "+f"(c[3])
        : "r"(a[0]), "r"(a[1]), "r"(a[2]), "r"(a[3]), "r"(b[0]), "r"(b[1]));
}

__device__ __forceinline__ void cp16(float* s, const float* g, bool valid) {
    uint32_t sa = (uint32_t)__cvta_generic_to_shared(s);
    int sz = valid ? 16 : 0;
    asm volatile("cp.async.cg.shared.global [%0], [%1], 16, %2;" ::"r"(sa), "l"(g), "r"(sz));
}

__global__ __launch_bounds__(256, 2) void mma_gemm(
    const float* __restrict__ A, const float* __restrict__ B,
    const float* __restrict__ bias, const float* __restrict__ alpha,
    float* __restrict__ C, __nv_bfloat16* __restrict__ C16, int M, int N, int K) {
    extern __shared__ float sm[];

    const int tid = threadIdx.x;
    const int lane = tid & 31;
    const int wid = tid >> 5;
    const int wm = wid & 1;
    const int wn = wid >> 1;
    const int tg = lane >> 2;
    const int tc = lane & 3;

    const int row0 = blockIdx.x * TBM;
    const int col0 = blockIdx.y * TBN;

    const int a_r[4] = {(tid * 4) >> 5, (1024 + tid * 4) >> 5, (2048 + tid * 4) >> 5,
                        (3072 + tid * 4) >> 5};
    const int a_c = (tid * 4) & 31;
    const int b_r[4] = {(tid * 4) >> 7, (1024 + tid * 4) >> 7, (2048 + tid * 4) >> 7,
                        (3072 + tid * 4) >> 7};
    const int b_c = (tid * 4) & 127;

    const int T = K / TBK;

    float acc[4][4][4];
#pragma unroll
    for (int mt = 0; mt < 4; mt++)
#pragma unroll
        for (int nt = 0; nt < 4; nt++)
#pragma unroll
            for (int r = 0; r < 4; r++) acc[mt][nt][r] = 0.0f;

    {
        float* sA = sm;
        float* sB = sm + A_WORDS;
#pragma unroll
        for (int p = 0; p < 4; p++) {
            int gr = row0 + a_r[p];
            cp16(&sA[a_r[p] * ASTRIDE + a_c], A + (size_t)gr * K + a_c, gr < M);
            cp16(&sB[b_r[p] * BSTRIDE + b_c], B + (size_t)b_r[p] * N + col0 + b_c, true);
        }
        asm volatile("cp.async.commit_group;");
    }

    for (int t = 0; t < T; t++) {
        if (t + 1 < T) {
            float* sA = sm + ((t + 1) & 1) * STAGE_WORDS;
            float* sB = sA + A_WORDS;
            int k0 = (t + 1) * TBK;
#pragma unroll
            for (int p = 0; p < 4; p++) {
                int gr = row0 + a_r[p];
                cp16(&sA[a_r[p] * ASTRIDE + a_c], A + (size_t)gr * K + k0 + a_c, gr < M);
                cp16(&sB[b_r[p] * BSTRIDE + b_c], B + (size_t)(k0 + b_r[p]) * N + col0 + b_c,
                     true);
            }
            asm volatile("cp.async.commit_group;");
            asm volatile("cp.async.wait_group 1;");
        } else {
            asm volatile("cp.async.wait_group 0;");
        }
        __syncthreads();

        const float* sA = sm + (t & 1) * STAGE_WORDS;
        const float* sB = sA + A_WORDS;

#pragma unroll
        for (int ks = 0; ks < 4; ks++) {
            const int kb = ks * 8;
            uint32_t af[4][4], bf[4][2];
#pragma unroll
            for (int mt = 0; mt < 4; mt++) {
                int mrow = wm * 64 + mt * 16;
                af[mt][0] = f2tf32(sA[(mrow + tg) * ASTRIDE + kb + tc]);
                af[mt][1] = f2tf32(sA[(mrow + tg + 8) * ASTRIDE + kb + tc]);
                af[mt][2] = f2tf32(sA[(mrow + tg) * ASTRIDE + kb + tc + 4]);
                af[mt][3] = f2tf32(sA[(mrow + tg + 8) * ASTRIDE + kb + tc + 4]);
            }
#pragma unroll
            for (int nt = 0; nt < 4; nt++) {
                int ncol = wn * 32 + nt * 8;
                bf[nt][0] = f2tf32(sB[(kb + tc) * BSTRIDE + ncol + tg]);
                bf[nt][1] = f2tf32(sB[(kb + tc + 4) * BSTRIDE + ncol + tg]);
            }
#pragma unroll
            for (int mt = 0; mt < 4; mt++)
#pragma unroll
                for (int nt = 0; nt < 4; nt++) mma_tf32(acc[mt][nt], af[mt], bf[nt]);
        }
        __syncthreads();
    }

#pragma unroll
    for (int mt = 0; mt < 4; mt++) {
#pragma unroll
        for (int nt = 0; nt < 4; nt++) {
            int gc = col0 + wn * 32 + nt * 8 + tc * 2;
            float b0 = bias[gc], b1 = bias[gc + 1];
            float v0 = acc[mt][nt][0] + b0;
            float v1 = acc[mt][nt][1] + b1;
            float v2 = acc[mt][nt][2] + b0;
            float v3 = acc[mt][nt][3] + b1;
            if (alpha) {
                float a0 = alpha[gc], a1 = alpha[gc + 1];
                v0 = v0 > 0.f ? v0 : a0 * v0;
                v1 = v1 > 0.f ? v1 : a1 * v1;
                v2 = v2 > 0.f ? v2 : a0 * v2;
                v3 = v3 > 0.f ? v3 : a1 * v3;
            }
            int gr = row0 + wm * 64 + mt * 16 + tg;
            if (C16) {
                if (gr < M)
                    *(__nv_bfloat162*)(C16 + (size_t)gr * N + gc) =
                        __floats2bfloat162_rn(v0, v1);
                if (gr + 8 < M)
                    *(__nv_bfloat162*)(C16 + (size_t)(gr + 8) * N + gc) =
                        __floats2bfloat162_rn(v2, v3);
            } else {
                if (gr < M) *(float2*)(C + (size_t)gr * N + gc) = make_float2(v0, v1);
                if (gr + 8 < M) *(float2*)(C + (size_t)(gr + 8) * N + gc) = make_float2(v2, v3);
            }
        }
    }
}

// ---------------- fused edge kernel (bf16 q/k gathers, fp32 v) -------------
__global__ void edge_fused(const __nv_bfloat16* __restrict__ q,
                           const __nv_bfloat16* __restrict__ k,
                           const float* __restrict__ v, const int* __restrict__ src,
                           const int* __restrict__ dst, float* __restrict__ denom,
                           float* __restrict__ acc, int E) {
    int e = (blockIdx.x * blockDim.x + threadIdx.x) >> 5;
    if (e >= E) return;
    int lane = threadIdx.x & 31;
    int h = lane >> 2;
    int s = src[e];
    int d = dst[e];
    const __nv_bfloat162* kp = (const __nv_bfloat162*)(k + (size_t)s * D + lane * 4);
    const __nv_bfloat162* qp = (const __nv_bfloat162*)(q + (size_t)d * D + lane * 4);
    float2 k0 = __bfloat1622float2(kp[0]);
    float2 k1 = __bfloat1622float2(kp[1]);
    float2 q0 = __bfloat1622float2(qp[0]);
    float2 q1 = __bfloat1622float2(qp[1]);
    float p = k0.x * q0.x + k0.y * q0.y + k1.x * q1.x + k1.y * q1.y;
    p += __shfl_xor_sync(0xffffffffu, p, 1);
    p += __shfl_xor_sync(0xffffffffu, p, 2);
    float ex = __expf(p * 0.08838834764831843f);  // 1/sqrt(128)
    if ((lane & 3) == 0) atomicAdd(&denom[(size_t)d * H + h], ex);
    float4 vv = *(const float4*)(v + (size_t)s * D + lane * 4);
    float* pp = acc + (size_t)d * D + lane * 4;
    asm volatile("red.global.add.v4.f32 [%0], {%1,%2,%3,%4};" ::"l"(pp), "f"(vv.x * ex),
                 "f"(vv.y * ex), "f"(vv.z * ex), "f"(vv.w * ex)
                 : "memory");
}

// ---------------- LN1: out = LN(acc/denom + feat) ---------------------------
__global__ void ln_norm_kernel(const float* __restrict__ acc, const float* __restrict__ denom,
                               const float* __restrict__ feat, const float* __restrict__ g,
                               const float* __restrict__ b, float* __restrict__ out, int n) {
    int row = blockIdx.x * 4 + (threadIdx.x >> 5);
    if (row >= n) return;
    int lane = threadIdx.x & 31;
    float inv = 1.0f / denom[(size_t)row * H + (lane >> 2)];
    float4 vx = *(const float4*)(acc + (size_t)row * D + lane * 4);
    float4 fv = *(const float4*)(feat + (size_t)row * D + lane * 4);
    vx.x = vx.x * inv + fv.x;
    vx.y = vx.y * inv + fv.y;
    vx.z = vx.z * inv + fv.z;
    vx.w = vx.w * inv + fv.w;
    float s = vx.x + vx.y + vx.z + vx.w;
    float s2 = vx.x * vx.x + vx.y * vx.y + vx.z * vx.z + vx.w * vx.w;
#pragma unroll
    for (int o = 16; o > 0; o >>= 1) {
        s += __shfl_xor_sync(0xffffffffu, s, o);
        s2 += __shfl_xor_sync(0xffffffffu, s2, o);
    }
    float mean = s * (1.0f / D);
    float var = s2 * (1.0f / D) - mean * mean;
    float rstd = rsqrtf(var + 1e-5f);
    float4 gv = *(const float4*)(g + lane * 4);
    float4 bv = *(const float4*)(b + lane * 4);
    float4 o;
    o.x = (vx.x - mean) * rstd * gv.x + bv.x;
    o.y = (vx.y - mean) * rstd * gv.y + bv.y;
    o.z = (vx.z - mean) * rstd * gv.z + bv.z;
    o.w = (vx.w - mean) * rstd * gv.w + bv.w;
    *(float4*)(out + (size_t)row * D + lane * 4) = o;
}

// ---------------- LN2: out = LN(x + add) ------------------------------------
__global__ void ln_kernel(const float* __restrict__ x, const float* __restrict__ add,
                          const float* __restrict__ g, const float* __restrict__ b,
                          float* __restrict__ out, int n) {
    int row = blockIdx.x * 4 + (threadIdx.x >> 5);
    if (row >= n) return;
    int lane = threadIdx.x & 31;
    float4 vx = *(const float4*)(x + (size_t)row * D + lane * 4);
    float4 av = *(const float4*)(add + (size_t)row * D + lane * 4);
    vx.x += av.x;
    vx.y += av.y;
    vx.z += av.z;
    vx.w += av.w;
    float s = vx.x + vx.y + vx.z + vx.w;
    float s2 = vx.x * vx.x + vx.y * vx.y + vx.z * vx.z + vx.w * vx.w;
#pragma unroll
    for (int o = 16; o > 0; o >>= 1) {
        s += __shfl_xor_sync(0xffffffffu, s, o);
        s2 += __shfl_xor_sync(0xffffffffu, s2, o);
    }
    float mean = s * (1.0f / D);
    float var = s2 * (1.0f / D) - mean * mean;
    float rstd = rsqrtf(var + 1e-5f);
    float4 gv = *(const float4*)(g + lane * 4);
    float4 bv = *(const float4*)(b + lane * 4);
    float4 o;
    o.x = (vx.x - mean) * rstd * gv.x + bv.x;
    o.y = (vx.y - mean) * rstd * gv.y + bv.y;
    o.z = (vx.z - mean) * rstd * gv.z + bv.z;
    o.w = (vx.w - mean) * rstd * gv.w + bv.w;
    *(float4*)(out + (size_t)row * D + lane * 4) = o;
}

// ---------------- launch ----------------------------------------------------
extern "C" void kernel_launch(void* const* d_in, const int* in_sizes, int n_in,
                              void* d_out, int out_size) {
    const float* feat = (const float*)d_in[0];
    const int* src = (const int*)d_in[1];
    const int* dst = (const int*)d_in[2];
    const float* Wq = (const float*)d_in[3];
    const float* bq = (const float*)d_in[4];
    const float* Wk = (const float*)d_in[5];
    const float* bk = (const float*)d_in[6];
    const float* Wv = (const float*)d_in[7];
    const float* bv = (const float*)d_in[8];
    const float* ln_g = (const float*)d_in[9];
    const float* ln_b = (const float*)d_in[10];
    const float* W1 = (const float*)d_in[11];
    const float* b1 = (const float*)d_in[12];
    const float* alpha = (const float*)d_in[13];
    const float* W2 = (const float*)d_in[14];
    const float* b2 = (const float*)d_in[15];

    const int N = in_sizes[0] / D;
    const int E = in_sizes[1];

    __nv_bfloat16 *q16, *k16;
    float *v, *denom, *acc, *rstln, *hb, *ffn;
    cudaGetSymbolAddress((void**)&q16, g_q16);
    cudaGetSymbolAddress((void**)&k16, g_k16);
    cudaGetSymbolAddress((void**)&v, g_v);
    cudaGetSymbolAddress((void**)&denom, g_denom);
    cudaGetSymbolAddress((void**)&acc, g_acc);
    cudaGetSymbolAddress((void**)&rstln, g_rstln);
    cudaGetSymbolAddress((void**)&hb, g_h);
    cudaGetSymbolAddress((void**)&ffn, g_ffn);

    static int smem_set = 0;
    if (!smem_set) {
        cudaFuncSetAttribute(mma_gemm, cudaFuncAttributeMaxDynamicSharedMemorySize, GEMM_SMEM);
        smem_set = 1;
    }

    const int mgrid = (N + TBM - 1) / TBM;

    cudaMemsetAsync(denom, 0, (size_t)N * H * sizeof(float), 0);
    cudaMemsetAsync(acc, 0, (size_t)N * D * sizeof(float), 0);

    // q/k (bf16 out, edge-phase only) and v (fp32) projections
    mma_gemm<<<dim3(mgrid, 1), 256, GEMM_SMEM>>>(feat, Wq, bq, nullptr, nullptr, q16, N, D, D);
    mma_gemm<<<dim3(mgrid, 1), 256, GEMM_SMEM>>>(feat, Wk, bk, nullptr, nullptr, k16, N, D, D);
    mma_gemm<<<dim3(mgrid, 1), 256, GEMM_SMEM>>>(feat, Wv, bv, nullptr, v, nullptr, N, D, D);

    // fused edge attention
    edge_fused<<<((size_t)E * 32 + 255) / 256, 256>>>(q16, k16, v, src, dst, denom, acc, E);

    // LN1 with per-head normalization + residual
    ln_norm_kernel<<<(N + 3) / 4, 128>>>(acc, denom, feat, ln_g, ln_b, rstln, N);

    // FFN
    mma_gemm<<<dim3(mgrid, F / TBN), 256, GEMM_SMEM>>>(rstln, W1, b1, alpha, hb, nullptr, N, F,
                                                       D);
    mma_gemm<<<dim3(mgrid, 1), 256, GEMM_SMEM>>>(hb, W2, b2, nullptr, ffn, nullptr, N, D, F);

    // out = LN(rstln + ffn)
    ln_kernel<<<(N + 3) / 4, 128>>>(rstln, ffn, ln_g, ln_b, (float*)d_out, N);
}

// round 5
// speedup vs baseline: 3.6461x; 1.2739x over previous
#include <cuda_runtime.h>
#include <cuda_bf16.h>
#include <math.h>
#include <stdint.h>

#define NODES_MAX 100000
#define EDGES_MAX 1600000
#define D 128
#define H 8
#define F 512

// ---------------- scratch (static device globals; no allocation allowed) ----
__device__ __nv_bfloat16 g_q16[NODES_MAX * D];
__device__ __nv_bfloat16 g_k16[NODES_MAX * D];
__device__ float g_v[NODES_MAX * D];
__device__ float g_rstln[NODES_MAX * D];
__device__ float g_h[NODES_MAX * F];
__device__ float g_ffn[NODES_MAX * D];
// CSR build
__device__ int g_counts[NODES_MAX];
__device__ int g_rowptr[NODES_MAX + 1];
__device__ int g_wp[NODES_MAX];
__device__ int g_srcl[EDGES_MAX];
__device__ int g_bsums[256];

// ---------------- tf32 tensor-core GEMM, cp.async double-buffered ----------
#define TBM 128
#define TBN 128
#define TBK 32
#define ASTRIDE 36
#define BSTRIDE 136
#define A_WORDS (TBM * ASTRIDE)
#define B_WORDS (TBK * BSTRIDE)
#define STAGE_WORDS (A_WORDS + B_WORDS)
#define GEMM_SMEM (2 * STAGE_WORDS * 4)

__device__ __forceinline__ uint32_t f2tf32(float x) {
    uint32_t r;
    asm("cvt.rna.tf32.f32 %0, %1;" : "=r"(r) : "f"(x));
    return r;
}

__device__ __forceinline__ void mma_tf32(float* c, const uint32_t* a, const uint32_t* b) {
    asm volatile(
        "mma.sync.aligned.m16n8k8.row.col.f32.tf32.tf32.f32 "
        "{%0,%1,%2,%3}, {%4,%5,%6,%7}, {%8,%9}, {%0,%1,%2,%3};\n"
        : "+f"(c[0]), "+f"(c[1]), "+f"(c[2]), "+f"(c[3])
        : "r"(a[0]), "r"(a[1]), "r"(a[2]), "r"(a[3]), "r"(b[0]), "r"(b[1]));
}

__device__ __forceinline__ void cp16(float* s, const float* g, bool valid) {
    uint32_t sa = (uint32_t)__cvta_generic_to_shared(s);
    int sz = valid ? 16 : 0;
    asm volatile("cp.async.cg.shared.global [%0], [%1], 16, %2;" ::"r"(sa), "l"(g), "r"(sz));
}

__global__ __launch_bounds__(256, 2) void mma_gemm(
    const float* __restrict__ A, const float* __restrict__ B,
    const float* __restrict__ bias, const float* __restrict__ alpha,
    float* __restrict__ C, __nv_bfloat16* __restrict__ C16, int M, int N, int K) {
    extern __shared__ float sm[];

    const int tid = threadIdx.x;
    const int lane = tid & 31;
    const int wid = tid >> 5;
    const int wm = wid & 1;
    const int wn = wid >> 1;
    const int tg = lane >> 2;
    const int tc = lane & 3;

    const int row0 = blockIdx.x * TBM;
    const int col0 = blockIdx.y * TBN;

    const int a_r[4] = {(tid * 4) >> 5, (1024 + tid * 4) >> 5, (2048 + tid * 4) >> 5,
                        (3072 + tid * 4) >> 5};
    const int a_c = (tid * 4) & 31;
    const int b_r[4] = {(tid * 4) >> 7, (1024 + tid * 4) >> 7, (2048 + tid * 4) >> 7,
                        (3072 + tid * 4) >> 7};
    const int b_c = (tid * 4) & 127;

    const int T = K / TBK;

    float acc[4][4][4];
#pragma unroll
    for (int mt = 0; mt < 4; mt++)
#pragma unroll
        for (int nt = 0; nt < 4; nt++)
#pragma unroll
            for (int r = 0; r < 4; r++) acc[mt][nt][r] = 0.0f;

    {
        float* sA = sm;
        float* sB = sm + A_WORDS;
#pragma unroll
        for (int p = 0; p < 4; p++) {
            int gr = row0 + a_r[p];
            cp16(&sA[a_r[p] * ASTRIDE + a_c], A + (size_t)gr * K + a_c, gr < M);
            cp16(&sB[b_r[p] * BSTRIDE + b_c], B + (size_t)b_r[p] * N + col0 + b_c, true);
        }
        asm volatile("cp.async.commit_group;");
    }

    for (int t = 0; t < T; t++) {
        if (t + 1 < T) {
            float* sA = sm + ((t + 1) & 1) * STAGE_WORDS;
            float* sB = sA + A_WORDS;
            int k0 = (t + 1) * TBK;
#pragma unroll
            for (int p = 0; p < 4; p++) {
                int gr = row0 + a_r[p];
                cp16(&sA[a_r[p] * ASTRIDE + a_c], A + (size_t)gr * K + k0 + a_c, gr < M);
                cp16(&sB[b_r[p] * BSTRIDE + b_c], B + (size_t)(k0 + b_r[p]) * N + col0 + b_c,
                     true);
            }
            asm volatile("cp.async.commit_group;");
            asm volatile("cp.async.wait_group 1;");
        } else {
            asm volatile("cp.async.wait_group 0;");
        }
        __syncthreads();

        const float* sA = sm + (t & 1) * STAGE_WORDS;
        const float* sB = sA + A_WORDS;

#pragma unroll
        for (int ks = 0; ks < 4; ks++) {
            const int kb = ks * 8;
            uint32_t af[4][4], bf[4][2];
#pragma unroll
            for (int mt = 0; mt < 4; mt++) {
                int mrow = wm * 64 + mt * 16;
                af[mt][0] = f2tf32(sA[(mrow + tg) * ASTRIDE + kb + tc]);
                af[mt][1] = f2tf32(sA[(mrow + tg + 8) * ASTRIDE + kb + tc]);
                af[mt][2] = f2tf32(sA[(mrow + tg) * ASTRIDE + kb + tc + 4]);
                af[mt][3] = f2tf32(sA[(mrow + tg + 8) * ASTRIDE + kb + tc + 4]);
            }
#pragma unroll
            for (int nt = 0; nt < 4; nt++) {
                int ncol = wn * 32 + nt * 8;
                bf[nt][0] = f2tf32(sB[(kb + tc) * BSTRIDE + ncol + tg]);
                bf[nt][1] = f2tf32(sB[(kb + tc + 4) * BSTRIDE + ncol + tg]);
            }
#pragma unroll
            for (int mt = 0; mt < 4; mt++)
#pragma unroll
                for (int nt = 0; nt < 4; nt++) mma_tf32(acc[mt][nt], af[mt], bf[nt]);
        }
        __syncthreads();
    }

#pragma unroll
    for (int mt = 0; mt < 4; mt++) {
#pragma unroll
        for (int nt = 0; nt < 4; nt++) {
            int gc = col0 + wn * 32 + nt * 8 + tc * 2;
            float b0 = bias[gc], b1 = bias[gc + 1];
            float v0 = acc[mt][nt][0] + b0;
            float v1 = acc[mt][nt][1] + b1;
            float v2 = acc[mt][nt][2] + b0;
            float v3 = acc[mt][nt][3] + b1;
            if (alpha) {
                float a0 = alpha[gc], a1 = alpha[gc + 1];
                v0 = v0 > 0.f ? v0 : a0 * v0;
                v1 = v1 > 0.f ? v1 : a1 * v1;
                v2 = v2 > 0.f ? v2 : a0 * v2;
                v3 = v3 > 0.f ? v3 : a1 * v3;
            }
            int gr = row0 + wm * 64 + mt * 16 + tg;
            if (C16) {
                if (gr < M)
                    *(__nv_bfloat162*)(C16 + (size_t)gr * N + gc) =
                        __floats2bfloat162_rn(v0, v1);
                if (gr + 8 < M)
                    *(__nv_bfloat162*)(C16 + (size_t)(gr + 8) * N + gc) =
                        __floats2bfloat162_rn(v2, v3);
            } else {
                if (gr < M) *(float2*)(C + (size_t)gr * N + gc) = make_float2(v0, v1);
                if (gr + 8 < M) *(float2*)(C + (size_t)(gr + 8) * N + gc) = make_float2(v2, v3);
            }
        }
    }
}

// ---------------- CSR build --------------------------------------------------
__global__ void hist_kernel(const int* __restrict__ dst, int* __restrict__ counts, int E) {
    int i = blockIdx.x * blockDim.x + threadIdx.x;
    if (i < E) atomicAdd(&counts[dst[i]], 1);
}

// block-level exclusive scan: 256 threads x 4 elements = 1024 per block
__global__ void scan1_kernel(const int* __restrict__ counts, int* __restrict__ rowptr,
                             int* __restrict__ bsums, int n) {
    __shared__ int wsum[8];
    int base = blockIdx.x * 1024 + threadIdx.x * 4;
    int lane = threadIdx.x & 31, wid = threadIdx.x >> 5;
    int v[4];
#pragma unroll
    for (int i = 0; i < 4; i++) v[i] = (base + i < n) ? counts[base + i] : 0;
    int t = v[0] + v[1] + v[2] + v[3];
    int sc = t;
#pragma unroll
    for (int o = 1; o < 32; o <<= 1) {
        int x = __shfl_up_sync(0xffffffffu, sc, o);
        if (lane >= o) sc += x;
    }
    if (lane == 31) wsum[wid] = sc;
    __syncthreads();
    if (wid == 0) {
        int ws = (lane < 8) ? wsum[lane] : 0;
#pragma unroll
        for (int o = 1; o < 8; o <<= 1) {
            int x = __shfl_up_sync(0xffffffffu, ws, o);
            if (lane >= o) ws += x;
        }
        if (lane < 8) wsum[lane] = ws;
    }
    __syncthreads();
    int run = sc - t + (wid > 0 ? wsum[wid - 1] : 0);
#pragma unroll
    for (int i = 0; i < 4; i++) {
        if (base + i < n) rowptr[base + i] = run;
        run += v[i];
    }
    if (threadIdx.x == 0) bsums[blockIdx.x] = wsum[7];
}

__global__ void scan2_kernel(int* __restrict__ bsums, int nb) {
    if (threadIdx.x == 0 && blockIdx.x == 0) {
        int run = 0;
        for (int i = 0; i < nb; i++) {
            int t = bsums[i];
            bsums[i] = run;
            run += t;
        }
    }
}

__global__ void scan3_kernel(int* __restrict__ rowptr, const int* __restrict__ bsums, int n,
                             int E) {
    int i = blockIdx.x * blockDim.x + threadIdx.x;
    if (i < n) rowptr[i] += bsums[i >> 10];
    if (i == 0) rowptr[n] = E;
}

__global__ void fill_kernel(const int* __restrict__ src, const int* __restrict__ dst,
                            int* __restrict__ wp, int* __restrict__ srcl, int E) {
    int i = blockIdx.x * blockDim.x + threadIdx.x;
    if (i >= E) return;
    int pos = atomicAdd(&wp[dst[i]], 1);
    srcl[pos] = src[i];
}

// ---------------- fused per-node attention + LN1 ----------------------------
// One warp per destination node: gather k/v of in-neighbors, softmax-weighted
// aggregate in registers, add residual, LayerNorm, write rstln.
__global__ __launch_bounds__(256) void node_attn_ln(
    const __nv_bfloat16* __restrict__ q, const __nv_bfloat16* __restrict__ k,
    const float* __restrict__ v, const int* __restrict__ rowptr,
    const int* __restrict__ srcl, const float* __restrict__ feat,
    const float* __restrict__ g, const float* __restrict__ b, float* __restrict__ out,
    int n) {
    int node = blockIdx.x * 8 + (threadIdx.x >> 5);
    if (node >= n) return;
    int lane = threadIdx.x & 31;

    // q fragment: 4 bf16 per lane
    const __nv_bfloat162* qp = (const __nv_bfloat162*)(q + (size_t)node * D + lane * 4);
    float2 q0 = __bfloat1622float2(qp[0]);
    float2 q1 = __bfloat1622float2(qp[1]);

    int start = rowptr[node], end = rowptr[node + 1];

    float a0 = 0.f, a1 = 0.f, a2 = 0.f, a3 = 0.f, den = 0.f;

    for (int eb = start; eb < end; eb += 32) {
        int me = eb + lane;
        int sid = (me < end) ? srcl[me] : 0;
        int cnt = min(32, end - eb);
        for (int j = 0; j < cnt; j++) {
            int s = __shfl_sync(0xffffffffu, sid, j);
            const __nv_bfloat162* kp = (const __nv_bfloat162*)(k + (size_t)s * D + lane * 4);
            float2 k0 = __bfloat1622float2(kp[0]);
            float2 k1 = __bfloat1622float2(kp[1]);
            float p = k0.x * q0.x + k0.y * q0.y + k1.x * q1.x + k1.y * q1.y;
            p += __shfl_xor_sync(0xffffffffu, p, 1);
            p += __shfl_xor_sync(0xffffffffu, p, 2);
            float ex = __expf(p * 0.08838834764831843f);  // 1/sqrt(128)
            den += ex;
            float4 vv = *(const float4*)(v + (size_t)s * D + lane * 4);
            a0 += vv.x * ex;
            a1 += vv.y * ex;
            a2 += vv.z * ex;
            a3 += vv.w * ex;
        }
    }

    float inv = den > 0.f ? 1.0f / den : 0.0f;
    float4 fv = *(const float4*)(feat + (size_t)node * D + lane * 4);
    float r0 = a0 * inv + fv.x;
    float r1 = a1 * inv + fv.y;
    float r2 = a2 * inv + fv.z;
    float r3 = a3 * inv + fv.w;

    float s = r0 + r1 + r2 + r3;
    float s2 = r0 * r0 + r1 * r1 + r2 * r2 + r3 * r3;
#pragma unroll
    for (int o = 16; o > 0; o >>= 1) {
        s += __shfl_xor_sync(0xffffffffu, s, o);
        s2 += __shfl_xor_sync(0xffffffffu, s2, o);
    }
    float mean = s * (1.0f / D);
    float var = s2 * (1.0f / D) - mean * mean;
    float rstd = rsqrtf(var + 1e-5f);
    float4 gv = *(const float4*)(g + lane * 4);
    float4 bv = *(const float4*)(b + lane * 4);
    float4 o;
    o.x = (r0 - mean) * rstd * gv.x + bv.x;
    o.y = (r1 - mean) * rstd * gv.y + bv.y;
    o.z = (r2 - mean) * rstd * gv.z + bv.z;
    o.w = (r3 - mean) * rstd * gv.w + bv.w;
    *(float4*)(out + (size_t)node * D + lane * 4) = o;
}

// ---------------- LN2: out = LN(x + add) ------------------------------------
__global__ void ln_kernel(const float* __restrict__ x, const float* __restrict__ add,
                          const float* __restrict__ g, const float* __restrict__ b,
                          float* __restrict__ out, int n) {
    int row = blockIdx.x * 4 + (threadIdx.x >> 5);
    if (row >= n) return;
    int lane = threadIdx.x & 31;
    float4 vx = *(const float4*)(x + (size_t)row * D + lane * 4);
    float4 av = *(const float4*)(add + (size_t)row * D + lane * 4);
    vx.x += av.x;
    vx.y += av.y;
    vx.z += av.z;
    vx.w += av.w;
    float s = vx.x + vx.y + vx.z + vx.w;
    float s2 = vx.x * vx.x + vx.y * vx.y + vx.z * vx.z + vx.w * vx.w;
#pragma unroll
    for (int o = 16; o > 0; o >>= 1) {
        s += __shfl_xor_sync(0xffffffffu, s, o);
        s2 += __shfl_xor_sync(0xffffffffu, s2, o);
    }
    float mean = s * (1.0f / D);
    float var = s2 * (1.0f / D) - mean * mean;
    float rstd = rsqrtf(var + 1e-5f);
    float4 gv = *(const float4*)(g + lane * 4);
    float4 bv = *(const float4*)(b + lane * 4);
    float4 o;
    o.x = (vx.x - mean) * rstd * gv.x + bv.x;
    o.y = (vx.y - mean) * rstd * gv.y + bv.y;
    o.z = (vx.z - mean) * rstd * gv.z + bv.z;
    o.w = (vx.w - mean) * rstd * gv.w + bv.w;
    *(float4*)(out + (size_t)row * D + lane * 4) = o;
}

// ---------------- launch ----------------------------------------------------
extern "C" void kernel_launch(void* const* d_in, const int* in_sizes, int n_in,
                              void* d_out, int out_size) {
    const float* feat = (const float*)d_in[0];
    const int* src = (const int*)d_in[1];
    const int* dst = (const int*)d_in[2];
    const float* Wq = (const float*)d_in[3];
    const float* bq = (const float*)d_in[4];
    const float* Wk = (const float*)d_in[5];
    const float* bk = (const float*)d_in[6];
    const float* Wv = (const float*)d_in[7];
    const float* bv = (const float*)d_in[8];
    const float* ln_g = (const float*)d_in[9];
    const float* ln_b = (const float*)d_in[10];
    const float* W1 = (const float*)d_in[11];
    const float* b1 = (const float*)d_in[12];
    const float* alpha = (const float*)d_in[13];
    const float* W2 = (const float*)d_in[14];
    const float* b2 = (const float*)d_in[15];

    const int N = in_sizes[0] / D;
    const int E = in_sizes[1];

    __nv_bfloat16 *q16, *k16;
    float *v, *rstln, *hb, *ffn;
    int *counts, *rowptr, *wp, *srcl, *bsums;
    cudaGetSymbolAddress((void**)&q16, g_q16);
    cudaGetSymbolAddress((void**)&k16, g_k16);
    cudaGetSymbolAddress((void**)&v, g_v);
    cudaGetSymbolAddress((void**)&rstln, g_rstln);
    cudaGetSymbolAddress((void**)&hb, g_h);
    cudaGetSymbolAddress((void**)&ffn, g_ffn);
    cudaGetSymbolAddress((void**)&counts, g_counts);
    cudaGetSymbolAddress((void**)&rowptr, g_rowptr);
    cudaGetSymbolAddress((void**)&wp, g_wp);
    cudaGetSymbolAddress((void**)&srcl, g_srcl);
    cudaGetSymbolAddress((void**)&bsums, g_bsums);

    static int smem_set = 0;
    if (!smem_set) {
        cudaFuncSetAttribute(mma_gemm, cudaFuncAttributeMaxDynamicSharedMemorySize, GEMM_SMEM);
        smem_set = 1;
    }

    const int mgrid = (N + TBM - 1) / TBM;
    const int nb = (N + 1023) / 1024;

    // ---- CSR build
    cudaMemsetAsync(counts, 0, (size_t)N * sizeof(int), 0);
    hist_kernel<<<(E + 255) / 256, 256>>>(dst, counts, E);
    scan1_kernel<<<nb, 256>>>(counts, rowptr, bsums, N);
    scan2_kernel<<<1, 32>>>(bsums, nb);
    scan3_kernel<<<(N + 255) / 256, 256>>>(rowptr, bsums, N, E);
    cudaMemcpyAsync(wp, rowptr, (size_t)N * sizeof(int), cudaMemcpyDeviceToDevice, 0);
    fill_kernel<<<(E + 255) / 256, 256>>>(src, dst, wp, srcl, E);

    // ---- q/k (bf16 out) and v (fp32) projections
    mma_gemm<<<dim3(mgrid, 1), 256, GEMM_SMEM>>>(feat, Wq, bq, nullptr, nullptr, q16, N, D, D);
    mma_gemm<<<dim3(mgrid, 1), 256, GEMM_SMEM>>>(feat, Wk, bk, nullptr, nullptr, k16, N, D, D);
    mma_gemm<<<dim3(mgrid, 1), 256, GEMM_SMEM>>>(feat, Wv, bv, nullptr, v, nullptr, N, D, D);

    // ---- fused per-node attention + LN1
    node_attn_ln<<<(N + 7) / 8, 256>>>(q16, k16, v, rowptr, srcl, feat, ln_g, ln_b, rstln, N);

    // ---- FFN
    mma_gemm<<<dim3(mgrid, F / TBN), 256, GEMM_SMEM>>>(rstln, W1, b1, alpha, hb, nullptr, N, F,
                                                       D);
    mma_gemm<<<dim3(mgrid, 1), 256, GEMM_SMEM>>>(hb, W2, b2, nullptr, ffn, nullptr, N, D, F);

    // ---- out = LN(rstln + ffn)
    ln_kernel<<<(N + 3) / 4, 128>>>(rstln, ffn, ln_g, ln_b, (float*)d_out, N);
}

// round 6
// speedup vs baseline: 4.0195x; 1.1024x over previous
#include <cuda_runtime.h>
#include <cuda_bf16.h>
#include <math.h>
#include <stdint.h>

#define NODES_MAX 100000
#define EDGES_MAX 1600000
#define D 128
#define H 8
#define F 512

// ---------------- scratch (static device globals; no allocation allowed) ----
__device__ __nv_bfloat16 g_q16[NODES_MAX * D];
__device__ __nv_bfloat16 g_k16[NODES_MAX * D];
__device__ __nv_bfloat16 g_v16[NODES_MAX * D];
__device__ float g_rstln[NODES_MAX * D];
__device__ float g_h[NODES_MAX * F];
__device__ float g_ffn[NODES_MAX * D];
// CSR build
__device__ int g_counts[NODES_MAX];
__device__ int g_rowptr[NODES_MAX + 1];
__device__ int g_wp[NODES_MAX];
__device__ int g_srcl[EDGES_MAX];
__device__ int g_bsums[256];

// ---------------- tf32 tensor-core GEMM core, cp.async double-buffered ------
#define TBM 128
#define TBN 128
#define TBK 32
#define ASTRIDE 36
#define BSTRIDE 136
#define A_WORDS (TBM * ASTRIDE)
#define B_WORDS (TBK * BSTRIDE)
#define STAGE_WORDS (A_WORDS + B_WORDS)
#define GEMM_SMEM (2 * STAGE_WORDS * 4)

__device__ __forceinline__ uint32_t f2tf32(float x) {
    uint32_t r;
    asm("cvt.rna.tf32.f32 %0, %1;" : "=r"(r) : "f"(x));
    return r;
}

__device__ __forceinline__ void mma_tf32(float* c, const uint32_t* a, const uint32_t* b) {
    asm volatile(
        "mma.sync.aligned.m16n8k8.row.col.f32.tf32.tf32.f32 "
        "{%0,%1,%2,%3}, {%4,%5,%6,%7}, {%8,%9}, {%0,%1,%2,%3};\n"
        : "+f"(c[0]), "+f"(c[1]), "+f"(c[2]), "+f"(c[3])
        : "r"(a[0]), "r"(a[1]), "r"(a[2]), "r"(a[3]), "r"(b[0]), "r"(b[1]));
}

__device__ __forceinline__ void cp16(float* s, const float* g, bool valid) {
    uint32_t sa = (uint32_t)__cvta_generic_to_shared(s);
    int sz = valid ? 16 : 0;
    asm volatile("cp.async.cg.shared.global [%0], [%1], 16, %2;" ::"r"(sa), "l"(g), "r"(sz));
}

// Shared GEMM body. If C16 != nullptr, stores bf16; else fp32 (+optional PReLU).
__device__ __forceinline__ void gemm_body(const float* __restrict__ A,
                                          const float* __restrict__ B,
                                          const float* __restrict__ bias,
                                          const float* __restrict__ alpha,
                                          float* __restrict__ C,
                                          __nv_bfloat16* __restrict__ C16, int M, int N,
                                          int K, float* sm) {
    const int tid = threadIdx.x;
    const int lane = tid & 31;
    const int wid = tid >> 5;
    const int wm = wid & 1;
    const int wn = wid >> 1;
    const int tg = lane >> 2;
    const int tc = lane & 3;

    const int row0 = blockIdx.x * TBM;
    const int col0 = blockIdx.y * TBN;

    const int a_r[4] = {(tid * 4) >> 5, (1024 + tid * 4) >> 5, (2048 + tid * 4) >> 5,
                        (3072 + tid * 4) >> 5};
    const int a_c = (tid * 4) & 31;
    const int b_r[4] = {(tid * 4) >> 7, (1024 + tid * 4) >> 7, (2048 + tid * 4) >> 7,
                        (3072 + tid * 4) >> 7};
    const int b_c = (tid * 4) & 127;

    const int T = K / TBK;

    float acc[4][4][4];
#pragma unroll
    for (int mt = 0; mt < 4; mt++)
#pragma unroll
        for (int nt = 0; nt < 4; nt++)
#pragma unroll
            for (int r = 0; r < 4; r++) acc[mt][nt][r] = 0.0f;

    {
        float* sA = sm;
        float* sB = sm + A_WORDS;
#pragma unroll
        for (int p = 0; p < 4; p++) {
            int gr = row0 + a_r[p];
            cp16(&sA[a_r[p] * ASTRIDE + a_c], A + (size_t)gr * K + a_c, gr < M);
            cp16(&sB[b_r[p] * BSTRIDE + b_c], B + (size_t)b_r[p] * N + col0 + b_c, true);
        }
        asm volatile("cp.async.commit_group;");
    }

    for (int t = 0; t < T; t++) {
        if (t + 1 < T) {
            float* sA = sm + ((t + 1) & 1) * STAGE_WORDS;
            float* sB = sA + A_WORDS;
            int k0 = (t + 1) * TBK;
#pragma unroll
            for (int p = 0; p < 4; p++) {
                int gr = row0 + a_r[p];
                cp16(&sA[a_r[p] * ASTRIDE + a_c], A + (size_t)gr * K + k0 + a_c, gr < M);
                cp16(&sB[b_r[p] * BSTRIDE + b_c], B + (size_t)(k0 + b_r[p]) * N + col0 + b_c,
                     true);
            }
            asm volatile("cp.async.commit_group;");
            asm volatile("cp.async.wait_group 1;");
        } else {
            asm volatile("cp.async.wait_group 0;");
        }
        __syncthreads();

        const float* sA = sm + (t & 1) * STAGE_WORDS;
        const float* sB = sA + A_WORDS;

#pragma unroll
        for (int ks = 0; ks < 4; ks++) {
            const int kb = ks * 8;
            uint32_t af[4][4], bf[4][2];
#pragma unroll
            for (int mt = 0; mt < 4; mt++) {
                int mrow = wm * 64 + mt * 16;
                af[mt][0] = f2tf32(sA[(mrow + tg) * ASTRIDE + kb + tc]);
                af[mt][1] = f2tf32(sA[(mrow + tg + 8) * ASTRIDE + kb + tc]);
                af[mt][2] = f2tf32(sA[(mrow + tg) * ASTRIDE + kb + tc + 4]);
                af[mt][3] = f2tf32(sA[(mrow + tg + 8) * ASTRIDE + kb + tc + 4]);
            }
#pragma unroll
            for (int nt = 0; nt < 4; nt++) {
                int ncol = wn * 32 + nt * 8;
                bf[nt][0] = f2tf32(sB[(kb + tc) * BSTRIDE + ncol + tg]);
                bf[nt][1] = f2tf32(sB[(kb + tc + 4) * BSTRIDE + ncol + tg]);
            }
#pragma unroll
            for (int mt = 0; mt < 4; mt++)
#pragma unroll
                for (int nt = 0; nt < 4; nt++) mma_tf32(acc[mt][nt], af[mt], bf[nt]);
        }
        __syncthreads();
    }

#pragma unroll
    for (int mt = 0; mt < 4; mt++) {
#pragma unroll
        for (int nt = 0; nt < 4; nt++) {
            int gc = col0 + wn * 32 + nt * 8 + tc * 2;
            float b0 = bias[gc], b1 = bias[gc + 1];
            float v0 = acc[mt][nt][0] + b0;
            float v1 = acc[mt][nt][1] + b1;
            float v2 = acc[mt][nt][2] + b0;
            float v3 = acc[mt][nt][3] + b1;
            if (alpha) {
                float a0 = alpha[gc], a1 = alpha[gc + 1];
                v0 = v0 > 0.f ? v0 : a0 * v0;
                v1 = v1 > 0.f ? v1 : a1 * v1;
                v2 = v2 > 0.f ? v2 : a0 * v2;
                v3 = v3 > 0.f ? v3 : a1 * v3;
            }
            int gr = row0 + wm * 64 + mt * 16 + tg;
            if (C16) {
                if (gr < M)
                    *(__nv_bfloat162*)(C16 + (size_t)gr * N + gc) =
                        __floats2bfloat162_rn(v0, v1);
                if (gr + 8 < M)
                    *(__nv_bfloat162*)(C16 + (size_t)(gr + 8) * N + gc) =
                        __floats2bfloat162_rn(v2, v3);
            } else {
                if (gr < M) *(float2*)(C + (size_t)gr * N + gc) = make_float2(v0, v1);
                if (gr + 8 < M) *(float2*)(C + (size_t)(gr + 8) * N + gc) = make_float2(v2, v3);
            }
        }
    }
}

// generic fp32-out GEMM (FFN)
__global__ __launch_bounds__(256, 2) void mma_gemm(
    const float* __restrict__ A, const float* __restrict__ B,
    const float* __restrict__ bias, const float* __restrict__ alpha,
    float* __restrict__ C, int M, int N, int K) {
    extern __shared__ float sm[];
    gemm_body(A, B, bias, alpha, C, nullptr, M, N, K, sm);
}

// fused q/k/v projection: blockIdx.z selects weight/bias/output, bf16 out
__global__ __launch_bounds__(256, 2) void qkv_gemm(
    const float* __restrict__ A, const float* __restrict__ Wq,
    const float* __restrict__ Wk, const float* __restrict__ Wv,
    const float* __restrict__ bq, const float* __restrict__ bk,
    const float* __restrict__ bv, __nv_bfloat16* __restrict__ q16,
    __nv_bfloat16* __restrict__ k16, __nv_bfloat16* __restrict__ v16, int M) {
    extern __shared__ float sm[];
    const float* B = (blockIdx.z == 0) ? Wq : (blockIdx.z == 1) ? Wk : Wv;
    const float* bias = (blockIdx.z == 0) ? bq : (blockIdx.z == 1) ? bk : bv;
    __nv_bfloat16* C16 = (blockIdx.z == 0) ? q16 : (blockIdx.z == 1) ? k16 : v16;
    gemm_body(A, B, bias, nullptr, nullptr, C16, M, D, D, sm);
}

// ---------------- CSR build --------------------------------------------------
__global__ void hist_kernel(const int* __restrict__ dst, int* __restrict__ counts, int E) {
    int i = blockIdx.x * blockDim.x + threadIdx.x;
    if (i < E) atomicAdd(&counts[dst[i]], 1);
}

__global__ void scan1_kernel(const int* __restrict__ counts, int* __restrict__ rowptr,
                             int* __restrict__ bsums, int n) {
    __shared__ int wsum[8];
    int base = blockIdx.x * 1024 + threadIdx.x * 4;
    int lane = threadIdx.x & 31, wid = threadIdx.x >> 5;
    int v[4];
#pragma unroll
    for (int i = 0; i < 4; i++) v[i] = (base + i < n) ? counts[base + i] : 0;
    int t = v[0] + v[1] + v[2] + v[3];
    int sc = t;
#pragma unroll
    for (int o = 1; o < 32; o <<= 1) {
        int x = __shfl_up_sync(0xffffffffu, sc, o);
        if (lane >= o) sc += x;
    }
    if (lane == 31) wsum[wid] = sc;
    __syncthreads();
    if (wid == 0) {
        int ws = (lane < 8) ? wsum[lane] : 0;
#pragma unroll
        for (int o = 1; o < 8; o <<= 1) {
            int x = __shfl_up_sync(0xffffffffu, ws, o);
            if (lane >= o) ws += x;
        }
        if (lane < 8) wsum[lane] = ws;
    }
    __syncthreads();
    int run = sc - t + (wid > 0 ? wsum[wid - 1] : 0);
#pragma unroll
    for (int i = 0; i < 4; i++) {
        if (base + i < n) rowptr[base + i] = run;
        run += v[i];
    }
    if (threadIdx.x == 0) bsums[blockIdx.x] = wsum[7];
}

__global__ void scan2_kernel(int* __restrict__ bsums, int nb) {
    if (threadIdx.x == 0 && blockIdx.x == 0) {
        int run = 0;
        for (int i = 0; i < nb; i++) {
            int t = bsums[i];
            bsums[i] = run;
            run += t;
        }
    }
}

__global__ void scan3_kernel(int* __restrict__ rowptr, const int* __restrict__ bsums, int n,
                             int E) {
    int i = blockIdx.x * blockDim.x + threadIdx.x;
    if (i < n) rowptr[i] += bsums[i >> 10];
    if (i == 0) rowptr[n] = E;
}

__global__ void fill_kernel(const int* __restrict__ src, const int* __restrict__ dst,
                            int* __restrict__ wp, int* __restrict__ srcl, int E) {
    int i = blockIdx.x * blockDim.x + threadIdx.x;
    if (i >= E) return;
    int pos = atomicAdd(&wp[dst[i]], 1);
    srcl[pos] = src[i];
}

// ---------------- fused per-node attention + LN1 ----------------------------
__device__ __forceinline__ float2 bf2f(uint32_t u) {
    return __bfloat1622float2(*reinterpret_cast<__nv_bfloat162*>(&u));
}

__global__ __launch_bounds__(256) void node_attn_ln(
    const __nv_bfloat16* __restrict__ q, const __nv_bfloat16* __restrict__ k,
    const __nv_bfloat16* __restrict__ v, const int* __restrict__ rowptr,
    const int* __restrict__ srcl, const float* __restrict__ feat,
    const float* __restrict__ g, const float* __restrict__ b, float* __restrict__ out,
    int n) {
    int node = blockIdx.x * 8 + (threadIdx.x >> 5);
    if (node >= n) return;
    int lane = threadIdx.x & 31;

    uint2 qraw = *(const uint2*)(q + (size_t)node * D + lane * 4);
    float2 q0 = bf2f(qraw.x);
    float2 q1 = bf2f(qraw.y);

    int start = rowptr[node], end = rowptr[node + 1];

    float a0 = 0.f, a1 = 0.f, a2 = 0.f, a3 = 0.f, den = 0.f;

    for (int eb = start; eb < end; eb += 32) {
        int me = eb + lane;
        int sid = (me < end) ? srcl[me] : 0;
        int cnt = min(32, end - eb);
        int j = 0;
        for (; j + 2 <= cnt; j += 2) {
            int sa = __shfl_sync(0xffffffffu, sid, j);
            int sb = __shfl_sync(0xffffffffu, sid, j + 1);
            uint2 kra = *(const uint2*)(k + (size_t)sa * D + lane * 4);
            uint2 krb = *(const uint2*)(k + (size_t)sb * D + lane * 4);
            uint2 vra = *(const uint2*)(v + (size_t)sa * D + lane * 4);
            uint2 vrb = *(const uint2*)(v + (size_t)sb * D + lane * 4);
            float2 ka0 = bf2f(kra.x), ka1 = bf2f(kra.y);
            float2 kb0 = bf2f(krb.x), kb1 = bf2f(krb.y);
            float pa = ka0.x * q0.x + ka0.y * q0.y + ka1.x * q1.x + ka1.y * q1.y;
            float pb = kb0.x * q0.x + kb0.y * q0.y + kb1.x * q1.x + kb1.y * q1.y;
            pa += __shfl_xor_sync(0xffffffffu, pa, 1);
            pb += __shfl_xor_sync(0xffffffffu, pb, 1);
            pa += __shfl_xor_sync(0xffffffffu, pa, 2);
            pb += __shfl_xor_sync(0xffffffffu, pb, 2);
            float exa = __expf(pa * 0.08838834764831843f);
            float exb = __expf(pb * 0.08838834764831843f);
            den += exa + exb;
            float2 va0 = bf2f(vra.x), va1 = bf2f(vra.y);
            float2 vb0 = bf2f(vrb.x), vb1 = bf2f(vrb.y);
            a0 += va0.x * exa + vb0.x * exb;
            a1 += va0.y * exa + vb0.y * exb;
            a2 += va1.x * exa + vb1.x * exb;
            a3 += va1.y * exa + vb1.y * exb;
        }
        for (; j < cnt; j++) {
            int s = __shfl_sync(0xffffffffu, sid, j);
            uint2 kr = *(const uint2*)(k + (size_t)s * D + lane * 4);
            uint2 vr = *(const uint2*)(v + (size_t)s * D + lane * 4);
            float2 k0 = bf2f(kr.x), k1 = bf2f(kr.y);
            float p = k0.x * q0.x + k0.y * q0.y + k1.x * q1.x + k1.y * q1.y;
            p += __shfl_xor_sync(0xffffffffu, p, 1);
            p += __shfl_xor_sync(0xffffffffu, p, 2);
            float ex = __expf(p * 0.08838834764831843f);
            den += ex;
            float2 v0 = bf2f(vr.x), v1 = bf2f(vr.y);
            a0 += v0.x * ex;
            a1 += v0.y * ex;
            a2 += v1.x * ex;
            a3 += v1.y * ex;
        }
    }

    float inv = den > 0.f ? 1.0f / den : 0.0f;
    float4 fv = *(const float4*)(feat + (size_t)node * D + lane * 4);
    float r0 = a0 * inv + fv.x;
    float r1 = a1 * inv + fv.y;
    float r2 = a2 * inv + fv.z;
    float r3 = a3 * inv + fv.w;

    float s = r0 + r1 + r2 + r3;
    float s2 = r0 * r0 + r1 * r1 + r2 * r2 + r3 * r3;
#pragma unroll
    for (int o = 16; o > 0; o >>= 1) {
        s += __shfl_xor_sync(0xffffffffu, s, o);
        s2 += __shfl_xor_sync(0xffffffffu, s2, o);
    }
    float mean = s * (1.0f / D);
    float var = s2 * (1.0f / D) - mean * mean;
    float rstd = rsqrtf(var + 1e-5f);
    float4 gv = *(const float4*)(g + lane * 4);
    float4 bv = *(const float4*)(b + lane * 4);
    float4 o;
    o.x = (r0 - mean) * rstd * gv.x + bv.x;
    o.y = (r1 - mean) * rstd * gv.y + bv.y;
    o.z = (r2 - mean) * rstd * gv.z + bv.z;
    o.w = (r3 - mean) * rstd * gv.w + bv.w;
    *(float4*)(out + (size_t)node * D + lane * 4) = o;
}

// ---------------- LN2: out = LN(x + add) ------------------------------------
__global__ void ln_kernel(const float* __restrict__ x, const float* __restrict__ add,
                          const float* __restrict__ g, const float* __restrict__ b,
                          float* __restrict__ out, int n) {
    int row = blockIdx.x * 4 + (threadIdx.x >> 5);
    if (row >= n) return;
    int lane = threadIdx.x & 31;
    float4 vx = *(const float4*)(x + (size_t)row * D + lane * 4);
    float4 av = *(const float4*)(add + (size_t)row * D + lane * 4);
    vx.x += av.x;
    vx.y += av.y;
    vx.z += av.z;
    vx.w += av.w;
    float s = vx.x + vx.y + vx.z + vx.w;
    float s2 = vx.x * vx.x + vx.y * vx.y + vx.z * vx.z + vx.w * vx.w;
#pragma unroll
    for (int o = 16; o > 0; o >>= 1) {
        s += __shfl_xor_sync(0xffffffffu, s, o);
        s2 += __shfl_xor_sync(0xffffffffu, s2, o);
    }
    float mean = s * (1.0f / D);
    float var = s2 * (1.0f / D) - mean * mean;
    float rstd = rsqrtf(var + 1e-5f);
    float4 gv = *(const float4*)(g + lane * 4);
    float4 bv = *(const float4*)(b + lane * 4);
    float4 o;
    o.x = (vx.x - mean) * rstd * gv.x + bv.x;
    o.y = (vx.y - mean) * rstd * gv.y + bv.y;
    o.z = (vx.z - mean) * rstd * gv.z + bv.z;
    o.w = (vx.w - mean) * rstd * gv.w + bv.w;
    *(float4*)(out + (size_t)row * D + lane * 4) = o;
}

// ---------------- launch ----------------------------------------------------
extern "C" void kernel_launch(void* const* d_in, const int* in_sizes, int n_in,
                              void* d_out, int out_size) {
    const float* feat = (const float*)d_in[0];
    const int* src = (const int*)d_in[1];
    const int* dst = (const int*)d_in[2];
    const float* Wq = (const float*)d_in[3];
    const float* bq = (const float*)d_in[4];
    const float* Wk = (const float*)d_in[5];
    const float* bk = (const float*)d_in[6];
    const float* Wv = (const float*)d_in[7];
    const float* bv = (const float*)d_in[8];
    const float* ln_g = (const float*)d_in[9];
    const float* ln_b = (const float*)d_in[10];
    const float* W1 = (const float*)d_in[11];
    const float* b1 = (const float*)d_in[12];
    const float* alpha = (const float*)d_in[13];
    const float* W2 = (const float*)d_in[14];
    const float* b2 = (const float*)d_in[15];

    const int N = in_sizes[0] / D;
    const int E = in_sizes[1];

    __nv_bfloat16 *q16, *k16, *v16;
    float *rstln, *hb, *ffn;
    int *counts, *rowptr, *wp, *srcl, *bsums;
    cudaGetSymbolAddress((void**)&q16, g_q16);
    cudaGetSymbolAddress((void**)&k16, g_k16);
    cudaGetSymbolAddress((void**)&v16, g_v16);
    cudaGetSymbolAddress((void**)&rstln, g_rstln);
    cudaGetSymbolAddress((void**)&hb, g_h);
    cudaGetSymbolAddress((void**)&ffn, g_ffn);
    cudaGetSymbolAddress((void**)&counts, g_counts);
    cudaGetSymbolAddress((void**)&rowptr, g_rowptr);
    cudaGetSymbolAddress((void**)&wp, g_wp);
    cudaGetSymbolAddress((void**)&srcl, g_srcl);
    cudaGetSymbolAddress((void**)&bsums, g_bsums);

    static int smem_set = 0;
    if (!smem_set) {
        cudaFuncSetAttribute(mma_gemm, cudaFuncAttributeMaxDynamicSharedMemorySize, GEMM_SMEM);
        cudaFuncSetAttribute(qkv_gemm, cudaFuncAttributeMaxDynamicSharedMemorySize, GEMM_SMEM);
        smem_set = 1;
    }

    const int mgrid = (N + TBM - 1) / TBM;
    const int nb = (N + 1023) / 1024;

    // ---- CSR build
    cudaMemsetAsync(counts, 0, (size_t)N * sizeof(int), 0);
    hist_kernel<<<(E + 255) / 256, 256>>>(dst, counts, E);
    scan1_kernel<<<nb, 256>>>(counts, rowptr, bsums, N);
    scan2_kernel<<<1, 32>>>(bsums, nb);
    scan3_kernel<<<(N + 255) / 256, 256>>>(rowptr, bsums, N, E);
    cudaMemcpyAsync(wp, rowptr, (size_t)N * sizeof(int), cudaMemcpyDeviceToDevice, 0);
    fill_kernel<<<(E + 255) / 256, 256>>>(src, dst, wp, srcl, E);

    // ---- fused q/k/v projections (bf16 out)
    qkv_gemm<<<dim3(mgrid, 1, 3), 256, GEMM_SMEM>>>(feat, Wq, Wk, Wv, bq, bk, bv, q16, k16,
                                                    v16, N);

    // ---- fused per-node attention + LN1
    node_attn_ln<<<(N + 7) / 8, 256>>>(q16, k16, v16, rowptr, srcl, feat, ln_g, ln_b, rstln,
                                       N);

    // ---- FFN
    mma_gemm<<<dim3(mgrid, F / TBN), 256, GEMM_SMEM>>>(rstln, W1, b1, alpha, hb, N, F, D);
    mma_gemm<<<dim3(mgrid, 1), 256, GEMM_SMEM>>>(hb, W2, b2, nullptr, ffn, N, D, F);

    // ---- out = LN(rstln + ffn)
    ln_kernel<<<(N + 3) / 4, 128>>>(rstln, ffn, ln_g, ln_b, (float*)d_out, N);
}

// round 9
// speedup vs baseline: 4.0554x; 1.0089x over previous
#include <cuda_runtime.h>
#include <cuda_bf16.h>
#include <math.h>
#include <stdint.h>

#define NODES_MAX 100000
#define EDGES_MAX 1600000
#define D 128
#define H 8
#define F 512

// ---------------- scratch (static device globals; no allocation allowed) ----
__device__ __nv_bfloat16 g_q16[NODES_MAX * D];
__device__ __nv_bfloat16 g_k16[NODES_MAX * D];
__device__ __nv_bfloat16 g_v16[NODES_MAX * D];
__device__ float g_rstln[NODES_MAX * D];
__device__ float g_h[NODES_MAX * F];
// CSR build
__device__ int g_counts[NODES_MAX];
__device__ int g_rowptr[NODES_MAX + 1];
__device__ int g_wp[NODES_MAX];
__device__ int g_srcl[EDGES_MAX];
__device__ int g_bsums[256];

// ---------------- tf32 tensor-core GEMM core, cp.async double-buffered ------
#define TBM 128
#define TBN 128
#define TBK 32
#define ASTRIDE 36
#define BSTRIDE 136
#define A_WORDS (TBM * ASTRIDE)
#define B_WORDS (TBK * BSTRIDE)
#define STAGE_WORDS (A_WORDS + B_WORDS)
#define GEMM_SMEM (2 * STAGE_WORDS * 4)   // 71680 B >= 128*132*4 (LN staging)
#define LNSTRIDE 132

__device__ __forceinline__ uint32_t f2tf32(float x) {
    uint32_t r;
    asm("cvt.rna.tf32.f32 %0, %1;" : "=r"(r) : "f"(x));
    return r;
}

__device__ __forceinline__ void mma_tf32(float* c, const uint32_t* a, const uint32_t* b) {
    asm volatile(
        "mma.sync.aligned.m16n8k8.row.col.f32.tf32.tf32.f32 "
        "{%0,%1,%2,%3}, {%4,%5,%6,%7}, {%8,%9}, {%0,%1,%2,%3};\n"
        : "+f"(c[0]), "+f"(c[1]), "+f"(c[2]), "+f"(c[3])
        : "r"(a[0]), "r"(a[1]), "r"(a[2]), "r"(a[3]), "r"(b[0]), "r"(b[1]));
}

__device__ __forceinline__ void cp16(float* s, const float* g, bool valid) {
    uint32_t sa = (uint32_t)__cvta_generic_to_shared(s);
    int sz = valid ? 16 : 0;
    asm volatile("cp.async.cg.shared.global [%0], [%1], 16, %2;" ::"r"(sa), "l"(g), "r"(sz));
}

// MODE: 0 = fp32 store (+PRELU), 1 = bf16 store, 2 = fused residual+LayerNorm
template <int MODE, bool PRELU>
__device__ __forceinline__ void gemm_body(const float* __restrict__ A,
                                          const float* __restrict__ B,
                                          const float* __restrict__ bias,
                                          const float* __restrict__ alpha,
                                          float* __restrict__ C,
                                          __nv_bfloat16* __restrict__ C16,
                                          const float* __restrict__ res,
                                          const float* __restrict__ lng,
                                          const float* __restrict__ lnb, int M, int N,
                                          int K, float* sm) {
    const int tid = threadIdx.x;
    const int lane = tid & 31;
    const int wid = tid >> 5;
    const int wm = wid & 1;
    const int wn = wid >> 1;
    const int tg = lane >> 2;
    const int tc = lane & 3;

    const int row0 = blockIdx.x * TBM;
    const int col0 = blockIdx.y * TBN;

    const int a_r[4] = {(tid * 4) >> 5, (1024 + tid * 4) >> 5, (2048 + tid * 4) >> 5,
                        (3072 + tid * 4) >> 5};
    const int a_c = (tid * 4) & 31;
    const int b_r[4] = {(tid * 4) >> 7, (1024 + tid * 4) >> 7, (2048 + tid * 4) >> 7,
                        (3072 + tid * 4) >> 7};
    const int b_c = (tid * 4) & 127;

    const int T = K / TBK;

    float acc[4][4][4];
#pragma unroll
    for (int mt = 0; mt < 4; mt++)
#pragma unroll
        for (int nt = 0; nt < 4; nt++)
#pragma unroll
            for (int r = 0; r < 4; r++) acc[mt][nt][r] = 0.0f;

    {
        float* sA = sm;
        float* sB = sm + A_WORDS;
#pragma unroll
        for (int p = 0; p < 4; p++) {
            int gr = row0 + a_r[p];
            cp16(&sA[a_r[p] * ASTRIDE + a_c], A + (size_t)gr * K + a_c, gr < M);
            cp16(&sB[b_r[p] * BSTRIDE + b_c], B + (size_t)b_r[p] * N + col0 + b_c, true);
        }
        asm volatile("cp.async.commit_group;");
    }

    for (int t = 0; t < T; t++) {
        if (t + 1 < T) {
            float* sA = sm + ((t + 1) & 1) * STAGE_WORDS;
            float* sB = sA + A_WORDS;
            int k0 = (t + 1) * TBK;
#pragma unroll
            for (int p = 0; p < 4; p++) {
                int gr = row0 + a_r[p];
                cp16(&sA[a_r[p] * ASTRIDE + a_c], A + (size_t)gr * K + k0 + a_c, gr < M);
                cp16(&sB[b_r[p] * BSTRIDE + b_c], B + (size_t)(k0 + b_r[p]) * N + col0 + b_c,
                     true);
            }
            asm volatile("cp.async.commit_group;");
            asm volatile("cp.async.wait_group 1;");
        } else {
            asm volatile("cp.async.wait_group 0;");
        }
        __syncthreads();

        const float* sA = sm + (t & 1) * STAGE_WORDS;
        const float* sB = sA + A_WORDS;

#pragma unroll
        for (int ks = 0; ks < 4; ks++) {
            const int kb = ks * 8;
            uint32_t af[4][4], bf[4][2];
#pragma unroll
            for (int mt = 0; mt < 4; mt++) {
                int mrow = wm * 64 + mt * 16;
                af[mt][0] = f2tf32(sA[(mrow + tg) * ASTRIDE + kb + tc]);
                af[mt][1] = f2tf32(sA[(mrow + tg + 8) * ASTRIDE + kb + tc]);
                af[mt][2] = f2tf32(sA[(mrow + tg) * ASTRIDE + kb + tc + 4]);
                af[mt][3] = f2tf32(sA[(mrow + tg + 8) * ASTRIDE + kb + tc + 4]);
            }
#pragma unroll
            for (int nt = 0; nt < 4; nt++) {
                int ncol = wn * 32 + nt * 8;
                bf[nt][0] = f2tf32(sB[(kb + tc) * BSTRIDE + ncol + tg]);
                bf[nt][1] = f2tf32(sB[(kb + tc + 4) * BSTRIDE + ncol + tg]);
            }
#pragma unroll
            for (int mt = 0; mt < 4; mt++)
#pragma unroll
                for (int nt = 0; nt < 4; nt++) mma_tf32(acc[mt][nt], af[mt], bf[nt]);
        }
        __syncthreads();
    }

    if (MODE == 2) {
        // stage acc + bias + residual into smem, then warp-per-row LayerNorm
        float* se = sm;
#pragma unroll
        for (int mt = 0; mt < 4; mt++) {
#pragma unroll
            for (int nt = 0; nt < 4; nt++) {
                int lc = wn * 32 + nt * 8 + tc * 2;
                int gc = col0 + lc;
                float b0 = bias[gc], b1 = bias[gc + 1];
                int lr = wm * 64 + mt * 16 + tg;
                int gr = row0 + lr;
                if (gr < M) {
                    float2 rr = *(const float2*)(res + (size_t)gr * N + gc);
                    se[lr * LNSTRIDE + lc] = acc[mt][nt][0] + b0 + rr.x;
                    se[lr * LNSTRIDE + lc + 1] = acc[mt][nt][1] + b1 + rr.y;
                }
                if (gr + 8 < M) {
                    float2 rr = *(const float2*)(res + (size_t)(gr + 8) * N + gc);
                    se[(lr + 8) * LNSTRIDE + lc] = acc[mt][nt][2] + b0 + rr.x;
                    se[(lr + 8) * LNSTRIDE + lc + 1] = acc[mt][nt][3] + b1 + rr.y;
                }
            }
        }
        __syncthreads();
        float4 gv = *(const float4*)(lng + lane * 4);
        float4 bv = *(const float4*)(lnb + lane * 4);
#pragma unroll
        for (int r = 0; r < 16; r++) {
            int lrow = wid * 16 + r;
            int grow = row0 + lrow;
            if (grow >= M) continue;
            float4 vx = *(const float4*)&se[lrow * LNSTRIDE + lane * 4];
            float s = vx.x + vx.y + vx.z + vx.w;
            float s2 = vx.x * vx.x + vx.y * vx.y + vx.z * vx.z + vx.w * vx.w;
#pragma unroll
            for (int o = 16; o > 0; o >>= 1) {
                s += __shfl_xor_sync(0xffffffffu, s, o);
                s2 += __shfl_xor_sync(0xffffffffu, s2, o);
            }
            float mean = s * (1.0f / D);
            float var = s2 * (1.0f / D) - mean * mean;
            float rstd = rsqrtf(var + 1e-5f);
            float4 o;
            o.x = (vx.x - mean) * rstd * gv.x + bv.x;
            o.y = (vx.y - mean) * rstd * gv.y + bv.y;
            o.z = (vx.z - mean) * rstd * gv.z + bv.z;
            o.w = (vx.w - mean) * rstd * gv.w + bv.w;
            *(float4*)(C + (size_t)grow * N + lane * 4) = o;
        }
        return;
    }

#pragma unroll
    for (int mt = 0; mt < 4; mt++) {
#pragma unroll
        for (int nt = 0; nt < 4; nt++) {
            int gc = col0 + wn * 32 + nt * 8 + tc * 2;
            float b0 = bias[gc], b1 = bias[gc + 1];
            float v0 = acc[mt][nt][0] + b0;
            float v1 = acc[mt][nt][1] + b1;
            float v2 = acc[mt][nt][2] + b0;
            float v3 = acc[mt][nt][3] + b1;
            if (PRELU) {
                float a0 = alpha[gc], a1 = alpha[gc + 1];
                v0 = v0 > 0.f ? v0 : a0 * v0;
                v1 = v1 > 0.f ? v1 : a1 * v1;
                v2 = v2 > 0.f ? v2 : a0 * v2;
                v3 = v3 > 0.f ? v3 : a1 * v3;
            }
            int gr = row0 + wm * 64 + mt * 16 + tg;
            if (MODE == 1) {
                if (gr < M)
                    *(__nv_bfloat162*)(C16 + (size_t)gr * N + gc) =
                        __floats2bfloat162_rn(v0, v1);
                if (gr + 8 < M)
                    *(__nv_bfloat162*)(C16 + (size_t)(gr + 8) * N + gc) =
                        __floats2bfloat162_rn(v2, v3);
            } else {
                if (gr < M) *(float2*)(C + (size_t)gr * N + gc) = make_float2(v0, v1);
                if (gr + 8 < M) *(float2*)(C + (size_t)(gr + 8) * N + gc) = make_float2(v2, v3);
            }
        }
    }
}

// fused q/k/v projection: blockIdx.z selects weight/bias/output, bf16 out
__global__ __launch_bounds__(256, 2) void qkv_gemm(
    const float* __restrict__ A, const float* __restrict__ Wq,
    const float* __restrict__ Wk, const float* __restrict__ Wv,
    const float* __restrict__ bq, const float* __restrict__ bk,
    const float* __restrict__ bv, __nv_bfloat16* __restrict__ q16,
    __nv_bfloat16* __restrict__ k16, __nv_bfloat16* __restrict__ v16, int M) {
    extern __shared__ float sm[];
    const float* B = (blockIdx.z == 0) ? Wq : (blockIdx.z == 1) ? Wk : Wv;
    const float* bias = (blockIdx.z == 0) ? bq : (blockIdx.z == 1) ? bk : bv;
    __nv_bfloat16* C16 = (blockIdx.z == 0) ? q16 : (blockIdx.z == 1) ? k16 : v16;
    gemm_body<1, false>(A, B, bias, nullptr, nullptr, C16, nullptr, nullptr, nullptr, M, D, D,
                        sm);
}

// W1: fp32 out + PReLU
__global__ __launch_bounds__(256, 2) void w1_gemm(
    const float* __restrict__ A, const float* __restrict__ B,
    const float* __restrict__ bias, const float* __restrict__ alpha,
    float* __restrict__ C, int M) {
    extern __shared__ float sm[];
    gemm_body<0, true>(A, B, bias, alpha, C, nullptr, nullptr, nullptr, nullptr, M, F, D, sm);
}

// W2 + residual + LN2, writes final output
__global__ __launch_bounds__(256, 2) void w2_ln_gemm(
    const float* __restrict__ A, const float* __restrict__ B,
    const float* __restrict__ bias, const float* __restrict__ res,
    const float* __restrict__ lng, const float* __restrict__ lnb, float* __restrict__ out,
    int M) {
    extern __shared__ float sm[];
    gemm_body<2, false>(A, B, bias, nullptr, out, nullptr, res, lng, lnb, M, D, F, sm);
}

// ---------------- CSR build --------------------------------------------------
__global__ void hist_kernel(const int* __restrict__ dst, int* __restrict__ counts, int E) {
    int i = blockIdx.x * blockDim.x + threadIdx.x;
    if (i < E) atomicAdd(&counts[dst[i]], 1);
}

__global__ void scan1_kernel(const int* __restrict__ counts, int* __restrict__ rowptr,
                             int* __restrict__ bsums, int n) {
    __shared__ int wsum[8];
    int base = blockIdx.x * 1024 + threadIdx.x * 4;
    int lane = threadIdx.x & 31, wid = threadIdx.x >> 5;
    int v[4];
#pragma unroll
    for (int i = 0; i < 4; i++) v[i] = (base + i < n) ? counts[base + i] : 0;
    int t = v[0] + v[1] + v[2] + v[3];
    int sc = t;
#pragma unroll
    for (int o = 1; o < 32; o <<= 1) {
        int x = __shfl_up_sync(0xffffffffu, sc, o);
        if (lane >= o) sc += x;
    }
    if (lane == 31) wsum[wid] = sc;
    __syncthreads();
    if (wid == 0) {
        int ws = (lane < 8) ? wsum[lane] : 0;
#pragma unroll
        for (int o = 1; o < 8; o <<= 1) {
            int x = __shfl_up_sync(0xffffffffu, ws, o);
            if (lane >= o) ws += x;
        }
        if (lane < 8) wsum[lane] = ws;
    }
    __syncthreads();
    int run = sc - t + (wid > 0 ? wsum[wid - 1] : 0);
#pragma unroll
    for (int i = 0; i < 4; i++) {
        if (base + i < n) rowptr[base + i] = run;
        run += v[i];
    }
    if (threadIdx.x == 0) bsums[blockIdx.x] = wsum[7];
}

__global__ void scan2_kernel(int* __restrict__ bsums, int nb) {
    if (threadIdx.x == 0 && blockIdx.x == 0) {
        int run = 0;
        for (int i = 0; i < nb; i++) {
            int t = bsums[i];
            bsums[i] = run;
            run += t;
        }
    }
}

__global__ void scan3_kernel(int* __restrict__ rowptr, int* __restrict__ wp,
                             const int* __restrict__ bsums, int n, int E) {
    int i = blockIdx.x * blockDim.x + threadIdx.x;
    if (i < n) {
        int v = rowptr[i] + bsums[i >> 10];
        rowptr[i] = v;
        wp[i] = v;
    }
    if (i == 0) rowptr[n] = E;
}

__global__ void fill_kernel(const int* __restrict__ src, const int* __restrict__ dst,
                            int* __restrict__ wp, int* __restrict__ srcl, int E) {
    int i = blockIdx.x * blockDim.x + threadIdx.x;
    if (i >= E) return;
    int pos = atomicAdd(&wp[dst[i]], 1);
    srcl[pos] = src[i];
}

// ---------------- fused per-node attention + LN1 ----------------------------
__device__ __forceinline__ float2 bf2f(uint32_t u) {
    return __bfloat1622float2(*reinterpret_cast<__nv_bfloat162*>(&u));
}

__global__ __launch_bounds__(256) void node_attn_ln(
    const __nv_bfloat16* __restrict__ q, const __nv_bfloat16* __restrict__ k,
    const __nv_bfloat16* __restrict__ v, const int* __restrict__ rowptr,
    const int* __restrict__ srcl, const float* __restrict__ feat,
    const float* __restrict__ g, const float* __restrict__ b, float* __restrict__ out,
    int n) {
    int node = blockIdx.x * 8 + (threadIdx.x >> 5);
    if (node >= n) return;
    int lane = threadIdx.x & 31;

    uint2 qraw = *(const uint2*)(q + (size_t)node * D + lane * 4);
    float2 q0 = bf2f(qraw.x);
    float2 q1 = bf2f(qraw.y);

    int start = rowptr[node], end = rowptr[node + 1];

    float a0 = 0.f, a1 = 0.f, a2 = 0.f, a3 = 0.f, den = 0.f;

    for (int eb = start; eb < end; eb += 32) {
        int me = eb + lane;
        int sid = (me < end) ? srcl[me] : 0;
        int cnt = min(32, end - eb);
        int j = 0;
        for (; j + 4 <= cnt; j += 4) {
            int s0 = __shfl_sync(0xffffffffu, sid, j);
            int s1 = __shfl_sync(0xffffffffu, sid, j + 1);
            int s2 = __shfl_sync(0xffffffffu, sid, j + 2);
            int s3 = __shfl_sync(0xffffffffu, sid, j + 3);
            uint2 kr0 = *(const uint2*)(k + (size_t)s0 * D + lane * 4);
            uint2 kr1 = *(const uint2*)(k + (size_t)s1 * D + lane * 4);
            uint2 kr2 = *(const uint2*)(k + (size_t)s2 * D + lane * 4);
            uint2 kr3 = *(const uint2*)(k + (size_t)s3 * D + lane * 4);
            uint2 vr0 = *(const uint2*)(v + (size_t)s0 * D + lane * 4);
            uint2 vr1 = *(const uint2*)(v + (size_t)s1 * D + lane * 4);
            uint2 vr2 = *(const uint2*)(v + (size_t)s2 * D + lane * 4);
            uint2 vr3 = *(const uint2*)(v + (size_t)s3 * D + lane * 4);
            float2 ka, kb2;
            float p0, p1, p2, p3;
            ka = bf2f(kr0.x); kb2 = bf2f(kr0.y);
            p0 = ka.x * q0.x + ka.y * q0.y + kb2.x * q1.x + kb2.y * q1.y;
            ka = bf2f(kr1.x); kb2 = bf2f(kr1.y);
            p1 = ka.x * q0.x + ka.y * q0.y + kb2.x * q1.x + kb2.y * q1.y;
            ka = bf2f(kr2.x); kb2 = bf2f(kr2.y);
            p2 = ka.x * q0.x + ka.y * q0.y + kb2.x * q1.x + kb2.y * q1.y;
            ka = bf2f(kr3.x); kb2 = bf2f(kr3.y);
            p3 = ka.x * q0.x + ka.y * q0.y + kb2.x * q1.x + kb2.y * q1.y;
            p0 += __shfl_xor_sync(0xffffffffu, p0, 1);
            p1 += __shfl_xor_sync(0xffffffffu, p1, 1);
            p2 += __shfl_xor_sync(0xffffffffu, p2, 1);
            p3 += __shfl_xor_sync(0xffffffffu, p3, 1);
            p0 += __shfl_xor_sync(0xffffffffu, p0, 2);
            p1 += __shfl_xor_sync(0xffffffffu, p1, 2);
            p2 += __shfl_xor_sync(0xffffffffu, p2, 2);
            p3 += __shfl_xor_sync(0xffffffffu, p3, 2);
            float e0 = __expf(p0 * 0.08838834764831843f);
            float e1 = __expf(p1 * 0.08838834764831843f);
            float e2 = __expf(p2 * 0.08838834764831843f);
            float e3 = __expf(p3 * 0.08838834764831843f);
            den += (e0 + e1) + (e2 + e3);
            float2 va, vb2;
            va = bf2f(vr0.x); vb2 = bf2f(vr0.y);
            a0 += va.x * e0; a1 += va.y * e0; a2 += vb2.x * e0; a3 += vb2.y * e0;
            va = bf2f(vr1.x); vb2 = bf2f(vr1.y);
            a0 += va.x * e1; a1 += va.y * e1; a2 += vb2.x * e1; a3 += vb2.y * e1;
            va = bf2f(vr2.x); vb2 = bf2f(vr2.y);
            a0 += va.x * e2; a1 += va.y * e2; a2 += vb2.x * e2; a3 += vb2.y * e2;
            va = bf2f(vr3.x); vb2 = bf2f(vr3.y);
            a0 += va.x * e3; a1 += va.y * e3; a2 += vb2.x * e3; a3 += vb2.y * e3;
        }
        for (; j < cnt; j++) {
            int s = __shfl_sync(0xffffffffu, sid, j);
            uint2 kr = *(const uint2*)(k + (size_t)s * D + lane * 4);
            uint2 vr = *(const uint2*)(v + (size_t)s * D + lane * 4);
            float2 k0 = bf2f(kr.x), k1 = bf2f(kr.y);
            float p = k0.x * q0.x + k0.y * q0.y + k1.x * q1.x + k1.y * q1.y;
            p += __shfl_xor_sync(0xffffffffu, p, 1);
            p += __shfl_xor_sync(0xffffffffu, p, 2);
            float ex = __expf(p * 0.08838834764831843f);
            den += ex;
            float2 v0 = bf2f(vr.x), v1 = bf2f(vr.y);
            a0 += v0.x * ex;
            a1 += v0.y * ex;
            a2 += v1.x * ex;
            a3 += v1.y * ex;
        }
    }

    float inv = den > 0.f ? 1.0f / den : 0.0f;
    float4 fv = *(const float4*)(feat + (size_t)node * D + lane * 4);
    float r0 = a0 * inv + fv.x;
    float r1 = a1 * inv + fv.y;
    float r2 = a2 * inv + fv.z;
    float r3 = a3 * inv + fv.w;

    float s = r0 + r1 + r2 + r3;
    float s2 = r0 * r0 + r1 * r1 + r2 * r2 + r3 * r3;
#pragma unroll
    for (int o = 16; o > 0; o >>= 1) {
        s += __shfl_xor_sync(0xffffffffu, s, o);
        s2 += __shfl_xor_sync(0xffffffffu, s2, o);
    }
    float mean = s * (1.0f / D);
    float var = s2 * (1.0f / D) - mean * mean;
    float rstd = rsqrtf(var + 1e-5f);
    float4 gv = *(const float4*)(g + lane * 4);
    float4 bv = *(const float4*)(b + lane * 4);
    float4 o;
    o.x = (r0 - mean) * rstd * gv.x + bv.x;
    o.y = (r1 - mean) * rstd * gv.y + bv.y;
    o.z = (r2 - mean) * rstd * gv.z + bv.z;
    o.w = (r3 - mean) * rstd * gv.w + bv.w;
    *(float4*)(out + (size_t)node * D + lane * 4) = o;
}

// ---------------- launch ----------------------------------------------------
extern "C" void kernel_launch(void* const* d_in, const int* in_sizes, int n_in,
                              void* d_out, int out_size) {
    const float* feat = (const float*)d_in[0];
    const int* src = (const int*)d_in[1];
    const int* dst = (const int*)d_in[2];
    const float* Wq = (const float*)d_in[3];
    const float* bq = (const float*)d_in[4];
    const float* Wk = (const float*)d_in[5];
    const float* bk = (const float*)d_in[6];
    const float* Wv = (const float*)d_in[7];
    const float* bv = (const float*)d_in[8];
    const float* ln_g = (const float*)d_in[9];
    const float* ln_b = (const float*)d_in[10];
    const float* W1 = (const float*)d_in[11];
    const float* b1 = (const float*)d_in[12];
    const float* alpha = (const float*)d_in[13];
    const float* W2 = (const float*)d_in[14];
    const float* b2 = (const float*)d_in[15];

    const int N = in_sizes[0] / D;
    const int E = in_sizes[1];

    __nv_bfloat16 *q16, *k16, *v16;
    float *rstln, *hb;
    int *counts, *rowptr, *wp, *srcl, *bsums;
    cudaGetSymbolAddress((void**)&q16, g_q16);
    cudaGetSymbolAddress((void**)&k16, g_k16);
    cudaGetSymbolAddress((void**)&v16, g_v16);
    cudaGetSymbolAddress((void**)&rstln, g_rstln);
    cudaGetSymbolAddress((void**)&hb, g_h);
    cudaGetSymbolAddress((void**)&counts, g_counts);
    cudaGetSymbolAddress((void**)&rowptr, g_rowptr);
    cudaGetSymbolAddress((void**)&wp, g_wp);
    cudaGetSymbolAddress((void**)&srcl, g_srcl);
    cudaGetSymbolAddress((void**)&bsums, g_bsums);

    static int attr_set = 0;
    if (!attr_set) {
        cudaFuncSetAttribute(qkv_gemm, cudaFuncAttributeMaxDynamicSharedMemorySize, GEMM_SMEM);
        cudaFuncSetAttribute(w1_gemm, cudaFuncAttributeMaxDynamicSharedMemorySize, GEMM_SMEM);
        cudaFuncSetAttribute(w2_ln_gemm, cudaFuncAttributeMaxDynamicSharedMemorySize,
                             GEMM_SMEM);
        attr_set = 1;
    }

    const int mgrid = (N + TBM - 1) / TBM;
    const int nb = (N + 1023) / 1024;

    // ---- CSR build
    cudaMemsetAsync(counts, 0, (size_t)N * sizeof(int), 0);
    hist_kernel<<<(E + 255) / 256, 256>>>(dst, counts, E);
    scan1_kernel<<<nb, 256>>>(counts, rowptr, bsums, N);
    scan2_kernel<<<1, 32>>>(bsums, nb);
    scan3_kernel<<<(N + 255) / 256, 256>>>(rowptr, wp, bsums, N, E);
    fill_kernel<<<(E + 255) / 256, 256>>>(src, dst, wp, srcl, E);

    // ---- fused q/k/v projections (bf16 out)
    qkv_gemm<<<dim3(mgrid, 1, 3), 256, GEMM_SMEM>>>(feat, Wq, Wk, Wv, bq, bk, bv, q16, k16,
                                                    v16, N);

    // ---- fused per-node attention + LN1
    node_attn_ln<<<(N + 7) / 8, 256>>>(q16, k16, v16, rowptr, srcl, feat, ln_g, ln_b, rstln,
                                       N);

    // ---- FFN: W1 (+PReLU), then W2 + residual + LN2 fused into final output
    w1_gemm<<<dim3(mgrid, F / TBN), 256, GEMM_SMEM>>>(rstln, W1, b1, alpha, hb, N);
    w2_ln_gemm<<<dim3(mgrid, 1), 256, GEMM_SMEM>>>(hb, W2, b2, rstln, ln_g, ln_b,
                                                   (float*)d_out, N);
}

// round 10
// speedup vs baseline: 4.6978x; 1.1584x over previous
#include <cuda_runtime.h>
#include <cuda_bf16.h>
#include <cuda_fp16.h>
#include <math.h>
#include <stdint.h>

#define NODES_MAX 100000
#define EDGES_MAX 1600000
#define D 128
#define H 8
#define F 512

// ---------------- scratch (static device globals; no allocation allowed) ----
__device__ __nv_bfloat16 g_q16[NODES_MAX * D];
__device__ __nv_bfloat16 g_k16[NODES_MAX * D];
__device__ __nv_bfloat16 g_v16[NODES_MAX * D];
__device__ float g_rstln[NODES_MAX * D];
__device__ __half g_rstln16[NODES_MAX * D];
__device__ __half g_h16[NODES_MAX * F];
// CSR build
__device__ int g_counts[NODES_MAX];
__device__ int g_rowptr[NODES_MAX + 1];
__device__ int g_wp[NODES_MAX];
__device__ int g_srcl[EDGES_MAX];
__device__ int g_bsums[256];

// ---------------- fp16 tensor-core GEMM core, cp.async double-buffered ------
// CTA tile 128x128x32, 8 warps (2x4), warp tile 64x32, mma.m16n8k16.f16 fp32-acc.
#define TBM 128
#define TBN 128
#define TBK 32
#define AS32 40            // fp32 A smem stride (floats)
#define AS16 40            // fp16 A smem stride (halves)
#define BSTR 132           // fp32 B smem stride (floats)
#define A32_BYTES (128 * AS32 * 4)   // 20480
#define A16_BYTES (128 * AS16 * 2)   // 10240
#define B_BYTES (32 * BSTR * 4)      // 16896
#define LNSTRIDE 132
#define GEMM_SMEM (2 * (A32_BYTES + B_BYTES))  // 74752 (covers LN staging too)

__device__ __forceinline__ uint32_t packh2(float lo, float hi) {
    __half2 h = __floats2half2_rn(lo, hi);
    return *reinterpret_cast<uint32_t*>(&h);
}

__device__ __forceinline__ void mma_f16(float* c, const uint32_t* a, const uint32_t* b) {
    asm volatile(
        "mma.sync.aligned.m16n8k16.row.col.f32.f16.f16.f32 "
        "{%0,%1,%2,%3}, {%4,%5,%6,%7}, {%8,%9}, {%0,%1,%2,%3};\n"
        : "+f"(c[0]), "+f"(c[1]), "+f"(c[2]), "+f"(c[3])
        : "r"(a[0]), "r"(a[1]), "r"(a[2]), "r"(a[3]), "r"(b[0]), "r"(b[1]));
}

__device__ __forceinline__ void cp16(void* s, const void* g, bool valid) {
    uint32_t sa = (uint32_t)__cvta_generic_to_shared(s);
    int sz = valid ? 16 : 0;
    asm volatile("cp.async.cg.shared.global [%0], [%1], 16, %2;" ::"r"(sa), "l"(g), "r"(sz));
}

// MODE: 0 = fp16 store (+PReLU), 1 = bf16 store, 2 = fused residual+LayerNorm(fp32 out)
template <int MODE, bool PRELU, bool AHALF>
__device__ __forceinline__ void gemm_body(const void* __restrict__ Ap,
                                          const float* __restrict__ B,
                                          const float* __restrict__ bias,
                                          const float* __restrict__ alpha,
                                          float* __restrict__ C,
                                          __nv_bfloat16* __restrict__ Cb,
                                          __half* __restrict__ Ch,
                                          const float* __restrict__ res,
                                          const float* __restrict__ lng,
                                          const float* __restrict__ lnb, int M, int N,
                                          int K) {
    extern __shared__ char smem[];
    constexpr int A_BYTES = AHALF ? A16_BYTES : A32_BYTES;
    constexpr int STAGE = A_BYTES + B_BYTES;

    const int tid = threadIdx.x;
    const int lane = tid & 31;
    const int wid = tid >> 5;
    const int wm = wid & 1;
    const int wn = wid >> 1;
    const int tg = lane >> 2;
    const int tc = lane & 3;

    const int row0 = blockIdx.x * TBM;
    const int col0 = blockIdx.y * TBN;
    const int T = K / TBK;

    float acc[4][4][4];
#pragma unroll
    for (int mt = 0; mt < 4; mt++)
#pragma unroll
        for (int nt = 0; nt < 4; nt++)
#pragma unroll
            for (int r = 0; r < 4; r++) acc[mt][nt][r] = 0.0f;

    auto fill = [&](int t) {
        char* st = smem + (t & 1) * STAGE;
        const int k0 = t * TBK;
        if (AHALF) {
            const __half* A16 = (const __half*)Ap;
#pragma unroll
            for (int p = 0; p < 2; p++) {
                int idx = tid + p * 256;
                int r = idx >> 2, c8 = (idx & 3) * 8;
                int gr = row0 + r;
                cp16(st + r * (AS16 * 2) + c8 * 2, A16 + (size_t)gr * K + k0 + c8, gr < M);
            }
        } else {
            const float* A32 = (const float*)Ap;
#pragma unroll
            for (int p = 0; p < 4; p++) {
                int idx = tid + p * 256;
                int r = idx >> 3, c4 = (idx & 7) * 4;
                int gr = row0 + r;
                cp16(st + r * (AS32 * 4) + c4 * 4, A32 + (size_t)gr * K + k0 + c4, gr < M);
            }
        }
        char* sb = st + A_BYTES;
#pragma unroll
        for (int p = 0; p < 4; p++) {
            int idx = tid + p * 256;
            int r = idx >> 5, c4 = (idx & 31) * 4;
            cp16(sb + r * (BSTR * 4) + c4 * 4, B + (size_t)(k0 + r) * N + col0 + c4, true);
        }
        asm volatile("cp.async.commit_group;");
    };

    fill(0);

    for (int t = 0; t < T; t++) {
        if (t + 1 < T) {
            fill(t + 1);
            asm volatile("cp.async.wait_group 1;");
        } else {
            asm volatile("cp.async.wait_group 0;");
        }
        __syncthreads();

        const char* st = smem + (t & 1) * STAGE;
        const __half* sA16 = (const __half*)st;
        const float* sA32 = (const float*)st;
        const float* sB = (const float*)(st + A_BYTES);

#pragma unroll
        for (int ks = 0; ks < 2; ks++) {
            const int kb = ks * 16;
            uint32_t af[4][4], bf[4][2];
#pragma unroll
            for (int mt = 0; mt < 4; mt++) {
                int mrow = wm * 64 + mt * 16;
                if (AHALF) {
                    af[mt][0] = *(const uint32_t*)&sA16[(mrow + tg) * AS16 + kb + 2 * tc];
                    af[mt][1] = *(const uint32_t*)&sA16[(mrow + tg + 8) * AS16 + kb + 2 * tc];
                    af[mt][2] =
                        *(const uint32_t*)&sA16[(mrow + tg) * AS16 + kb + 2 * tc + 8];
                    af[mt][3] =
                        *(const uint32_t*)&sA16[(mrow + tg + 8) * AS16 + kb + 2 * tc + 8];
                } else {
                    float2 x0 = *(const float2*)&sA32[(mrow + tg) * AS32 + kb + 2 * tc];
                    float2 x1 = *(const float2*)&sA32[(mrow + tg + 8) * AS32 + kb + 2 * tc];
                    float2 x2 =
                        *(const float2*)&sA32[(mrow + tg) * AS32 + kb + 2 * tc + 8];
                    float2 x3 =
                        *(const float2*)&sA32[(mrow + tg + 8) * AS32 + kb + 2 * tc + 8];
                    af[mt][0] = packh2(x0.x, x0.y);
                    af[mt][1] = packh2(x1.x, x1.y);
                    af[mt][2] = packh2(x2.x, x2.y);
                    af[mt][3] = packh2(x3.x, x3.y);
                }
            }
#pragma unroll
            for (int nt = 0; nt < 4; nt++) {
                int ncol = wn * 32 + nt * 8 + tg;
                float e0 = sB[(kb + 2 * tc) * BSTR + ncol];
                float e1 = sB[(kb + 2 * tc + 1) * BSTR + ncol];
                float e2 = sB[(kb + 2 * tc + 8) * BSTR + ncol];
                float e3 = sB[(kb + 2 * tc + 9) * BSTR + ncol];
                bf[nt][0] = packh2(e0, e1);
                bf[nt][1] = packh2(e2, e3);
            }
#pragma unroll
            for (int mt = 0; mt < 4; mt++)
#pragma unroll
                for (int nt = 0; nt < 4; nt++) mma_f16(acc[mt][nt], af[mt], bf[nt]);
        }
        __syncthreads();
    }

    if (MODE == 2) {
        float* se = (float*)smem;
#pragma unroll
        for (int mt = 0; mt < 4; mt++) {
#pragma unroll
            for (int nt = 0; nt < 4; nt++) {
                int lc = wn * 32 + nt * 8 + tc * 2;
                int gc = col0 + lc;
                float b0 = bias[gc], b1 = bias[gc + 1];
                int lr = wm * 64 + mt * 16 + tg;
                int gr = row0 + lr;
                if (gr < M) {
                    float2 rr = *(const float2*)(res + (size_t)gr * N + gc);
                    se[lr * LNSTRIDE + lc] = acc[mt][nt][0] + b0 + rr.x;
                    se[lr * LNSTRIDE + lc + 1] = acc[mt][nt][1] + b1 + rr.y;
                }
                if (gr + 8 < M) {
                    float2 rr = *(const float2*)(res + (size_t)(gr + 8) * N + gc);
                    se[(lr + 8) * LNSTRIDE + lc] = acc[mt][nt][2] + b0 + rr.x;
                    se[(lr + 8) * LNSTRIDE + lc + 1] = acc[mt][nt][3] + b1 + rr.y;
                }
            }
        }
        __syncthreads();
        float4 gv = *(const float4*)(lng + lane * 4);
        float4 bv = *(const float4*)(lnb + lane * 4);
#pragma unroll
        for (int r = 0; r < 16; r++) {
            int lrow = wid * 16 + r;
            int grow = row0 + lrow;
            if (grow >= M) continue;
            float4 vx = *(const float4*)&se[lrow * LNSTRIDE + lane * 4];
            float s = vx.x + vx.y + vx.z + vx.w;
            float s2 = vx.x * vx.x + vx.y * vx.y + vx.z * vx.z + vx.w * vx.w;
#pragma unroll
            for (int o = 16; o > 0; o >>= 1) {
                s += __shfl_xor_sync(0xffffffffu, s, o);
                s2 += __shfl_xor_sync(0xffffffffu, s2, o);
            }
            float mean = s * (1.0f / D);
            float var = s2 * (1.0f / D) - mean * mean;
            float rstd = rsqrtf(var + 1e-5f);
            float4 o;
            o.x = (vx.x - mean) * rstd * gv.x + bv.x;
            o.y = (vx.y - mean) * rstd * gv.y + bv.y;
            o.z = (vx.z - mean) * rstd * gv.z + bv.z;
            o.w = (vx.w - mean) * rstd * gv.w + bv.w;
            *(float4*)(C + (size_t)grow * N + lane * 4) = o;
        }
        return;
    }

#pragma unroll
    for (int mt = 0; mt < 4; mt++) {
#pragma unroll
        for (int nt = 0; nt < 4; nt++) {
            int gc = col0 + wn * 32 + nt * 8 + tc * 2;
            float b0 = bias[gc], b1 = bias[gc + 1];
            float v0 = acc[mt][nt][0] + b0;
            float v1 = acc[mt][nt][1] + b1;
            float v2 = acc[mt][nt][2] + b0;
            float v3 = acc[mt][nt][3] + b1;
            if (PRELU) {
                float a0 = alpha[gc], a1 = alpha[gc + 1];
                v0 = v0 > 0.f ? v0 : a0 * v0;
                v1 = v1 > 0.f ? v1 : a1 * v1;
                v2 = v2 > 0.f ? v2 : a0 * v2;
                v3 = v3 > 0.f ? v3 : a1 * v3;
            }
            int gr = row0 + wm * 64 + mt * 16 + tg;
            if (MODE == 1) {
                if (gr < M)
                    *(__nv_bfloat162*)(Cb + (size_t)gr * N + gc) =
                        __floats2bfloat162_rn(v0, v1);
                if (gr + 8 < M)
                    *(__nv_bfloat162*)(Cb + (size_t)(gr + 8) * N + gc) =
                        __floats2bfloat162_rn(v2, v3);
            } else {
                if (gr < M)
                    *(__half2*)(Ch + (size_t)gr * N + gc) = __floats2half2_rn(v0, v1);
                if (gr + 8 < M)
                    *(__half2*)(Ch + (size_t)(gr + 8) * N + gc) = __floats2half2_rn(v2, v3);
            }
        }
    }
}

// fused q/k/v projection: blockIdx.z selects weight/bias/output, bf16 out, fp32 A
__global__ __launch_bounds__(256, 2) void qkv_gemm(
    const float* __restrict__ A, const float* __restrict__ Wq,
    const float* __restrict__ Wk, const float* __restrict__ Wv,
    const float* __restrict__ bq, const float* __restrict__ bk,
    const float* __restrict__ bv, __nv_bfloat16* __restrict__ q16,
    __nv_bfloat16* __restrict__ k16, __nv_bfloat16* __restrict__ v16, int M) {
    const float* B = (blockIdx.z == 0) ? Wq : (blockIdx.z == 1) ? Wk : Wv;
    const float* bias = (blockIdx.z == 0) ? bq : (blockIdx.z == 1) ? bk : bv;
    __nv_bfloat16* Cb = (blockIdx.z == 0) ? q16 : (blockIdx.z == 1) ? k16 : v16;
    gemm_body<1, false, false>(A, B, bias, nullptr, nullptr, Cb, nullptr, nullptr, nullptr,
                               nullptr, M, D, D);
}

// W1: fp16 A (rstln16) -> fp16 out (hb16) + PReLU
__global__ __launch_bounds__(256, 2) void w1_gemm(
    const __half* __restrict__ A, const float* __restrict__ B,
    const float* __restrict__ bias, const float* __restrict__ alpha,
    __half* __restrict__ C, int M) {
    gemm_body<0, true, true>(A, B, bias, alpha, nullptr, nullptr, C, nullptr, nullptr,
                             nullptr, M, F, D);
}

// W2: fp16 A (hb16) + residual(fp32) + LN2 -> final output
__global__ __launch_bounds__(256, 2) void w2_ln_gemm(
    const __half* __restrict__ A, const float* __restrict__ B,
    const float* __restrict__ bias, const float* __restrict__ res,
    const float* __restrict__ lng, const float* __restrict__ lnb, float* __restrict__ out,
    int M) {
    gemm_body<2, false, true>(A, B, bias, nullptr, out, nullptr, nullptr, res, lng, lnb, M,
                              D, F);
}

// ---------------- CSR build --------------------------------------------------
__global__ void hist_kernel(const int* __restrict__ dst, int* __restrict__ counts, int E) {
    int i = blockIdx.x * blockDim.x + threadIdx.x;
    if (i < E) atomicAdd(&counts[dst[i]], 1);
}

__global__ void scan1_kernel(const int* __restrict__ counts, int* __restrict__ rowptr,
                             int* __restrict__ bsums, int n) {
    __shared__ int wsum[8];
    int base = blockIdx.x * 1024 + threadIdx.x * 4;
    int lane = threadIdx.x & 31, wid = threadIdx.x >> 5;
    int v[4];
#pragma unroll
    for (int i = 0; i < 4; i++) v[i] = (base + i < n) ? counts[base + i] : 0;
    int t = v[0] + v[1] + v[2] + v[3];
    int sc = t;
#pragma unroll
    for (int o = 1; o < 32; o <<= 1) {
        int x = __shfl_up_sync(0xffffffffu, sc, o);
        if (lane >= o) sc += x;
    }
    if (lane == 31) wsum[wid] = sc;
    __syncthreads();
    if (wid == 0) {
        int ws = (lane < 8) ? wsum[lane] : 0;
#pragma unroll
        for (int o = 1; o < 8; o <<= 1) {
            int x = __shfl_up_sync(0xffffffffu, ws, o);
            if (lane >= o) ws += x;
        }
        if (lane < 8) wsum[lane] = ws;
    }
    __syncthreads();
    int run = sc - t + (wid > 0 ? wsum[wid - 1] : 0);
#pragma unroll
    for (int i = 0; i < 4; i++) {
        if (base + i < n) rowptr[base + i] = run;
        run += v[i];
    }
    if (threadIdx.x == 0) bsums[blockIdx.x] = wsum[7];
}

__global__ void scan2_kernel(int* __restrict__ bsums, int nb) {
    if (threadIdx.x == 0 && blockIdx.x == 0) {
        int run = 0;
        for (int i = 0; i < nb; i++) {
            int t = bsums[i];
            bsums[i] = run;
            run += t;
        }
    }
}

__global__ void scan3_kernel(int* __restrict__ rowptr, int* __restrict__ wp,
                             const int* __restrict__ bsums, int n, int E) {
    int i = blockIdx.x * blockDim.x + threadIdx.x;
    if (i < n) {
        int v = rowptr[i] + bsums[i >> 10];
        rowptr[i] = v;
        wp[i] = v;
    }
    if (i == 0) rowptr[n] = E;
}

__global__ void fill_kernel(const int* __restrict__ src, const int* __restrict__ dst,
                            int* __restrict__ wp, int* __restrict__ srcl, int E) {
    int i = blockIdx.x * blockDim.x + threadIdx.x;
    if (i >= E) return;
    int pos = atomicAdd(&wp[dst[i]], 1);
    srcl[pos] = src[i];
}

// ---------------- fused per-node attention + LN1 ----------------------------
__device__ __forceinline__ float2 bf2f(uint32_t u) {
    return __bfloat1622float2(*reinterpret_cast<__nv_bfloat162*>(&u));
}

__global__ __launch_bounds__(256) void node_attn_ln(
    const __nv_bfloat16* __restrict__ q, const __nv_bfloat16* __restrict__ k,
    const __nv_bfloat16* __restrict__ v, const int* __restrict__ rowptr,
    const int* __restrict__ srcl, const float* __restrict__ feat,
    const float* __restrict__ g, const float* __restrict__ b, float* __restrict__ out,
    __half* __restrict__ out16, int n) {
    int node = blockIdx.x * 8 + (threadIdx.x >> 5);
    if (node >= n) return;
    int lane = threadIdx.x & 31;

    uint2 qraw = *(const uint2*)(q + (size_t)node * D + lane * 4);
    float2 q0 = bf2f(qraw.x);
    float2 q1 = bf2f(qraw.y);

    int start = rowptr[node], end = rowptr[node + 1];

    float a0 = 0.f, a1 = 0.f, a2 = 0.f, a3 = 0.f, den = 0.f;

    for (int eb = start; eb < end; eb += 32) {
        int me = eb + lane;
        int sid = (me < end) ? srcl[me] : 0;
        int cnt = min(32, end - eb);
        int j = 0;
        for (; j + 4 <= cnt; j += 4) {
            int s0 = __shfl_sync(0xffffffffu, sid, j);
            int s1 = __shfl_sync(0xffffffffu, sid, j + 1);
            int s2 = __shfl_sync(0xffffffffu, sid, j + 2);
            int s3 = __shfl_sync(0xffffffffu, sid, j + 3);
            uint2 kr0 = *(const uint2*)(k + (size_t)s0 * D + lane * 4);
            uint2 kr1 = *(const uint2*)(k + (size_t)s1 * D + lane * 4);
            uint2 kr2 = *(const uint2*)(k + (size_t)s2 * D + lane * 4);
            uint2 kr3 = *(const uint2*)(k + (size_t)s3 * D + lane * 4);
            uint2 vr0 = *(const uint2*)(v + (size_t)s0 * D + lane * 4);
            uint2 vr1 = *(const uint2*)(v + (size_t)s1 * D + lane * 4);
            uint2 vr2 = *(const uint2*)(v + (size_t)s2 * D + lane * 4);
            uint2 vr3 = *(const uint2*)(v + (size_t)s3 * D + lane * 4);
            float2 ka, kb2;
            float p0, p1, p2, p3;
            ka = bf2f(kr0.x); kb2 = bf2f(kr0.y);
            p0 = ka.x * q0.x + ka.y * q0.y + kb2.x * q1.x + kb2.y * q1.y;
            ka = bf2f(kr1.x); kb2 = bf2f(kr1.y);
            p1 = ka.x * q0.x + ka.y * q0.y + kb2.x * q1.x + kb2.y * q1.y;
            ka = bf2f(kr2.x); kb2 = bf2f(kr2.y);
            p2 = ka.x * q0.x + ka.y * q0.y + kb2.x * q1.x + kb2.y * q1.y;
            ka = bf2f(kr3.x); kb2 = bf2f(kr3.y);
            p3 = ka.x * q0.x + ka.y * q0.y + kb2.x * q1.x + kb2.y * q1.y;
            p0 += __shfl_xor_sync(0xffffffffu, p0, 1);
            p1 += __shfl_xor_sync(0xffffffffu, p1, 1);
            p2 += __shfl_xor_sync(0xffffffffu, p2, 1);
            p3 += __shfl_xor_sync(0xffffffffu, p3, 1);
            p0 += __shfl_xor_sync(0xffffffffu, p0, 2);
            p1 += __shfl_xor_sync(0xffffffffu, p1, 2);
            p2 += __shfl_xor_sync(0xffffffffu, p2, 2);
            p3 += __shfl_xor_sync(0xffffffffu, p3, 2);
            float e0 = __expf(p0 * 0.08838834764831843f);
            float e1 = __expf(p1 * 0.08838834764831843f);
            float e2 = __expf(p2 * 0.08838834764831843f);
            float e3 = __expf(p3 * 0.08838834764831843f);
            den += (e0 + e1) + (e2 + e3);
            float2 va, vb2;
            va = bf2f(vr0.x); vb2 = bf2f(vr0.y);
            a0 += va.x * e0; a1 += va.y * e0; a2 += vb2.x * e0; a3 += vb2.y * e0;
            va = bf2f(vr1.x); vb2 = bf2f(vr1.y);
            a0 += va.x * e1; a1 += va.y * e1; a2 += vb2.x * e1; a3 += vb2.y * e1;
            va = bf2f(vr2.x); vb2 = bf2f(vr2.y);
            a0 += va.x * e2; a1 += va.y * e2; a2 += vb2.x * e2; a3 += vb2.y * e2;
            va = bf2f(vr3.x); vb2 = bf2f(vr3.y);
            a0 += va.x * e3; a1 += va.y * e3; a2 += vb2.x * e3; a3 += vb2.y * e3;
        }
        for (; j < cnt; j++) {
            int s = __shfl_sync(0xffffffffu, sid, j);
            uint2 kr = *(const uint2*)(k + (size_t)s * D + lane * 4);
            uint2 vr = *(const uint2*)(v + (size_t)s * D + lane * 4);
            float2 k0 = bf2f(kr.x), k1 = bf2f(kr.y);
            float p = k0.x * q0.x + k0.y * q0.y + k1.x * q1.x + k1.y * q1.y;
            p += __shfl_xor_sync(0xffffffffu, p, 1);
            p += __shfl_xor_sync(0xffffffffu, p, 2);
            float ex = __expf(p * 0.08838834764831843f);
            den += ex;
            float2 v0 = bf2f(vr.x), v1 = bf2f(vr.y);
            a0 += v0.x * ex;
            a1 += v0.y * ex;
            a2 += v1.x * ex;
            a3 += v1.y * ex;
        }
    }

    float inv = den > 0.f ? 1.0f / den : 0.0f;
    float4 fv = *(const float4*)(feat + (size_t)node * D + lane * 4);
    float r0 = a0 * inv + fv.x;
    float r1 = a1 * inv + fv.y;
    float r2 = a2 * inv + fv.z;
    float r3 = a3 * inv + fv.w;

    float s = r0 + r1 + r2 + r3;
    float s2 = r0 * r0 + r1 * r1 + r2 * r2 + r3 * r3;
#pragma unroll
    for (int o = 16; o > 0; o >>= 1) {
        s += __shfl_xor_sync(0xffffffffu, s, o);
        s2 += __shfl_xor_sync(0xffffffffu, s2, o);
    }
    float mean = s * (1.0f / D);
    float var = s2 * (1.0f / D) - mean * mean;
    float rstd = rsqrtf(var + 1e-5f);
    float4 gv = *(const float4*)(g + lane * 4);
    float4 bv = *(const float4*)(b + lane * 4);
    float4 o;
    o.x = (r0 - mean) * rstd * gv.x + bv.x;
    o.y = (r1 - mean) * rstd * gv.y + bv.y;
    o.z = (r2 - mean) * rstd * gv.z + bv.z;
    o.w = (r3 - mean) * rstd * gv.w + bv.w;
    *(float4*)(out + (size_t)node * D + lane * 4) = o;
    __half2 h0 = __floats2half2_rn(o.x, o.y);
    __half2 h1 = __floats2half2_rn(o.z, o.w);
    uint2 hp = make_uint2(*reinterpret_cast<uint32_t*>(&h0), *reinterpret_cast<uint32_t*>(&h1));
    *(uint2*)(out16 + (size_t)node * D + lane * 4) = hp;
}

// ---------------- launch ----------------------------------------------------
extern "C" void kernel_launch(void* const* d_in, const int* in_sizes, int n_in,
                              void* d_out, int out_size) {
    const float* feat = (const float*)d_in[0];
    const int* src = (const int*)d_in[1];
    const int* dst = (const int*)d_in[2];
    const float* Wq = (const float*)d_in[3];
    const float* bq = (const float*)d_in[4];
    const float* Wk = (const float*)d_in[5];
    const float* bk = (const float*)d_in[6];
    const float* Wv = (const float*)d_in[7];
    const float* bv = (const float*)d_in[8];
    const float* ln_g = (const float*)d_in[9];
    const float* ln_b = (const float*)d_in[10];
    const float* W1 = (const float*)d_in[11];
    const float* b1 = (const float*)d_in[12];
    const float* alpha = (const float*)d_in[13];
    const float* W2 = (const float*)d_in[14];
    const float* b2 = (const float*)d_in[15];

    const int N = in_sizes[0] / D;
    const int E = in_sizes[1];

    __nv_bfloat16 *q16, *k16, *v16;
    __half *rstln16, *hb16;
    float* rstln;
    int *counts, *rowptr, *wp, *srcl, *bsums;
    cudaGetSymbolAddress((void**)&q16, g_q16);
    cudaGetSymbolAddress((void**)&k16, g_k16);
    cudaGetSymbolAddress((void**)&v16, g_v16);
    cudaGetSymbolAddress((void**)&rstln, g_rstln);
    cudaGetSymbolAddress((void**)&rstln16, g_rstln16);
    cudaGetSymbolAddress((void**)&hb16, g_h16);
    cudaGetSymbolAddress((void**)&counts, g_counts);
    cudaGetSymbolAddress((void**)&rowptr, g_rowptr);
    cudaGetSymbolAddress((void**)&wp, g_wp);
    cudaGetSymbolAddress((void**)&srcl, g_srcl);
    cudaGetSymbolAddress((void**)&bsums, g_bsums);

    static int attr_set = 0;
    if (!attr_set) {
        cudaFuncSetAttribute(qkv_gemm, cudaFuncAttributeMaxDynamicSharedMemorySize, GEMM_SMEM);
        cudaFuncSetAttribute(w1_gemm, cudaFuncAttributeMaxDynamicSharedMemorySize, GEMM_SMEM);
        cudaFuncSetAttribute(w2_ln_gemm, cudaFuncAttributeMaxDynamicSharedMemorySize,
                             GEMM_SMEM);
        attr_set = 1;
    }

    const int mgrid = (N + TBM - 1) / TBM;
    const int nb = (N + 1023) / 1024;

    // ---- CSR build
    cudaMemsetAsync(counts, 0, (size_t)N * sizeof(int), 0);
    hist_kernel<<<(E + 255) / 256, 256>>>(dst, counts, E);
    scan1_kernel<<<nb, 256>>>(counts, rowptr, bsums, N);
    scan2_kernel<<<1, 32>>>(bsums, nb);
    scan3_kernel<<<(N + 255) / 256, 256>>>(rowptr, wp, bsums, N, E);
    fill_kernel<<<(E + 255) / 256, 256>>>(src, dst, wp, srcl, E);

    // ---- fused q/k/v projections (fp16 MMA, bf16 out)
    qkv_gemm<<<dim3(mgrid, 1, 3), 256, GEMM_SMEM>>>(feat, Wq, Wk, Wv, bq, bk, bv, q16, k16,
                                                    v16, N);

    // ---- fused per-node attention + LN1 (fp32 + fp16 outputs)
    node_attn_ln<<<(N + 7) / 8, 256>>>(q16, k16, v16, rowptr, srcl, feat, ln_g, ln_b, rstln,
                                       rstln16, N);

    // ---- FFN: W1 (fp16 A/out, +PReLU), then W2 + residual + LN2 -> final output
    w1_gemm<<<dim3(mgrid, F / TBN), 256, GEMM_SMEM>>>(rstln16, W1, b1, alpha, hb16, N);
    w2_ln_gemm<<<dim3(mgrid, 1), 256, GEMM_SMEM>>>(hb16, W2, b2, rstln, ln_g, ln_b,
                                                   (float*)d_out, N);
}

// round 11
// speedup vs baseline: 5.0915x; 1.0838x over previous
#include <cuda_runtime.h>
#include <cuda_bf16.h>
#include <cuda_fp16.h>
#include <math.h>
#include <stdint.h>

#define NODES_MAX 100000
#define EDGES_MAX 1600000
#define D 128
#define H 8
#define F 512

// ---------------- scratch (static device globals; no allocation allowed) ----
__device__ __half g_feat16[NODES_MAX * D];
__device__ __nv_bfloat16 g_q16[NODES_MAX * D];
__device__ __nv_bfloat16 g_kv[NODES_MAX * 2 * D];  // interleaved k/v per 4-elem chunk
__device__ float g_rstln[NODES_MAX * D];
__device__ __half g_rstln16[NODES_MAX * D];
__device__ __half g_h16[NODES_MAX * F];
// fp16 transposed weights [N][K]
__device__ __half g_wtq[D * D];
__device__ __half g_wtk[D * D];
__device__ __half g_wtv[D * D];
__device__ __half g_wt1[F * D];
__device__ __half g_wt2[D * F];
// CSR build
__device__ int g_counts[NODES_MAX];
__device__ int g_rowptr[NODES_MAX + 1];
__device__ int g_wp[NODES_MAX];
__device__ int g_srcl[EDGES_MAX];
__device__ int g_bsums[256];

// ---------------- fp16 tensor-core GEMM core, cp.async double-buffered ------
// CTA tile 128x128x32, 8 warps (2x4), warp tile 64x32, mma.m16n8k16.f16 fp32-acc.
// A fp16 [M][K], B fp16 transposed [N][K]. Fully vectorized fragment loads.
#define TBM 128
#define TBN 128
#define TBK 32
#define STR 40                      // smem stride in halves (80B rows)
#define OP_BYTES (128 * STR * 2)    // 10240 per operand
#define STAGE (2 * OP_BYTES)        // 20480
#define GEMM_SMEM (2 * STAGE)       // 40960
#define LNSTRIDE 132
#define W2_SMEM (128 * LNSTRIDE * 4)  // 67584 (LN staging)

__device__ __forceinline__ void mma_f16(float* c, const uint32_t* a, const uint32_t* b) {
    asm volatile(
        "mma.sync.aligned.m16n8k16.row.col.f32.f16.f16.f32 "
        "{%0,%1,%2,%3}, {%4,%5,%6,%7}, {%8,%9}, {%0,%1,%2,%3};\n"
        : "+f"(c[0]), "+f"(c[1]), "+f"(c[2]), "+f"(c[3])
        : "r"(a[0]), "r"(a[1]), "r"(a[2]), "r"(a[3]), "r"(b[0]), "r"(b[1]));
}

__device__ __forceinline__ void cp16(void* s, const void* g, bool valid) {
    uint32_t sa = (uint32_t)__cvta_generic_to_shared(s);
    int sz = valid ? 16 : 0;
    asm volatile("cp.async.cg.shared.global [%0], [%1], 16, %2;" ::"r"(sa), "l"(g), "r"(sz));
}

// MODE: 0 = fp16 store (+PReLU), 1 = bf16 store (kvoff<0: plain; else kv-interleaved),
//       2 = fused residual+LayerNorm (fp32 out)
template <int MODE, bool PRELU>
__device__ __forceinline__ void gemm_body(const __half* __restrict__ A,
                                          const __half* __restrict__ Bt,
                                          const float* __restrict__ bias,
                                          const float* __restrict__ alpha,
                                          float* __restrict__ C,
                                          __nv_bfloat16* __restrict__ Cb, int kvoff,
                                          __half* __restrict__ Ch,
                                          const float* __restrict__ res,
                                          const float* __restrict__ lng,
                                          const float* __restrict__ lnb, int M, int N,
                                          int K) {
    extern __shared__ char smem[];
    const int tid = threadIdx.x;
    const int lane = tid & 31;
    const int wid = tid >> 5;
    const int wm = wid & 1;
    const int wn = wid >> 1;
    const int tg = lane >> 2;
    const int tc = lane & 3;

    const int row0 = blockIdx.x * TBM;
    const int col0 = blockIdx.y * TBN;
    const int T = K / TBK;

    float acc[4][4][4];
#pragma unroll
    for (int mt = 0; mt < 4; mt++)
#pragma unroll
        for (int nt = 0; nt < 4; nt++)
#pragma unroll
            for (int r = 0; r < 4; r++) acc[mt][nt][r] = 0.0f;

    auto fill = [&](int t) {
        char* st = smem + (t & 1) * STAGE;
        char* sb = st + OP_BYTES;
        const int k0 = t * TBK;
#pragma unroll
        for (int p = 0; p < 2; p++) {
            int idx = tid + p * 256;
            int r = idx >> 2, c8 = (idx & 3) * 8;
            int gr = row0 + r;
            cp16(st + r * 80 + c8 * 2, A + (size_t)gr * K + k0 + c8, gr < M);
            cp16(sb + r * 80 + c8 * 2, Bt + (size_t)(col0 + r) * K + k0 + c8, true);
        }
        asm volatile("cp.async.commit_group;");
    };

    fill(0);

    for (int t = 0; t < T; t++) {
        if (t + 1 < T) {
            fill(t + 1);
            asm volatile("cp.async.wait_group 1;");
        } else {
            asm volatile("cp.async.wait_group 0;");
        }
        __syncthreads();

        const char* st = smem + (t & 1) * STAGE;
        const __half* sA = (const __half*)st;
        const __half* sB = (const __half*)(st + OP_BYTES);

#pragma unroll
        for (int ks = 0; ks < 2; ks++) {
            const int kb = ks * 16;
            uint32_t af[4][4], bf[4][2];
#pragma unroll
            for (int mt = 0; mt < 4; mt++) {
                int mrow = wm * 64 + mt * 16;
                af[mt][0] = *(const uint32_t*)&sA[(mrow + tg) * STR + kb + 2 * tc];
                af[mt][1] = *(const uint32_t*)&sA[(mrow + tg + 8) * STR + kb + 2 * tc];
                af[mt][2] = *(const uint32_t*)&sA[(mrow + tg) * STR + kb + 2 * tc + 8];
                af[mt][3] = *(const uint32_t*)&sA[(mrow + tg + 8) * STR + kb + 2 * tc + 8];
            }
#pragma unroll
            for (int nt = 0; nt < 4; nt++) {
                int ncol = wn * 32 + nt * 8 + tg;
                bf[nt][0] = *(const uint32_t*)&sB[ncol * STR + kb + 2 * tc];
                bf[nt][1] = *(const uint32_t*)&sB[ncol * STR + kb + 2 * tc + 8];
            }
#pragma unroll
            for (int mt = 0; mt < 4; mt++)
#pragma unroll
                for (int nt = 0; nt < 4; nt++) mma_f16(acc[mt][nt], af[mt], bf[nt]);
        }
        __syncthreads();
    }

    if (MODE == 2) {
        float* se = (float*)smem;
#pragma unroll
        for (int mt = 0; mt < 4; mt++) {
#pragma unroll
            for (int nt = 0; nt < 4; nt++) {
                int lc = wn * 32 + nt * 8 + tc * 2;
                int gc = col0 + lc;
                float b0 = bias[gc], b1 = bias[gc + 1];
                int lr = wm * 64 + mt * 16 + tg;
                int gr = row0 + lr;
                if (gr < M) {
                    float2 rr = *(const float2*)(res + (size_t)gr * N + gc);
                    se[lr * LNSTRIDE + lc] = acc[mt][nt][0] + b0 + rr.x;
                    se[lr * LNSTRIDE + lc + 1] = acc[mt][nt][1] + b1 + rr.y;
                }
                if (gr + 8 < M) {
                    float2 rr = *(const float2*)(res + (size_t)(gr + 8) * N + gc);
                    se[(lr + 8) * LNSTRIDE + lc] = acc[mt][nt][2] + b0 + rr.x;
                    se[(lr + 8) * LNSTRIDE + lc + 1] = acc[mt][nt][3] + b1 + rr.y;
                }
            }
        }
        __syncthreads();
        float4 gv = *(const float4*)(lng + lane * 4);
        float4 bv = *(const float4*)(lnb + lane * 4);
#pragma unroll
        for (int r = 0; r < 16; r++) {
            int lrow = wid * 16 + r;
            int grow = row0 + lrow;
            if (grow >= M) continue;
            float4 vx = *(const float4*)&se[lrow * LNSTRIDE + lane * 4];
            float s = vx.x + vx.y + vx.z + vx.w;
            float s2 = vx.x * vx.x + vx.y * vx.y + vx.z * vx.z + vx.w * vx.w;
#pragma unroll
            for (int o = 16; o > 0; o >>= 1) {
                s += __shfl_xor_sync(0xffffffffu, s, o);
                s2 += __shfl_xor_sync(0xffffffffu, s2, o);
            }
            float mean = s * (1.0f / D);
            float var = s2 * (1.0f / D) - mean * mean;
            float rstd = rsqrtf(var + 1e-5f);
            float4 o;
            o.x = (vx.x - mean) * rstd * gv.x + bv.x;
            o.y = (vx.y - mean) * rstd * gv.y + bv.y;
            o.z = (vx.z - mean) * rstd * gv.z + bv.z;
            o.w = (vx.w - mean) * rstd * gv.w + bv.w;
            *(float4*)(C + (size_t)grow * N + lane * 4) = o;
        }
        return;
    }

#pragma unroll
    for (int mt = 0; mt < 4; mt++) {
#pragma unroll
        for (int nt = 0; nt < 4; nt++) {
            int gc = col0 + wn * 32 + nt * 8 + tc * 2;
            float b0 = bias[gc], b1 = bias[gc + 1];
            float v0 = acc[mt][nt][0] + b0;
            float v1 = acc[mt][nt][1] + b1;
            float v2 = acc[mt][nt][2] + b0;
            float v3 = acc[mt][nt][3] + b1;
            if (PRELU) {
                float a0 = alpha[gc], a1 = alpha[gc + 1];
                v0 = v0 > 0.f ? v0 : a0 * v0;
                v1 = v1 > 0.f ? v1 : a1 * v1;
                v2 = v2 > 0.f ? v2 : a0 * v2;
                v3 = v3 > 0.f ? v3 : a1 * v3;
            }
            int gr = row0 + wm * 64 + mt * 16 + tg;
            if (MODE == 1) {
                if (kvoff < 0) {
                    if (gr < M)
                        *(__nv_bfloat162*)(Cb + (size_t)gr * N + gc) =
                            __floats2bfloat162_rn(v0, v1);
                    if (gr + 8 < M)
                        *(__nv_bfloat162*)(Cb + (size_t)(gr + 8) * N + gc) =
                            __floats2bfloat162_rn(v2, v3);
                } else {
                    int cc = ((gc >> 2) << 3) + (gc & 3) + kvoff;
                    if (gr < M)
                        *(__nv_bfloat162*)(Cb + (size_t)gr * 2 * D + cc) =
                            __floats2bfloat162_rn(v0, v1);
                    if (gr + 8 < M)
                        *(__nv_bfloat162*)(Cb + (size_t)(gr + 8) * 2 * D + cc) =
                            __floats2bfloat162_rn(v2, v3);
                }
            } else {
                if (gr < M)
                    *(__half2*)(Ch + (size_t)gr * N + gc) = __floats2half2_rn(v0, v1);
                if (gr + 8 < M)
                    *(__half2*)(Ch + (size_t)(gr + 8) * N + gc) = __floats2half2_rn(v2, v3);
            }
        }
    }
}

// fused q/k/v projection: blockIdx.z selects weight/bias/output
__global__ __launch_bounds__(256, 2) void qkv_gemm(
    const __half* __restrict__ A, const __half* __restrict__ Wtq,
    const __half* __restrict__ Wtk, const __half* __restrict__ Wtv,
    const float* __restrict__ bq, const float* __restrict__ bk,
    const float* __restrict__ bv, __nv_bfloat16* __restrict__ q16,
    __nv_bfloat16* __restrict__ kv, int M) {
    const __half* Bt = (blockIdx.z == 0) ? Wtq : (blockIdx.z == 1) ? Wtk : Wtv;
    const float* bias = (blockIdx.z == 0) ? bq : (blockIdx.z == 1) ? bk : bv;
    __nv_bfloat16* Cb = (blockIdx.z == 0) ? q16 : kv;
    int kvoff = (blockIdx.z == 0) ? -1 : (blockIdx.z == 1) ? 0 : 4;
    gemm_body<1, false>(A, Bt, bias, nullptr, nullptr, Cb, kvoff, nullptr, nullptr, nullptr,
                        nullptr, M, D, D);
}

// W1: fp16 A (rstln16) -> fp16 out (hb16) + PReLU
__global__ __launch_bounds__(256, 2) void w1_gemm(
    const __half* __restrict__ A, const __half* __restrict__ Bt,
    const float* __restrict__ bias, const float* __restrict__ alpha,
    __half* __restrict__ C, int M) {
    gemm_body<0, true>(A, Bt, bias, alpha, nullptr, nullptr, -1, C, nullptr, nullptr,
                       nullptr, M, F, D);
}

// W2: fp16 A (hb16) + residual(fp32) + LN2 -> final output
__global__ __launch_bounds__(256, 2) void w2_ln_gemm(
    const __half* __restrict__ A, const __half* __restrict__ Bt,
    const float* __restrict__ bias, const float* __restrict__ res,
    const float* __restrict__ lng, const float* __restrict__ lnb, float* __restrict__ out,
    int M) {
    gemm_body<2, false>(A, Bt, bias, nullptr, out, nullptr, -1, nullptr, res, lng, lnb, M,
                        D, F);
}

// ---------------- conversions -------------------------------------------------
__global__ void cvt_feat16(const float* __restrict__ in, __half* __restrict__ out, int n) {
    int base = (blockIdx.x * 256 + threadIdx.x) * 8;
    if (base >= n) return;
    float4 a = *(const float4*)(in + base);
    float4 b = *(const float4*)(in + base + 4);
    __half2 h0 = __floats2half2_rn(a.x, a.y), h1 = __floats2half2_rn(a.z, a.w);
    __half2 h2 = __floats2half2_rn(b.x, b.y), h3 = __floats2half2_rn(b.z, b.w);
    *(uint4*)(out + base) =
        make_uint4(*reinterpret_cast<uint32_t*>(&h0), *reinterpret_cast<uint32_t*>(&h1),
                   *reinterpret_cast<uint32_t*>(&h2), *reinterpret_cast<uint32_t*>(&h3));
}

// out[n*K+k] = (half)in[k*N+n]
__global__ void cvt_w_t(const float* __restrict__ in, __half* __restrict__ out, int K,
                        int N) {
    int idx = blockIdx.x * 256 + threadIdx.x;
    if (idx >= K * N) return;
    int n = idx / K;
    int k = idx - n * K;
    out[idx] = __float2half(in[(size_t)k * N + n]);
}

// ---------------- CSR build --------------------------------------------------
__global__ void hist_kernel(const int* __restrict__ dst, int* __restrict__ counts, int E) {
    int i = blockIdx.x * blockDim.x + threadIdx.x;
    if (i < E) atomicAdd(&counts[dst[i]], 1);
}

__global__ void scan1_kernel(const int* __restrict__ counts, int* __restrict__ rowptr,
                             int* __restrict__ bsums, int n) {
    __shared__ int wsum[8];
    int base = blockIdx.x * 1024 + threadIdx.x * 4;
    int lane = threadIdx.x & 31, wid = threadIdx.x >> 5;
    int v[4];
#pragma unroll
    for (int i = 0; i < 4; i++) v[i] = (base + i < n) ? counts[base + i] : 0;
    int t = v[0] + v[1] + v[2] + v[3];
    int sc = t;
#pragma unroll
    for (int o = 1; o < 32; o <<= 1) {
        int x = __shfl_up_sync(0xffffffffu, sc, o);
        if (lane >= o) sc += x;
    }
    if (lane == 31) wsum[wid] = sc;
    __syncthreads();
    if (wid == 0) {
        int ws = (lane < 8) ? wsum[lane] : 0;
#pragma unroll
        for (int o = 1; o < 8; o <<= 1) {
            int x = __shfl_up_sync(0xffffffffu, ws, o);
            if (lane >= o) ws += x;
        }
        if (lane < 8) wsum[lane] = ws;
    }
    __syncthreads();
    int run = sc - t + (wid > 0 ? wsum[wid - 1] : 0);
#pragma unroll
    for (int i = 0; i < 4; i++) {
        if (base + i < n) rowptr[base + i] = run;
        run += v[i];
    }
    if (threadIdx.x == 0) bsums[blockIdx.x] = wsum[7];
}

__global__ void scan2_kernel(int* __restrict__ bsums, int nb) {
    if (threadIdx.x == 0 && blockIdx.x == 0) {
        int run = 0;
        for (int i = 0; i < nb; i++) {
            int t = bsums[i];
            bsums[i] = run;
            run += t;
        }
    }
}

__global__ void scan3_kernel(int* __restrict__ rowptr, int* __restrict__ wp,
                             const int* __restrict__ bsums, int n, int E) {
    int i = blockIdx.x * blockDim.x + threadIdx.x;
    if (i < n) {
        int v = rowptr[i] + bsums[i >> 10];
        rowptr[i] = v;
        wp[i] = v;
    }
    if (i == 0) rowptr[n] = E;
}

__global__ void fill_kernel(const int* __restrict__ src, const int* __restrict__ dst,
                            int* __restrict__ wp, int* __restrict__ srcl, int E) {
    int i = blockIdx.x * blockDim.x + threadIdx.x;
    if (i >= E) return;
    int pos = atomicAdd(&wp[dst[i]], 1);
    srcl[pos] = src[i];
}

// ---------------- fused per-node attention + LN1 ----------------------------
__device__ __forceinline__ float2 bf2f(uint32_t u) {
    return __bfloat1622float2(*reinterpret_cast<__nv_bfloat162*>(&u));
}

__global__ __launch_bounds__(256) void node_attn_ln(
    const __nv_bfloat16* __restrict__ q, const __nv_bfloat16* __restrict__ kv,
    const int* __restrict__ rowptr, const int* __restrict__ srcl,
    const float* __restrict__ feat, const float* __restrict__ g,
    const float* __restrict__ b, float* __restrict__ out, __half* __restrict__ out16,
    int n) {
    int node = blockIdx.x * 8 + (threadIdx.x >> 5);
    if (node >= n) return;
    int lane = threadIdx.x & 31;

    uint2 qraw = *(const uint2*)(q + (size_t)node * D + lane * 4);
    float2 q0 = bf2f(qraw.x);
    float2 q1 = bf2f(qraw.y);

    int start = rowptr[node], end = rowptr[node + 1];

    float a0 = 0.f, a1 = 0.f, a2 = 0.f, a3 = 0.f, den = 0.f;

    for (int eb = start; eb < end; eb += 32) {
        int me = eb + lane;
        int sid = (me < end) ? srcl[me] : 0;
        int cnt = min(32, end - eb);
        int j = 0;
        for (; j + 4 <= cnt; j += 4) {
            int s0 = __shfl_sync(0xffffffffu, sid, j);
            int s1 = __shfl_sync(0xffffffffu, sid, j + 1);
            int s2 = __shfl_sync(0xffffffffu, sid, j + 2);
            int s3 = __shfl_sync(0xffffffffu, sid, j + 3);
            uint4 x0 = *(const uint4*)(kv + (size_t)s0 * 2 * D + lane * 8);
            uint4 x1 = *(const uint4*)(kv + (size_t)s1 * 2 * D + lane * 8);
            uint4 x2 = *(const uint4*)(kv + (size_t)s2 * 2 * D + lane * 8);
            uint4 x3 = *(const uint4*)(kv + (size_t)s3 * 2 * D + lane * 8);
            float2 ka, kb2;
            float p0, p1, p2, p3;
            ka = bf2f(x0.x); kb2 = bf2f(x0.y);
            p0 = ka.x * q0.x + ka.y * q0.y + kb2.x * q1.x + kb2.y * q1.y;
            ka = bf2f(x1.x); kb2 = bf2f(x1.y);
            p1 = ka.x * q0.x + ka.y * q0.y + kb2.x * q1.x + kb2.y * q1.y;
            ka = bf2f(x2.x); kb2 = bf2f(x2.y);
            p2 = ka.x * q0.x + ka.y * q0.y + kb2.x * q1.x + kb2.y * q1.y;
            ka = bf2f(x3.x); kb2 = bf2f(x3.y);
            p3 = ka.x * q0.x + ka.y * q0.y + kb2.x * q1.x + kb2.y * q1.y;
            p0 += __shfl_xor_sync(0xffffffffu, p0, 1);
            p1 += __shfl_xor_sync(0xffffffffu, p1, 1);
            p2 += __shfl_xor_sync(0xffffffffu, p2, 1);
            p3 += __shfl_xor_sync(0xffffffffu, p3, 1);
            p0 += __shfl_xor_sync(0xffffffffu, p0, 2);
            p1 += __shfl_xor_sync(0xffffffffu, p1, 2);
            p2 += __shfl_xor_sync(0xffffffffu, p2, 2);
            p3 += __shfl_xor_sync(0xffffffffu, p3, 2);
            float e0 = __expf(p0 * 0.08838834764831843f);
            float e1 = __expf(p1 * 0.08838834764831843f);
            float e2 = __expf(p2 * 0.08838834764831843f);
            float e3 = __expf(p3 * 0.08838834764831843f);
            den += (e0 + e1) + (e2 + e3);
            float2 va, vb2;
            va = bf2f(x0.z); vb2 = bf2f(x0.w);
            a0 += va.x * e0; a1 += va.y * e0; a2 += vb2.x * e0; a3 += vb2.y * e0;
            va = bf2f(x1.z); vb2 = bf2f(x1.w);
            a0 += va.x * e1; a1 += va.y * e1; a2 += vb2.x * e1; a3 += vb2.y * e1;
            va = bf2f(x2.z); vb2 = bf2f(x2.w);
            a0 += va.x * e2; a1 += va.y * e2; a2 += vb2.x * e2; a3 += vb2.y * e2;
            va = bf2f(x3.z); vb2 = bf2f(x3.w);
            a0 += va.x * e3; a1 += va.y * e3; a2 += vb2.x * e3; a3 += vb2.y * e3;
        }
        for (; j < cnt; j++) {
            int s = __shfl_sync(0xffffffffu, sid, j);
            uint4 x = *(const uint4*)(kv + (size_t)s * 2 * D + lane * 8);
            float2 k0 = bf2f(x.x), k1 = bf2f(x.y);
            float p = k0.x * q0.x + k0.y * q0.y + k1.x * q1.x + k1.y * q1.y;
            p += __shfl_xor_sync(0xffffffffu, p, 1);
            p += __shfl_xor_sync(0xffffffffu, p, 2);
            float ex = __expf(p * 0.08838834764831843f);
            den += ex;
            float2 v0 = bf2f(x.z), v1 = bf2f(x.w);
            a0 += v0.x * ex;
            a1 += v0.y * ex;
            a2 += v1.x * ex;
            a3 += v1.y * ex;
        }
    }

    float inv = den > 0.f ? 1.0f / den : 0.0f;
    float4 fv = *(const float4*)(feat + (size_t)node * D + lane * 4);
    float r0 = a0 * inv + fv.x;
    float r1 = a1 * inv + fv.y;
    float r2 = a2 * inv + fv.z;
    float r3 = a3 * inv + fv.w;

    float s = r0 + r1 + r2 + r3;
    float s2 = r0 * r0 + r1 * r1 + r2 * r2 + r3 * r3;
#pragma unroll
    for (int o = 16; o > 0; o >>= 1) {
        s += __shfl_xor_sync(0xffffffffu, s, o);
        s2 += __shfl_xor_sync(0xffffffffu, s2, o);
    }
    float mean = s * (1.0f / D);
    float var = s2 * (1.0f / D) - mean * mean;
    float rstd = rsqrtf(var + 1e-5f);
    float4 gv = *(const float4*)(g + lane * 4);
    float4 bv = *(const float4*)(b + lane * 4);
    float4 o;
    o.x = (r0 - mean) * rstd * gv.x + bv.x;
    o.y = (r1 - mean) * rstd * gv.y + bv.y;
    o.z = (r2 - mean) * rstd * gv.z + bv.z;
    o.w = (r3 - mean) * rstd * gv.w + bv.w;
    *(float4*)(out + (size_t)node * D + lane * 4) = o;
    __half2 h0 = __floats2half2_rn(o.x, o.y);
    __half2 h1 = __floats2half2_rn(o.z, o.w);
    uint2 hp =
        make_uint2(*reinterpret_cast<uint32_t*>(&h0), *reinterpret_cast<uint32_t*>(&h1));
    *(uint2*)(out16 + (size_t)node * D + lane * 4) = hp;
}

// ---------------- launch ----------------------------------------------------
extern "C" void kernel_launch(void* const* d_in, const int* in_sizes, int n_in,
                              void* d_out, int out_size) {
    const float* feat = (const float*)d_in[0];
    const int* src = (const int*)d_in[1];
    const int* dst = (const int*)d_in[2];
    const float* Wq = (const float*)d_in[3];
    const float* bq = (const float*)d_in[4];
    const float* Wk = (const float*)d_in[5];
    const float* bk = (const float*)d_in[6];
    const float* Wv = (const float*)d_in[7];
    const float* bv = (const float*)d_in[8];
    const float* ln_g = (const float*)d_in[9];
    const float* ln_b = (const float*)d_in[10];
    const float* W1 = (const float*)d_in[11];
    const float* b1 = (const float*)d_in[12];
    const float* alpha = (const float*)d_in[13];
    const float* W2 = (const float*)d_in[14];
    const float* b2 = (const float*)d_in[15];

    const int N = in_sizes[0] / D;
    const int E = in_sizes[1];

    __nv_bfloat16 *q16, *kv;
    __half *feat16, *rstln16, *hb16, *wtq, *wtk, *wtv, *wt1, *wt2;
    float* rstln;
    int *counts, *rowptr, *wp, *srcl, *bsums;
    cudaGetSymbolAddress((void**)&feat16, g_feat16);
    cudaGetSymbolAddress((void**)&q16, g_q16);
    cudaGetSymbolAddress((void**)&kv, g_kv);
    cudaGetSymbolAddress((void**)&rstln, g_rstln);
    cudaGetSymbolAddress((void**)&rstln16, g_rstln16);
    cudaGetSymbolAddress((void**)&hb16, g_h16);
    cudaGetSymbolAddress((void**)&wtq, g_wtq);
    cudaGetSymbolAddress((void**)&wtk, g_wtk);
    cudaGetSymbolAddress((void**)&wtv, g_wtv);
    cudaGetSymbolAddress((void**)&wt1, g_wt1);
    cudaGetSymbolAddress((void**)&wt2, g_wt2);
    cudaGetSymbolAddress((void**)&counts, g_counts);
    cudaGetSymbolAddress((void**)&rowptr, g_rowptr);
    cudaGetSymbolAddress((void**)&wp, g_wp);
    cudaGetSymbolAddress((void**)&srcl, g_srcl);
    cudaGetSymbolAddress((void**)&bsums, g_bsums);

    static int attr_set = 0;
    if (!attr_set) {
        cudaFuncSetAttribute(qkv_gemm, cudaFuncAttributeMaxDynamicSharedMemorySize,
                             GEMM_SMEM);
        cudaFuncSetAttribute(w1_gemm, cudaFuncAttributeMaxDynamicSharedMemorySize, GEMM_SMEM);
        cudaFuncSetAttribute(w2_ln_gemm, cudaFuncAttributeMaxDynamicSharedMemorySize,
                             W2_SMEM);
        attr_set = 1;
    }

    const int mgrid = (N + TBM - 1) / TBM;
    const int nb = (N + 1023) / 1024;

    // ---- conversions (feat -> fp16; weights -> fp16 transposed)
    cvt_feat16<<<(N * D / 8 + 255) / 256, 256>>>(feat, feat16, N * D);
    cvt_w_t<<<(D * D + 255) / 256, 256>>>(Wq, wtq, D, D);
    cvt_w_t<<<(D * D + 255) / 256, 256>>>(Wk, wtk, D, D);
    cvt_w_t<<<(D * D + 255) / 256, 256>>>(Wv, wtv, D, D);
    cvt_w_t<<<(D * F + 255) / 256, 256>>>(W1, wt1, D, F);
    cvt_w_t<<<(F * D + 255) / 256, 256>>>(W2, wt2, F, D);

    // ---- CSR build
    cudaMemsetAsync(counts, 0, (size_t)N * sizeof(int), 0);
    hist_kernel<<<(E + 255) / 256, 256>>>(dst, counts, E);
    scan1_kernel<<<nb, 256>>>(counts, rowptr, bsums, N);
    scan2_kernel<<<1, 32>>>(bsums, nb);
    scan3_kernel<<<(N + 255) / 256, 256>>>(rowptr, wp, bsums, N, E);
    fill_kernel<<<(E + 255) / 256, 256>>>(src, dst, wp, srcl, E);

    // ---- fused q/k/v projections (fp16 MMA; q bf16, k/v interleaved bf16)
    qkv_gemm<<<dim3(mgrid, 1, 3), 256, GEMM_SMEM>>>(feat16, wtq, wtk, wtv, bq, bk, bv, q16,
                                                    kv, N);

    // ---- fused per-node attention + LN1 (fp32 + fp16 outputs)
    node_attn_ln<<<(N + 7) / 8, 256>>>(q16, kv, rowptr, srcl, feat, ln_g, ln_b, rstln,
                                       rstln16, N);

    // ---- FFN: W1 (fp16, +PReLU), then W2 + residual + LN2 -> final output
    w1_gemm<<<dim3(mgrid, F / TBN), 256, GEMM_SMEM>>>(rstln16, wt1, b1, alpha, hb16, N);
    w2_ln_gemm<<<dim3(mgrid, 1), 256, W2_SMEM>>>(hb16, wt2, b2, rstln, ln_g, ln_b,
                                                 (float*)d_out, N);
}

// round 12
// speedup vs baseline: 5.3375x; 1.0483x over previous
#include <cuda_runtime.h>
#include <cuda_bf16.h>
#include <cuda_fp16.h>
#include <math.h>
#include <stdint.h>

#define NODES_MAX 100000
#define EDGES_MAX 1600000
#define D 128
#define H 8
#define F 512

// ---------------- scratch (static device globals; no allocation allowed) ----
__device__ __half g_feat16[NODES_MAX * D];
__device__ __nv_bfloat16 g_q16[NODES_MAX * D];
__device__ __nv_bfloat16 g_kv[NODES_MAX * 2 * D];  // interleaved k/v per 4-elem chunk
__device__ float g_rstln[NODES_MAX * D];
__device__ __half g_rstln16[NODES_MAX * D];
__device__ __half g_h16[NODES_MAX * F];
// fp16 transposed weights [N][K]
__device__ __half g_wtq[D * D];
__device__ __half g_wtk[D * D];
__device__ __half g_wtv[D * D];
__device__ __half g_wt1[F * D];
__device__ __half g_wt2[D * F];
// CSR build
__device__ int g_counts[NODES_MAX];
__device__ int g_rowptr[NODES_MAX + 1];
__device__ int g_wp[NODES_MAX];
__device__ int g_srcl[EDGES_MAX];
__device__ int g_bsums[256];

// ---------------- fp16 tensor-core GEMM core, cp.async double-buffered ------
#define TBM 128
#define TBN 128
#define TBK 32
#define STR 40                      // smem stride in halves (80B rows)
#define OP_BYTES (128 * STR * 2)    // 10240 per operand
#define STAGE (2 * OP_BYTES)        // 20480
#define GEMM_SMEM (2 * STAGE)       // 40960
#define LNSTRIDE 132
#define W2_SMEM (128 * LNSTRIDE * 4)  // 67584 (LN staging)

__device__ __forceinline__ void mma_f16(float* c, const uint32_t* a, const uint32_t* b) {
    asm volatile(
        "mma.sync.aligned.m16n8k16.row.col.f32.f16.f16.f32 "
        "{%0,%1,%2,%3}, {%4,%5,%6,%7}, {%8,%9}, {%0,%1,%2,%3};\n"
        : "+f"(c[0]), "+f"(c[1]), "+f"(c[2]), "+f"(c[3])
        : "r"(a[0]), "r"(a[1]), "r"(a[2]), "r"(a[3]), "r"(b[0]), "r"(b[1]));
}

__device__ __forceinline__ void cp16(void* s, const void* g, bool valid) {
    uint32_t sa = (uint32_t)__cvta_generic_to_shared(s);
    int sz = valid ? 16 : 0;
    asm volatile("cp.async.cg.shared.global [%0], [%1], 16, %2;" ::"r"(sa), "l"(g), "r"(sz));
}

// MODE: 0 = fp16 store (+PReLU), 1 = bf16 store (kvoff<0: plain; else kv-interleaved),
//       2 = fused residual+LayerNorm (fp32 out)
template <int MODE, bool PRELU>
__device__ __forceinline__ void gemm_body(const __half* __restrict__ A,
                                          const __half* __restrict__ Bt,
                                          const float* __restrict__ bias,
                                          const float* __restrict__ alpha,
                                          float* __restrict__ C,
                                          __nv_bfloat16* __restrict__ Cb, int kvoff,
                                          __half* __restrict__ Ch,
                                          const float* __restrict__ res,
                                          const float* __restrict__ lng,
                                          const float* __restrict__ lnb, int M, int N,
                                          int K) {
    extern __shared__ char smem[];
    const int tid = threadIdx.x;
    const int lane = tid & 31;
    const int wid = tid >> 5;
    const int wm = wid & 1;
    const int wn = wid >> 1;
    const int tg = lane >> 2;
    const int tc = lane & 3;

    const int row0 = blockIdx.x * TBM;
    const int col0 = blockIdx.y * TBN;
    const int T = K / TBK;

    float acc[4][4][4];
#pragma unroll
    for (int mt = 0; mt < 4; mt++)
#pragma unroll
        for (int nt = 0; nt < 4; nt++)
#pragma unroll
            for (int r = 0; r < 4; r++) acc[mt][nt][r] = 0.0f;

    auto fill = [&](int t) {
        char* st = smem + (t & 1) * STAGE;
        char* sb = st + OP_BYTES;
        const int k0 = t * TBK;
#pragma unroll
        for (int p = 0; p < 2; p++) {
            int idx = tid + p * 256;
            int r = idx >> 2, c8 = (idx & 3) * 8;
            int gr = row0 + r;
            cp16(st + r * 80 + c8 * 2, A + (size_t)gr * K + k0 + c8, gr < M);
            cp16(sb + r * 80 + c8 * 2, Bt + (size_t)(col0 + r) * K + k0 + c8, true);
        }
        asm volatile("cp.async.commit_group;");
    };

    fill(0);

    for (int t = 0; t < T; t++) {
        if (t + 1 < T) {
            fill(t + 1);
            asm volatile("cp.async.wait_group 1;");
        } else {
            asm volatile("cp.async.wait_group 0;");
        }
        __syncthreads();

        const char* st = smem + (t & 1) * STAGE;
        const __half* sA = (const __half*)st;
        const __half* sB = (const __half*)(st + OP_BYTES);

#pragma unroll
        for (int ks = 0; ks < 2; ks++) {
            const int kb = ks * 16;
            uint32_t af[4][4], bf[4][2];
#pragma unroll
            for (int mt = 0; mt < 4; mt++) {
                int mrow = wm * 64 + mt * 16;
                af[mt][0] = *(const uint32_t*)&sA[(mrow + tg) * STR + kb + 2 * tc];
                af[mt][1] = *(const uint32_t*)&sA[(mrow + tg + 8) * STR + kb + 2 * tc];
                af[mt][2] = *(const uint32_t*)&sA[(mrow + tg) * STR + kb + 2 * tc + 8];
                af[mt][3] = *(const uint32_t*)&sA[(mrow + tg + 8) * STR + kb + 2 * tc + 8];
            }
#pragma unroll
            for (int nt = 0; nt < 4; nt++) {
                int ncol = wn * 32 + nt * 8 + tg;
                bf[nt][0] = *(const uint32_t*)&sB[ncol * STR + kb + 2 * tc];
                bf[nt][1] = *(const uint32_t*)&sB[ncol * STR + kb + 2 * tc + 8];
            }
#pragma unroll
            for (int mt = 0; mt < 4; mt++)
#pragma unroll
                for (int nt = 0; nt < 4; nt++) mma_f16(acc[mt][nt], af[mt], bf[nt]);
        }
        __syncthreads();
    }

    if (MODE == 2) {
        float* se = (float*)smem;
#pragma unroll
        for (int mt = 0; mt < 4; mt++) {
#pragma unroll
            for (int nt = 0; nt < 4; nt++) {
                int lc = wn * 32 + nt * 8 + tc * 2;
                int gc = col0 + lc;
                float b0 = bias[gc], b1 = bias[gc + 1];
                int lr = wm * 64 + mt * 16 + tg;
                int gr = row0 + lr;
                if (gr < M) {
                    float2 rr = *(const float2*)(res + (size_t)gr * N + gc);
                    se[lr * LNSTRIDE + lc] = acc[mt][nt][0] + b0 + rr.x;
                    se[lr * LNSTRIDE + lc + 1] = acc[mt][nt][1] + b1 + rr.y;
                }
                if (gr + 8 < M) {
                    float2 rr = *(const float2*)(res + (size_t)(gr + 8) * N + gc);
                    se[(lr + 8) * LNSTRIDE + lc] = acc[mt][nt][2] + b0 + rr.x;
                    se[(lr + 8) * LNSTRIDE + lc + 1] = acc[mt][nt][3] + b1 + rr.y;
                }
            }
        }
        __syncthreads();
        float4 gv = *(const float4*)(lng + lane * 4);
        float4 bv = *(const float4*)(lnb + lane * 4);
#pragma unroll
        for (int r = 0; r < 16; r++) {
            int lrow = wid * 16 + r;
            int grow = row0 + lrow;
            if (grow >= M) continue;
            float4 vx = *(const float4*)&se[lrow * LNSTRIDE + lane * 4];
            float s = vx.x + vx.y + vx.z + vx.w;
            float s2 = vx.x * vx.x + vx.y * vx.y + vx.z * vx.z + vx.w * vx.w;
#pragma unroll
            for (int o = 16; o > 0; o >>= 1) {
                s += __shfl_xor_sync(0xffffffffu, s, o);
                s2 += __shfl_xor_sync(0xffffffffu, s2, o);
            }
            float mean = s * (1.0f / D);
            float var = s2 * (1.0f / D) - mean * mean;
            float rstd = rsqrtf(var + 1e-5f);
            float4 o;
            o.x = (vx.x - mean) * rstd * gv.x + bv.x;
            o.y = (vx.y - mean) * rstd * gv.y + bv.y;
            o.z = (vx.z - mean) * rstd * gv.z + bv.z;
            o.w = (vx.w - mean) * rstd * gv.w + bv.w;
            *(float4*)(C + (size_t)grow * N + lane * 4) = o;
        }
        return;
    }

#pragma unroll
    for (int mt = 0; mt < 4; mt++) {
#pragma unroll
        for (int nt = 0; nt < 4; nt++) {
            int gc = col0 + wn * 32 + nt * 8 + tc * 2;
            float b0 = bias[gc], b1 = bias[gc + 1];
            float v0 = acc[mt][nt][0] + b0;
            float v1 = acc[mt][nt][1] + b1;
            float v2 = acc[mt][nt][2] + b0;
            float v3 = acc[mt][nt][3] + b1;
            if (PRELU) {
                float a0 = alpha[gc], a1 = alpha[gc + 1];
                v0 = v0 > 0.f ? v0 : a0 * v0;
                v1 = v1 > 0.f ? v1 : a1 * v1;
                v2 = v2 > 0.f ? v2 : a0 * v2;
                v3 = v3 > 0.f ? v3 : a1 * v3;
            }
            int gr = row0 + wm * 64 + mt * 16 + tg;
            if (MODE == 1) {
                if (kvoff < 0) {
                    if (gr < M)
                        *(__nv_bfloat162*)(Cb + (size_t)gr * N + gc) =
                            __floats2bfloat162_rn(v0, v1);
                    if (gr + 8 < M)
                        *(__nv_bfloat162*)(Cb + (size_t)(gr + 8) * N + gc) =
                            __floats2bfloat162_rn(v2, v3);
                } else {
                    int cc = ((gc >> 2) << 3) + (gc & 3) + kvoff;
                    if (gr < M)
                        *(__nv_bfloat162*)(Cb + (size_t)gr * 2 * D + cc) =
                            __floats2bfloat162_rn(v0, v1);
                    if (gr + 8 < M)
                        *(__nv_bfloat162*)(Cb + (size_t)(gr + 8) * 2 * D + cc) =
                            __floats2bfloat162_rn(v2, v3);
                }
            } else {
                if (gr < M)
                    *(__half2*)(Ch + (size_t)gr * N + gc) = __floats2half2_rn(v0, v1);
                if (gr + 8 < M)
                    *(__half2*)(Ch + (size_t)(gr + 8) * N + gc) = __floats2half2_rn(v2, v3);
            }
        }
    }
}

// fused q/k/v projection: blockIdx.z selects weight/bias/output
__global__ __launch_bounds__(256, 2) void qkv_gemm(
    const __half* __restrict__ A, const __half* __restrict__ Wtq,
    const __half* __restrict__ Wtk, const __half* __restrict__ Wtv,
    const float* __restrict__ bq, const float* __restrict__ bk,
    const float* __restrict__ bv, __nv_bfloat16* __restrict__ q16,
    __nv_bfloat16* __restrict__ kv, int M) {
    const __half* Bt = (blockIdx.z == 0) ? Wtq : (blockIdx.z == 1) ? Wtk : Wtv;
    const float* bias = (blockIdx.z == 0) ? bq : (blockIdx.z == 1) ? bk : bv;
    __nv_bfloat16* Cb = (blockIdx.z == 0) ? q16 : kv;
    int kvoff = (blockIdx.z == 0) ? -1 : (blockIdx.z == 1) ? 0 : 4;
    gemm_body<1, false>(A, Bt, bias, nullptr, nullptr, Cb, kvoff, nullptr, nullptr, nullptr,
                        nullptr, M, D, D);
}

// W1: fp16 A (rstln16) -> fp16 out (hb16) + PReLU
__global__ __launch_bounds__(256, 2) void w1_gemm(
    const __half* __restrict__ A, const __half* __restrict__ Bt,
    const float* __restrict__ bias, const float* __restrict__ alpha,
    __half* __restrict__ C, int M) {
    gemm_body<0, true>(A, Bt, bias, alpha, nullptr, nullptr, -1, C, nullptr, nullptr,
                       nullptr, M, F, D);
}

// W2: fp16 A (hb16) + residual(fp32) + LN2 -> final output
__global__ __launch_bounds__(256, 2) void w2_ln_gemm(
    const __half* __restrict__ A, const __half* __restrict__ Bt,
    const float* __restrict__ bias, const float* __restrict__ res,
    const float* __restrict__ lng, const float* __restrict__ lnb, float* __restrict__ out,
    int M) {
    gemm_body<2, false>(A, Bt, bias, nullptr, out, nullptr, -1, nullptr, res, lng, lnb, M,
                        D, F);
}

// ---------------- conversions -------------------------------------------------
__global__ void cvt_feat16(const float* __restrict__ in, __half* __restrict__ out, int n) {
    int base = (blockIdx.x * 256 + threadIdx.x) * 8;
    if (base >= n) return;
    float4 a = *(const float4*)(in + base);
    float4 b = *(const float4*)(in + base + 4);
    __half2 h0 = __floats2half2_rn(a.x, a.y), h1 = __floats2half2_rn(a.z, a.w);
    __half2 h2 = __floats2half2_rn(b.x, b.y), h3 = __floats2half2_rn(b.z, b.w);
    *(uint4*)(out + base) =
        make_uint4(*reinterpret_cast<uint32_t*>(&h0), *reinterpret_cast<uint32_t*>(&h1),
                   *reinterpret_cast<uint32_t*>(&h2), *reinterpret_cast<uint32_t*>(&h3));
}

// all 5 weight transposes in one launch: out[n*K+k] = (half)in[k*N+n]
__global__ void cvt_w_all(const float* __restrict__ Wq, const float* __restrict__ Wk,
                          const float* __restrict__ Wv, const float* __restrict__ W1,
                          const float* __restrict__ W2, __half* __restrict__ wtq,
                          __half* __restrict__ wtk, __half* __restrict__ wtv,
                          __half* __restrict__ wt1, __half* __restrict__ wt2) {
    int idx = blockIdx.x * 256 + threadIdx.x;
    const int S = D * D;        // 16384
    const int SF = F * D;       // 65536
    const float* in;
    __half* out;
    int K, N, local;
    if (idx < S) {
        in = Wq; out = wtq; K = D; N = D; local = idx;
    } else if (idx < 2 * S) {
        in = Wk; out = wtk; K = D; N = D; local = idx - S;
    } else if (idx < 3 * S) {
        in = Wv; out = wtv; K = D; N = D; local = idx - 2 * S;
    } else if (idx < 3 * S + SF) {
        in = W1; out = wt1; K = D; N = F; local = idx - 3 * S;
    } else if (idx < 3 * S + 2 * SF) {
        in = W2; out = wt2; K = F; N = D; local = idx - 3 * S - SF;
    } else {
        return;
    }
    int n = local / K;
    int k = local - n * K;
    out[local] = __float2half(in[(size_t)k * N + n]);
}

// ---------------- CSR build --------------------------------------------------
__global__ void hist_kernel(const int* __restrict__ dst, int* __restrict__ counts, int E) {
    int i = blockIdx.x * blockDim.x + threadIdx.x;
    if (i < E) atomicAdd(&counts[dst[i]], 1);
}

__global__ void scan1_kernel(const int* __restrict__ counts, int* __restrict__ rowptr,
                             int* __restrict__ bsums, int n) {
    __shared__ int wsum[8];
    int base = blockIdx.x * 1024 + threadIdx.x * 4;
    int lane = threadIdx.x & 31, wid = threadIdx.x >> 5;
    int v[4];
#pragma unroll
    for (int i = 0; i < 4; i++) v[i] = (base + i < n) ? counts[base + i] : 0;
    int t = v[0] + v[1] + v[2] + v[3];
    int sc = t;
#pragma unroll
    for (int o = 1; o < 32; o <<= 1) {
        int x = __shfl_up_sync(0xffffffffu, sc, o);
        if (lane >= o) sc += x;
    }
    if (lane == 31) wsum[wid] = sc;
    __syncthreads();
    if (wid == 0) {
        int ws = (lane < 8) ? wsum[lane] : 0;
#pragma unroll
        for (int o = 1; o < 8; o <<= 1) {
            int x = __shfl_up_sync(0xffffffffu, ws, o);
            if (lane >= o) ws += x;
        }
        if (lane < 8) wsum[lane] = ws;
    }
    __syncthreads();
    int run = sc - t + (wid > 0 ? wsum[wid - 1] : 0);
#pragma unroll
    for (int i = 0; i < 4; i++) {
        if (base + i < n) rowptr[base + i] = run;
        run += v[i];
    }
    if (threadIdx.x == 0) bsums[blockIdx.x] = wsum[7];
}

__global__ void scan2_kernel(int* __restrict__ bsums, int nb) {
    if (threadIdx.x == 0 && blockIdx.x == 0) {
        int run = 0;
        for (int i = 0; i < nb; i++) {
            int t = bsums[i];
            bsums[i] = run;
            run += t;
        }
    }
}

__global__ void scan3_kernel(int* __restrict__ rowptr, int* __restrict__ wp,
                             const int* __restrict__ bsums, int n, int E) {
    int i = blockIdx.x * blockDim.x + threadIdx.x;
    if (i < n) {
        int v = rowptr[i] + bsums[i >> 10];
        rowptr[i] = v;
        wp[i] = v;
    }
    if (i == 0) rowptr[n] = E;
}

__global__ void fill_kernel(const int* __restrict__ src, const int* __restrict__ dst,
                            int* __restrict__ wp, int* __restrict__ srcl, int E) {
    int i = blockIdx.x * blockDim.x + threadIdx.x;
    if (i >= E) return;
    int pos = atomicAdd(&wp[dst[i]], 1);
    srcl[pos] = src[i];
}

// ---------------- fused per-node attention + LN1 ----------------------------
__device__ __forceinline__ float2 bf2f(uint32_t u) {
    return __bfloat1622float2(*reinterpret_cast<__nv_bfloat162*>(&u));
}

__global__ __launch_bounds__(256) void node_attn_ln(
    const __nv_bfloat16* __restrict__ q, const __nv_bfloat16* __restrict__ kv,
    const int* __restrict__ rowptr, const int* __restrict__ srcl,
    const float* __restrict__ feat, const float* __restrict__ g,
    const float* __restrict__ b, float* __restrict__ out, __half* __restrict__ out16,
    int n) {
    int node = blockIdx.x * 8 + (threadIdx.x >> 5);
    if (node >= n) return;
    int lane = threadIdx.x & 31;

    uint2 qraw = *(const uint2*)(q + (size_t)node * D + lane * 4);
    float2 q0 = bf2f(qraw.x);
    float2 q1 = bf2f(qraw.y);

    int start = rowptr[node], end = rowptr[node + 1];

    float a0 = 0.f, a1 = 0.f, a2 = 0.f, a3 = 0.f, den = 0.f;

    for (int eb = start; eb < end; eb += 32) {
        int me = eb + lane;
        int sid = (me < end) ? srcl[me] : 0;
        int cnt = min(32, end - eb);
        int j = 0;
        for (; j + 4 <= cnt; j += 4) {
            int s0 = __shfl_sync(0xffffffffu, sid, j);
            int s1 = __shfl_sync(0xffffffffu, sid, j + 1);
            int s2 = __shfl_sync(0xffffffffu, sid, j + 2);
            int s3 = __shfl_sync(0xffffffffu, sid, j + 3);
            uint4 x0 = *(const uint4*)(kv + (size_t)s0 * 2 * D + lane * 8);
            uint4 x1 = *(const uint4*)(kv + (size_t)s1 * 2 * D + lane * 8);
            uint4 x2 = *(const uint4*)(kv + (size_t)s2 * 2 * D + lane * 8);
            uint4 x3 = *(const uint4*)(kv + (size_t)s3 * 2 * D + lane * 8);
            float2 ka, kb2;
            float p0, p1, p2, p3;
            ka = bf2f(x0.x); kb2 = bf2f(x0.y);
            p0 = ka.x * q0.x + ka.y * q0.y + kb2.x * q1.x + kb2.y * q1.y;
            ka = bf2f(x1.x); kb2 = bf2f(x1.y);
            p1 = ka.x * q0.x + ka.y * q0.y + kb2.x * q1.x + kb2.y * q1.y;
            ka = bf2f(x2.x); kb2 = bf2f(x2.y);
            p2 = ka.x * q0.x + ka.y * q0.y + kb2.x * q1.x + kb2.y * q1.y;
            ka = bf2f(x3.x); kb2 = bf2f(x3.y);
            p3 = ka.x * q0.x + ka.y * q0.y + kb2.x * q1.x + kb2.y * q1.y;
            p0 += __shfl_xor_sync(0xffffffffu, p0, 1);
            p1 += __shfl_xor_sync(0xffffffffu, p1, 1);
            p2 += __shfl_xor_sync(0xffffffffu, p2, 1);
            p3 += __shfl_xor_sync(0xffffffffu, p3, 1);
            p0 += __shfl_xor_sync(0xffffffffu, p0, 2);
            p1 += __shfl_xor_sync(0xffffffffu, p1, 2);
            p2 += __shfl_xor_sync(0xffffffffu, p2, 2);
            p3 += __shfl_xor_sync(0xffffffffu, p3, 2);
            float e0 = __expf(p0 * 0.08838834764831843f);
            float e1 = __expf(p1 * 0.08838834764831843f);
            float e2 = __expf(p2 * 0.08838834764831843f);
            float e3 = __expf(p3 * 0.08838834764831843f);
            den += (e0 + e1) + (e2 + e3);
            float2 va, vb2;
            va = bf2f(x0.z); vb2 = bf2f(x0.w);
            a0 += va.x * e0; a1 += va.y * e0; a2 += vb2.x * e0; a3 += vb2.y * e0;
            va = bf2f(x1.z); vb2 = bf2f(x1.w);
            a0 += va.x * e1; a1 += va.y * e1; a2 += vb2.x * e1; a3 += vb2.y * e1;
            va = bf2f(x2.z); vb2 = bf2f(x2.w);
            a0 += va.x * e2; a1 += va.y * e2; a2 += vb2.x * e2; a3 += vb2.y * e2;
            va = bf2f(x3.z); vb2 = bf2f(x3.w);
            a0 += va.x * e3; a1 += va.y * e3; a2 += vb2.x * e3; a3 += vb2.y * e3;
        }
        for (; j < cnt; j++) {
            int s = __shfl_sync(0xffffffffu, sid, j);
            uint4 x = *(const uint4*)(kv + (size_t)s * 2 * D + lane * 8);
            float2 k0 = bf2f(x.x), k1 = bf2f(x.y);
            float p = k0.x * q0.x + k0.y * q0.y + k1.x * q1.x + k1.y * q1.y;
            p += __shfl_xor_sync(0xffffffffu, p, 1);
            p += __shfl_xor_sync(0xffffffffu, p, 2);
            float ex = __expf(p * 0.08838834764831843f);
            den += ex;
            float2 v0 = bf2f(x.z), v1 = bf2f(x.w);
            a0 += v0.x * ex;
            a1 += v0.y * ex;
            a2 += v1.x * ex;
            a3 += v1.y * ex;
        }
    }

    float inv = den > 0.f ? 1.0f / den : 0.0f;
    float4 fv = *(const float4*)(feat + (size_t)node * D + lane * 4);
    float r0 = a0 * inv + fv.x;
    float r1 = a1 * inv + fv.y;
    float r2 = a2 * inv + fv.z;
    float r3 = a3 * inv + fv.w;

    float s = r0 + r1 + r2 + r3;
    float s2 = r0 * r0 + r1 * r1 + r2 * r2 + r3 * r3;
#pragma unroll
    for (int o = 16; o > 0; o >>= 1) {
        s += __shfl_xor_sync(0xffffffffu, s, o);
        s2 += __shfl_xor_sync(0xffffffffu, s2, o);
    }
    float mean = s * (1.0f / D);
    float var = s2 * (1.0f / D) - mean * mean;
    float rstd = rsqrtf(var + 1e-5f);
    float4 gv = *(const float4*)(g + lane * 4);
    float4 bv = *(const float4*)(b + lane * 4);
    float4 o;
    o.x = (r0 - mean) * rstd * gv.x + bv.x;
    o.y = (r1 - mean) * rstd * gv.y + bv.y;
    o.z = (r2 - mean) * rstd * gv.z + bv.z;
    o.w = (r3 - mean) * rstd * gv.w + bv.w;
    *(float4*)(out + (size_t)node * D + lane * 4) = o;
    __half2 h0 = __floats2half2_rn(o.x, o.y);
    __half2 h1 = __floats2half2_rn(o.z, o.w);
    uint2 hp =
        make_uint2(*reinterpret_cast<uint32_t*>(&h0), *reinterpret_cast<uint32_t*>(&h1));
    *(uint2*)(out16 + (size_t)node * D + lane * 4) = hp;
}

// ---------------- launch ----------------------------------------------------
extern "C" void kernel_launch(void* const* d_in, const int* in_sizes, int n_in,
                              void* d_out, int out_size) {
    const float* feat = (const float*)d_in[0];
    const int* src = (const int*)d_in[1];
    const int* dst = (const int*)d_in[2];
    const float* Wq = (const float*)d_in[3];
    const float* bq = (const float*)d_in[4];
    const float* Wk = (const float*)d_in[5];
    const float* bk = (const float*)d_in[6];
    const float* Wv = (const float*)d_in[7];
    const float* bv = (const float*)d_in[8];
    const float* ln_g = (const float*)d_in[9];
    const float* ln_b = (const float*)d_in[10];
    const float* W1 = (const float*)d_in[11];
    const float* b1 = (const float*)d_in[12];
    const float* alpha = (const float*)d_in[13];
    const float* W2 = (const float*)d_in[14];
    const float* b2 = (const float*)d_in[15];

    const int N = in_sizes[0] / D;
    const int E = in_sizes[1];

    __nv_bfloat16 *q16, *kv;
    __half *feat16, *rstln16, *hb16, *wtq, *wtk, *wtv, *wt1, *wt2;
    float* rstln;
    int *counts, *rowptr, *wp, *srcl, *bsums;
    cudaGetSymbolAddress((void**)&feat16, g_feat16);
    cudaGetSymbolAddress((void**)&q16, g_q16);
    cudaGetSymbolAddress((void**)&kv, g_kv);
    cudaGetSymbolAddress((void**)&rstln, g_rstln);
    cudaGetSymbolAddress((void**)&rstln16, g_rstln16);
    cudaGetSymbolAddress((void**)&hb16, g_h16);
    cudaGetSymbolAddress((void**)&wtq, g_wtq);
    cudaGetSymbolAddress((void**)&wtk, g_wtk);
    cudaGetSymbolAddress((void**)&wtv, g_wtv);
    cudaGetSymbolAddress((void**)&wt1, g_wt1);
    cudaGetSymbolAddress((void**)&wt2, g_wt2);
    cudaGetSymbolAddress((void**)&counts, g_counts);
    cudaGetSymbolAddress((void**)&rowptr, g_rowptr);
    cudaGetSymbolAddress((void**)&wp, g_wp);
    cudaGetSymbolAddress((void**)&srcl, g_srcl);
    cudaGetSymbolAddress((void**)&bsums, g_bsums);

    static cudaStream_t s1 = nullptr;
    static cudaEvent_t evFork = nullptr, evCsr = nullptr;
    static int attr_set = 0;
    if (!attr_set) {
        cudaFuncSetAttribute(qkv_gemm, cudaFuncAttributeMaxDynamicSharedMemorySize,
                             GEMM_SMEM);
        cudaFuncSetAttribute(w1_gemm, cudaFuncAttributeMaxDynamicSharedMemorySize, GEMM_SMEM);
        cudaFuncSetAttribute(w2_ln_gemm, cudaFuncAttributeMaxDynamicSharedMemorySize,
                             W2_SMEM);
        cudaStreamCreateWithFlags(&s1, cudaStreamNonBlocking);
        cudaEventCreateWithFlags(&evFork, cudaEventDisableTiming);
        cudaEventCreateWithFlags(&evCsr, cudaEventDisableTiming);
        attr_set = 1;
    }

    const int mgrid = (N + TBM - 1) / TBM;
    const int nb = (N + 1023) / 1024;
    const int wtot = 3 * D * D + 2 * F * D;

    // ---- fork: CSR build on side stream, overlapped with conversions + qkv
    cudaEventRecord(evFork, 0);
    cudaStreamWaitEvent(s1, evFork, 0);
    cudaMemsetAsync(counts, 0, (size_t)N * sizeof(int), s1);
    hist_kernel<<<(E + 255) / 256, 256, 0, s1>>>(dst, counts, E);
    scan1_kernel<<<nb, 256, 0, s1>>>(counts, rowptr, bsums, N);
    scan2_kernel<<<1, 32, 0, s1>>>(bsums, nb);
    scan3_kernel<<<(N + 255) / 256, 256, 0, s1>>>(rowptr, wp, bsums, N, E);
    fill_kernel<<<(E + 255) / 256, 256, 0, s1>>>(src, dst, wp, srcl, E);
    cudaEventRecord(evCsr, s1);

    // ---- main stream: conversions then qkv
    cvt_feat16<<<(N * D / 8 + 255) / 256, 256>>>(feat, feat16, N * D);
    cvt_w_all<<<(wtot + 255) / 256, 256>>>(Wq, Wk, Wv, W1, W2, wtq, wtk, wtv, wt1, wt2);

    qkv_gemm<<<dim3(mgrid, 1, 3), 256, GEMM_SMEM>>>(feat16, wtq, wtk, wtv, bq, bk, bv, q16,
                                                    kv, N);

    // ---- join: node_attn needs CSR
    cudaStreamWaitEvent(0, evCsr, 0);
    node_attn_ln<<<(N + 7) / 8, 256>>>(q16, kv, rowptr, srcl, feat, ln_g, ln_b, rstln,
                                       rstln16, N);

    // ---- FFN: W1 (fp16, +PReLU), then W2 + residual + LN2 -> final output
    w1_gemm<<<dim3(mgrid, F / TBN), 256, GEMM_SMEM>>>(rstln16, wt1, b1, alpha, hb16, N);
    w2_ln_gemm<<<dim3(mgrid, 1), 256, W2_SMEM>>>(hb16, wt2, b2, rstln, ln_g, ln_b,
                                                 (float*)d_out, N);
}

// round 13
// speedup vs baseline: 5.3409x; 1.0006x over previous
#include <cuda_runtime.h>
#include <cuda_bf16.h>
#include <cuda_fp16.h>
#include <math.h>
#include <stdint.h>

#define NODES_MAX 100000
#define EDGES_MAX 1600000
#define D 128
#define H 8
#define F 512

// ---------------- scratch (static device globals; no allocation allowed) ----
__device__ __half g_feat16[NODES_MAX * D];
__device__ __nv_bfloat16 g_q16[NODES_MAX * D];
__device__ __nv_bfloat16 g_kv[NODES_MAX * 2 * D];  // interleaved k/v per 4-elem chunk
__device__ float g_rstln[NODES_MAX * D];
__device__ __half g_rstln16[NODES_MAX * D];
__device__ __half g_h16[NODES_MAX * F];
// fp16 transposed weights [N][K]
__device__ __half g_wtq[D * D];
__device__ __half g_wtk[D * D];
__device__ __half g_wtv[D * D];
__device__ __half g_wt1[F * D];
__device__ __half g_wt2[D * F];
// CSR build
__device__ int g_counts[NODES_MAX];
__device__ int g_rowptr[NODES_MAX + 1];
__device__ int g_wp[NODES_MAX];
__device__ int g_srcl[EDGES_MAX];
__device__ int g_bsums[256];

// ---------------- fp16 tensor-core GEMM core, cp.async double-buffered ------
#define TBM 128
#define TBN 128
#define TBK 32
#define STR 40                      // smem stride in halves (80B rows)
#define OP_BYTES (128 * STR * 2)    // 10240 per operand
#define STAGE (2 * OP_BYTES)        // 20480
#define GEMM_SMEM (2 * STAGE)       // 40960
#define LNSTRIDE 132
#define W2_SMEM (128 * LNSTRIDE * 4)  // 67584 (LN staging)

__device__ __forceinline__ void mma_f16(float* c, const uint32_t* a, const uint32_t* b) {
    asm volatile(
        "mma.sync.aligned.m16n8k16.row.col.f32.f16.f16.f32 "
        "{%0,%1,%2,%3}, {%4,%5,%6,%7}, {%8,%9}, {%0,%1,%2,%3};\n"
        : "+f"(c[0]), "+f"(c[1]), "+f"(c[2]), "+f"(c[3])
        : "r"(a[0]), "r"(a[1]), "r"(a[2]), "r"(a[3]), "r"(b[0]), "r"(b[1]));
}

__device__ __forceinline__ void cp16(void* s, const void* g, bool valid) {
    uint32_t sa = (uint32_t)__cvta_generic_to_shared(s);
    int sz = valid ? 16 : 0;
    asm volatile("cp.async.cg.shared.global [%0], [%1], 16, %2;" ::"r"(sa), "l"(g), "r"(sz));
}

// MODE: 0 = fp16 store (+PReLU), 1 = bf16 store (kvoff<0: plain; else kv-interleaved),
//       2 = fused residual+LayerNorm (fp32 out)
template <int MODE, bool PRELU>
__device__ __forceinline__ void gemm_body(const __half* __restrict__ A,
                                          const __half* __restrict__ Bt,
                                          const float* __restrict__ bias,
                                          const float* __restrict__ alpha,
                                          float* __restrict__ C,
                                          __nv_bfloat16* __restrict__ Cb, int kvoff,
                                          __half* __restrict__ Ch,
                                          const float* __restrict__ res,
                                          const float* __restrict__ lng,
                                          const float* __restrict__ lnb, int M, int N,
                                          int K) {
    extern __shared__ char smem[];
    const int tid = threadIdx.x;
    const int lane = tid & 31;
    const int wid = tid >> 5;
    const int wm = wid & 1;
    const int wn = wid >> 1;
    const int tg = lane >> 2;
    const int tc = lane & 3;

    const int row0 = blockIdx.x * TBM;
    const int col0 = blockIdx.y * TBN;
    const int T = K / TBK;

    float acc[4][4][4];
#pragma unroll
    for (int mt = 0; mt < 4; mt++)
#pragma unroll
        for (int nt = 0; nt < 4; nt++)
#pragma unroll
            for (int r = 0; r < 4; r++) acc[mt][nt][r] = 0.0f;

    auto fill = [&](int t) {
        char* st = smem + (t & 1) * STAGE;
        char* sb = st + OP_BYTES;
        const int k0 = t * TBK;
#pragma unroll
        for (int p = 0; p < 2; p++) {
            int idx = tid + p * 256;
            int r = idx >> 2, c8 = (idx & 3) * 8;
            int gr = row0 + r;
            cp16(st + r * 80 + c8 * 2, A + (size_t)gr * K + k0 + c8, gr < M);
            cp16(sb + r * 80 + c8 * 2, Bt + (size_t)(col0 + r) * K + k0 + c8, true);
        }
        asm volatile("cp.async.commit_group;");
    };

    fill(0);

    for (int t = 0; t < T; t++) {
        if (t + 1 < T) {
            fill(t + 1);
            asm volatile("cp.async.wait_group 1;");
        } else {
            asm volatile("cp.async.wait_group 0;");
        }
        __syncthreads();

        const char* st = smem + (t & 1) * STAGE;
        const __half* sA = (const __half*)st;
        const __half* sB = (const __half*)(st + OP_BYTES);

#pragma unroll
        for (int ks = 0; ks < 2; ks++) {
            const int kb = ks * 16;
            uint32_t af[4][4], bf[4][2];
#pragma unroll
            for (int mt = 0; mt < 4; mt++) {
                int mrow = wm * 64 + mt * 16;
                af[mt][0] = *(const uint32_t*)&sA[(mrow + tg) * STR + kb + 2 * tc];
                af[mt][1] = *(const uint32_t*)&sA[(mrow + tg + 8) * STR + kb + 2 * tc];
                af[mt][2] = *(const uint32_t*)&sA[(mrow + tg) * STR + kb + 2 * tc + 8];
                af[mt][3] = *(const uint32_t*)&sA[(mrow + tg + 8) * STR + kb + 2 * tc + 8];
            }
#pragma unroll
            for (int nt = 0; nt < 4; nt++) {
                int ncol = wn * 32 + nt * 8 + tg;
                bf[nt][0] = *(const uint32_t*)&sB[ncol * STR + kb + 2 * tc];
                bf[nt][1] = *(const uint32_t*)&sB[ncol * STR + kb + 2 * tc + 8];
            }
#pragma unroll
            for (int mt = 0; mt < 4; mt++)
#pragma unroll
                for (int nt = 0; nt < 4; nt++) mma_f16(acc[mt][nt], af[mt], bf[nt]);
        }
        __syncthreads();
    }

    if (MODE == 2) {
        float* se = (float*)smem;
#pragma unroll
        for (int mt = 0; mt < 4; mt++) {
#pragma unroll
            for (int nt = 0; nt < 4; nt++) {
                int lc = wn * 32 + nt * 8 + tc * 2;
                int gc = col0 + lc;
                float b0 = bias[gc], b1 = bias[gc + 1];
                int lr = wm * 64 + mt * 16 + tg;
                int gr = row0 + lr;
                if (gr < M) {
                    float2 rr = *(const float2*)(res + (size_t)gr * N + gc);
                    se[lr * LNSTRIDE + lc] = acc[mt][nt][0] + b0 + rr.x;
                    se[lr * LNSTRIDE + lc + 1] = acc[mt][nt][1] + b1 + rr.y;
                }
                if (gr + 8 < M) {
                    float2 rr = *(const float2*)(res + (size_t)(gr + 8) * N + gc);
                    se[(lr + 8) * LNSTRIDE + lc] = acc[mt][nt][2] + b0 + rr.x;
                    se[(lr + 8) * LNSTRIDE + lc + 1] = acc[mt][nt][3] + b1 + rr.y;
                }
            }
        }
        __syncthreads();
        float4 gv = *(const float4*)(lng + lane * 4);
        float4 bv = *(const float4*)(lnb + lane * 4);
#pragma unroll
        for (int r = 0; r < 16; r++) {
            int lrow = wid * 16 + r;
            int grow = row0 + lrow;
            if (grow >= M) continue;
            float4 vx = *(const float4*)&se[lrow * LNSTRIDE + lane * 4];
            float s = vx.x + vx.y + vx.z + vx.w;
            float s2 = vx.x * vx.x + vx.y * vx.y + vx.z * vx.z + vx.w * vx.w;
#pragma unroll
            for (int o = 16; o > 0; o >>= 1) {
                s += __shfl_xor_sync(0xffffffffu, s, o);
                s2 += __shfl_xor_sync(0xffffffffu, s2, o);
            }
            float mean = s * (1.0f / D);
            float var = s2 * (1.0f / D) - mean * mean;
            float rstd = rsqrtf(var + 1e-5f);
            float4 o;
            o.x = (vx.x - mean) * rstd * gv.x + bv.x;
            o.y = (vx.y - mean) * rstd * gv.y + bv.y;
            o.z = (vx.z - mean) * rstd * gv.z + bv.z;
            o.w = (vx.w - mean) * rstd * gv.w + bv.w;
            *(float4*)(C + (size_t)grow * N + lane * 4) = o;
        }
        return;
    }

#pragma unroll
    for (int mt = 0; mt < 4; mt++) {
#pragma unroll
        for (int nt = 0; nt < 4; nt++) {
            int gc = col0 + wn * 32 + nt * 8 + tc * 2;
            float b0 = bias[gc], b1 = bias[gc + 1];
            float v0 = acc[mt][nt][0] + b0;
            float v1 = acc[mt][nt][1] + b1;
            float v2 = acc[mt][nt][2] + b0;
            float v3 = acc[mt][nt][3] + b1;
            if (PRELU) {
                float a0 = alpha[gc], a1 = alpha[gc + 1];
                v0 = v0 > 0.f ? v0 : a0 * v0;
                v1 = v1 > 0.f ? v1 : a1 * v1;
                v2 = v2 > 0.f ? v2 : a0 * v2;
                v3 = v3 > 0.f ? v3 : a1 * v3;
            }
            int gr = row0 + wm * 64 + mt * 16 + tg;
            if (MODE == 1) {
                if (kvoff < 0) {
                    if (gr < M)
                        *(__nv_bfloat162*)(Cb + (size_t)gr * N + gc) =
                            __floats2bfloat162_rn(v0, v1);
                    if (gr + 8 < M)
                        *(__nv_bfloat162*)(Cb + (size_t)(gr + 8) * N + gc) =
                            __floats2bfloat162_rn(v2, v3);
                } else {
                    int cc = ((gc >> 2) << 3) + (gc & 3) + kvoff;
                    if (gr < M)
                        *(__nv_bfloat162*)(Cb + (size_t)gr * 2 * D + cc) =
                            __floats2bfloat162_rn(v0, v1);
                    if (gr + 8 < M)
                        *(__nv_bfloat162*)(Cb + (size_t)(gr + 8) * 2 * D + cc) =
                            __floats2bfloat162_rn(v2, v3);
                }
            } else {
                if (gr < M)
                    *(__half2*)(Ch + (size_t)gr * N + gc) = __floats2half2_rn(v0, v1);
                if (gr + 8 < M)
                    *(__half2*)(Ch + (size_t)(gr + 8) * N + gc) = __floats2half2_rn(v2, v3);
            }
        }
    }
}

// fused q/k/v projection: blockIdx.z selects weight/bias/output
__global__ __launch_bounds__(256, 2) void qkv_gemm(
    const __half* __restrict__ A, const __half* __restrict__ Wtq,
    const __half* __restrict__ Wtk, const __half* __restrict__ Wtv,
    const float* __restrict__ bq, const float* __restrict__ bk,
    const float* __restrict__ bv, __nv_bfloat16* __restrict__ q16,
    __nv_bfloat16* __restrict__ kv, int M) {
    const __half* Bt = (blockIdx.z == 0) ? Wtq : (blockIdx.z == 1) ? Wtk : Wtv;
    const float* bias = (blockIdx.z == 0) ? bq : (blockIdx.z == 1) ? bk : bv;
    __nv_bfloat16* Cb = (blockIdx.z == 0) ? q16 : kv;
    int kvoff = (blockIdx.z == 0) ? -1 : (blockIdx.z == 1) ? 0 : 4;
    gemm_body<1, false>(A, Bt, bias, nullptr, nullptr, Cb, kvoff, nullptr, nullptr, nullptr,
                        nullptr, M, D, D);
}

// W1: fp16 A (rstln16) -> fp16 out (hb16) + PReLU
__global__ __launch_bounds__(256, 2) void w1_gemm(
    const __half* __restrict__ A, const __half* __restrict__ Bt,
    const float* __restrict__ bias, const float* __restrict__ alpha,
    __half* __restrict__ C, int M) {
    gemm_body<0, true>(A, Bt, bias, alpha, nullptr, nullptr, -1, C, nullptr, nullptr,
                       nullptr, M, F, D);
}

// W2: fp16 A (hb16) + residual(fp32) + LN2 -> final output
__global__ __launch_bounds__(256, 2) void w2_ln_gemm(
    const __half* __restrict__ A, const __half* __restrict__ Bt,
    const float* __restrict__ bias, const float* __restrict__ res,
    const float* __restrict__ lng, const float* __restrict__ lnb, float* __restrict__ out,
    int M) {
    gemm_body<2, false>(A, Bt, bias, nullptr, out, nullptr, -1, nullptr, res, lng, lnb, M,
                        D, F);
}

// ---------------- conversions -------------------------------------------------
__global__ void cvt_feat16(const float* __restrict__ in, __half* __restrict__ out, int n) {
    int base = (blockIdx.x * 256 + threadIdx.x) * 8;
    if (base >= n) return;
    float4 a = *(const float4*)(in + base);
    float4 b = *(const float4*)(in + base + 4);
    __half2 h0 = __floats2half2_rn(a.x, a.y), h1 = __floats2half2_rn(a.z, a.w);
    __half2 h2 = __floats2half2_rn(b.x, b.y), h3 = __floats2half2_rn(b.z, b.w);
    *(uint4*)(out + base) =
        make_uint4(*reinterpret_cast<uint32_t*>(&h0), *reinterpret_cast<uint32_t*>(&h1),
                   *reinterpret_cast<uint32_t*>(&h2), *reinterpret_cast<uint32_t*>(&h3));
}

// all 5 weight transposes in one launch: out[n*K+k] = (half)in[k*N+n]
__global__ void cvt_w_all(const float* __restrict__ Wq, const float* __restrict__ Wk,
                          const float* __restrict__ Wv, const float* __restrict__ W1,
                          const float* __restrict__ W2, __half* __restrict__ wtq,
                          __half* __restrict__ wtk, __half* __restrict__ wtv,
                          __half* __restrict__ wt1, __half* __restrict__ wt2) {
    int idx = blockIdx.x * 256 + threadIdx.x;
    const int S = D * D;        // 16384
    const int SF = F * D;       // 65536
    const float* in;
    __half* out;
    int K, N, local;
    if (idx < S) {
        in = Wq; out = wtq; K = D; N = D; local = idx;
    } else if (idx < 2 * S) {
        in = Wk; out = wtk; K = D; N = D; local = idx - S;
    } else if (idx < 3 * S) {
        in = Wv; out = wtv; K = D; N = D; local = idx - 2 * S;
    } else if (idx < 3 * S + SF) {
        in = W1; out = wt1; K = D; N = F; local = idx - 3 * S;
    } else if (idx < 3 * S + 2 * SF) {
        in = W2; out = wt2; K = F; N = D; local = idx - 3 * S - SF;
    } else {
        return;
    }
    int n = local / K;
    int k = local - n * K;
    out[local] = __float2half(in[(size_t)k * N + n]);
}

// ---------------- CSR build --------------------------------------------------
__global__ void hist_kernel(const int* __restrict__ dst, int* __restrict__ counts, int E) {
    int i = blockIdx.x * blockDim.x + threadIdx.x;
    if (i < E) atomicAdd(&counts[dst[i]], 1);
}

__global__ void scan1_kernel(const int* __restrict__ counts, int* __restrict__ rowptr,
                             int* __restrict__ bsums, int n) {
    __shared__ int wsum[8];
    int base = blockIdx.x * 1024 + threadIdx.x * 4;
    int lane = threadIdx.x & 31, wid = threadIdx.x >> 5;
    int v[4];
#pragma unroll
    for (int i = 0; i < 4; i++) v[i] = (base + i < n) ? counts[base + i] : 0;
    int t = v[0] + v[1] + v[2] + v[3];
    int sc = t;
#pragma unroll
    for (int o = 1; o < 32; o <<= 1) {
        int x = __shfl_up_sync(0xffffffffu, sc, o);
        if (lane >= o) sc += x;
    }
    if (lane == 31) wsum[wid] = sc;
    __syncthreads();
    if (wid == 0) {
        int ws = (lane < 8) ? wsum[lane] : 0;
#pragma unroll
        for (int o = 1; o < 8; o <<= 1) {
            int x = __shfl_up_sync(0xffffffffu, ws, o);
            if (lane >= o) ws += x;
        }
        if (lane < 8) wsum[lane] = ws;
    }
    __syncthreads();
    int run = sc - t + (wid > 0 ? wsum[wid - 1] : 0);
#pragma unroll
    for (int i = 0; i < 4; i++) {
        if (base + i < n) rowptr[base + i] = run;
        run += v[i];
    }
    if (threadIdx.x == 0) bsums[blockIdx.x] = wsum[7];
}

__global__ void scan2_kernel(int* __restrict__ bsums, int nb) {
    if (threadIdx.x == 0 && blockIdx.x == 0) {
        int run = 0;
        for (int i = 0; i < nb; i++) {
            int t = bsums[i];
            bsums[i] = run;
            run += t;
        }
    }
}

__global__ void scan3_kernel(int* __restrict__ rowptr, int* __restrict__ wp,
                             const int* __restrict__ bsums, int n, int E) {
    int i = blockIdx.x * blockDim.x + threadIdx.x;
    if (i < n) {
        int v = rowptr[i] + bsums[i >> 10];
        rowptr[i] = v;
        wp[i] = v;
    }
    if (i == 0) rowptr[n] = E;
}

__global__ void fill_kernel(const int* __restrict__ src, const int* __restrict__ dst,
                            int* __restrict__ wp, int* __restrict__ srcl, int E) {
    int i = blockIdx.x * blockDim.x + threadIdx.x;
    if (i >= E) return;
    int pos = atomicAdd(&wp[dst[i]], 1);
    srcl[pos] = src[i];
}

// ---------------- fused per-node attention + LN1 ----------------------------
__device__ __forceinline__ float2 bf2f(uint32_t u) {
    return __bfloat1622float2(*reinterpret_cast<__nv_bfloat162*>(&u));
}

__global__ __launch_bounds__(256) void node_attn_ln(
    const __nv_bfloat16* __restrict__ q, const __nv_bfloat16* __restrict__ kv,
    const int* __restrict__ rowptr, const int* __restrict__ srcl,
    const float* __restrict__ feat, const float* __restrict__ g,
    const float* __restrict__ b, float* __restrict__ out, __half* __restrict__ out16,
    int n) {
    int node = blockIdx.x * 8 + (threadIdx.x >> 5);
    if (node >= n) return;
    int lane = threadIdx.x & 31;

    uint2 qraw = *(const uint2*)(q + (size_t)node * D + lane * 4);
    float2 q0 = bf2f(qraw.x);
    float2 q1 = bf2f(qraw.y);

    int start = rowptr[node], end = rowptr[node + 1];

    float a0 = 0.f, a1 = 0.f, a2 = 0.f, a3 = 0.f, den = 0.f;

    for (int eb = start; eb < end; eb += 32) {
        int me = eb + lane;
        int sid = (me < end) ? srcl[me] : 0;
        int cnt = min(32, end - eb);
        int j = 0;
        for (; j + 4 <= cnt; j += 4) {
            int s0 = __shfl_sync(0xffffffffu, sid, j);
            int s1 = __shfl_sync(0xffffffffu, sid, j + 1);
            int s2 = __shfl_sync(0xffffffffu, sid, j + 2);
            int s3 = __shfl_sync(0xffffffffu, sid, j + 3);
            uint4 x0 = *(const uint4*)(kv + (size_t)s0 * 2 * D + lane * 8);
            uint4 x1 = *(const uint4*)(kv + (size_t)s1 * 2 * D + lane * 8);
            uint4 x2 = *(const uint4*)(kv + (size_t)s2 * 2 * D + lane * 8);
            uint4 x3 = *(const uint4*)(kv + (size_t)s3 * 2 * D + lane * 8);
            float2 ka, kb2;
            float p0, p1, p2, p3;
            ka = bf2f(x0.x); kb2 = bf2f(x0.y);
            p0 = ka.x * q0.x + ka.y * q0.y + kb2.x * q1.x + kb2.y * q1.y;
            ka = bf2f(x1.x); kb2 = bf2f(x1.y);
            p1 = ka.x * q0.x + ka.y * q0.y + kb2.x * q1.x + kb2.y * q1.y;
            ka = bf2f(x2.x); kb2 = bf2f(x2.y);
            p2 = ka.x * q0.x + ka.y * q0.y + kb2.x * q1.x + kb2.y * q1.y;
            ka = bf2f(x3.x); kb2 = bf2f(x3.y);
            p3 = ka.x * q0.x + ka.y * q0.y + kb2.x * q1.x + kb2.y * q1.y;
            p0 += __shfl_xor_sync(0xffffffffu, p0, 1);
            p1 += __shfl_xor_sync(0xffffffffu, p1, 1);
            p2 += __shfl_xor_sync(0xffffffffu, p2, 1);
            p3 += __shfl_xor_sync(0xffffffffu, p3, 1);
            p0 += __shfl_xor_sync(0xffffffffu, p0, 2);
            p1 += __shfl_xor_sync(0xffffffffu, p1, 2);
            p2 += __shfl_xor_sync(0xffffffffu, p2, 2);
            p3 += __shfl_xor_sync(0xffffffffu, p3, 2);
            float e0 = __expf(p0 * 0.08838834764831843f);
            float e1 = __expf(p1 * 0.08838834764831843f);
            float e2 = __expf(p2 * 0.08838834764831843f);
            float e3 = __expf(p3 * 0.08838834764831843f);
            den += (e0 + e1) + (e2 + e3);
            float2 va, vb2;
            va = bf2f(x0.z); vb2 = bf2f(x0.w);
            a0 += va.x * e0; a1 += va.y * e0; a2 += vb2.x * e0; a3 += vb2.y * e0;
            va = bf2f(x1.z); vb2 = bf2f(x1.w);
            a0 += va.x * e1; a1 += va.y * e1; a2 += vb2.x * e1; a3 += vb2.y * e1;
            va = bf2f(x2.z); vb2 = bf2f(x2.w);
            a0 += va.x * e2; a1 += va.y * e2; a2 += vb2.x * e2; a3 += vb2.y * e2;
            va = bf2f(x3.z); vb2 = bf2f(x3.w);
            a0 += va.x * e3; a1 += va.y * e3; a2 += vb2.x * e3; a3 += vb2.y * e3;
        }
        for (; j < cnt; j++) {
            int s = __shfl_sync(0xffffffffu, sid, j);
            uint4 x = *(const uint4*)(kv + (size_t)s * 2 * D + lane * 8);
            float2 k0 = bf2f(x.x), k1 = bf2f(x.y);
            float p = k0.x * q0.x + k0.y * q0.y + k1.x * q1.x + k1.y * q1.y;
            p += __shfl_xor_sync(0xffffffffu, p, 1);
            p += __shfl_xor_sync(0xffffffffu, p, 2);
            float ex = __expf(p * 0.08838834764831843f);
            den += ex;
            float2 v0 = bf2f(x.z), v1 = bf2f(x.w);
            a0 += v0.x * ex;
            a1 += v0.y * ex;
            a2 += v1.x * ex;
            a3 += v1.y * ex;
        }
    }

    float inv = den > 0.f ? 1.0f / den : 0.0f;
    float4 fv = *(const float4*)(feat + (size_t)node * D + lane * 4);
    float r0 = a0 * inv + fv.x;
    float r1 = a1 * inv + fv.y;
    float r2 = a2 * inv + fv.z;
    float r3 = a3 * inv + fv.w;

    float s = r0 + r1 + r2 + r3;
    float s2 = r0 * r0 + r1 * r1 + r2 * r2 + r3 * r3;
#pragma unroll
    for (int o = 16; o > 0; o >>= 1) {
        s += __shfl_xor_sync(0xffffffffu, s, o);
        s2 += __shfl_xor_sync(0xffffffffu, s2, o);
    }
    float mean = s * (1.0f / D);
    float var = s2 * (1.0f / D) - mean * mean;
    float rstd = rsqrtf(var + 1e-5f);
    float4 gv = *(const float4*)(g + lane * 4);
    float4 bv = *(const float4*)(b + lane * 4);
    float4 o;
    o.x = (r0 - mean) * rstd * gv.x + bv.x;
    o.y = (r1 - mean) * rstd * gv.y + bv.y;
    o.z = (r2 - mean) * rstd * gv.z + bv.z;
    o.w = (r3 - mean) * rstd * gv.w + bv.w;
    *(float4*)(out + (size_t)node * D + lane * 4) = o;
    __half2 h0 = __floats2half2_rn(o.x, o.y);
    __half2 h1 = __floats2half2_rn(o.z, o.w);
    uint2 hp =
        make_uint2(*reinterpret_cast<uint32_t*>(&h0), *reinterpret_cast<uint32_t*>(&h1));
    *(uint2*)(out16 + (size_t)node * D + lane * 4) = hp;
}

// ---------------- launch ----------------------------------------------------
extern "C" void kernel_launch(void* const* d_in, const int* in_sizes, int n_in,
                              void* d_out, int out_size) {
    const float* feat = (const float*)d_in[0];
    const int* src = (const int*)d_in[1];
    const int* dst = (const int*)d_in[2];
    const float* Wq = (const float*)d_in[3];
    const float* bq = (const float*)d_in[4];
    const float* Wk = (const float*)d_in[5];
    const float* bk = (const float*)d_in[6];
    const float* Wv = (const float*)d_in[7];
    const float* bv = (const float*)d_in[8];
    const float* ln_g = (const float*)d_in[9];
    const float* ln_b = (const float*)d_in[10];
    const float* W1 = (const float*)d_in[11];
    const float* b1 = (const float*)d_in[12];
    const float* alpha = (const float*)d_in[13];
    const float* W2 = (const float*)d_in[14];
    const float* b2 = (const float*)d_in[15];

    const int N = in_sizes[0] / D;
    const int E = in_sizes[1];

    __nv_bfloat16 *q16, *kv;
    __half *feat16, *rstln16, *hb16, *wtq, *wtk, *wtv, *wt1, *wt2;
    float* rstln;
    int *counts, *rowptr, *wp, *srcl, *bsums;
    cudaGetSymbolAddress((void**)&feat16, g_feat16);
    cudaGetSymbolAddress((void**)&q16, g_q16);
    cudaGetSymbolAddress((void**)&kv, g_kv);
    cudaGetSymbolAddress((void**)&rstln, g_rstln);
    cudaGetSymbolAddress((void**)&rstln16, g_rstln16);
    cudaGetSymbolAddress((void**)&hb16, g_h16);
    cudaGetSymbolAddress((void**)&wtq, g_wtq);
    cudaGetSymbolAddress((void**)&wtk, g_wtk);
    cudaGetSymbolAddress((void**)&wtv, g_wtv);
    cudaGetSymbolAddress((void**)&wt1, g_wt1);
    cudaGetSymbolAddress((void**)&wt2, g_wt2);
    cudaGetSymbolAddress((void**)&counts, g_counts);
    cudaGetSymbolAddress((void**)&rowptr, g_rowptr);
    cudaGetSymbolAddress((void**)&wp, g_wp);
    cudaGetSymbolAddress((void**)&srcl, g_srcl);
    cudaGetSymbolAddress((void**)&bsums, g_bsums);

    static cudaStream_t s1 = nullptr;
    static cudaEvent_t evFork = nullptr, evCsr = nullptr;
    static int attr_set = 0;
    if (!attr_set) {
        cudaFuncSetAttribute(qkv_gemm, cudaFuncAttributeMaxDynamicSharedMemorySize,
                             GEMM_SMEM);
        cudaFuncSetAttribute(w1_gemm, cudaFuncAttributeMaxDynamicSharedMemorySize, GEMM_SMEM);
        cudaFuncSetAttribute(w2_ln_gemm, cudaFuncAttributeMaxDynamicSharedMemorySize,
                             W2_SMEM);
        cudaStreamCreateWithFlags(&s1, cudaStreamNonBlocking);
        cudaEventCreateWithFlags(&evFork, cudaEventDisableTiming);
        cudaEventCreateWithFlags(&evCsr, cudaEventDisableTiming);
        attr_set = 1;
    }

    const int mgrid = (N + TBM - 1) / TBM;
    const int nb = (N + 1023) / 1024;
    const int wtot = 3 * D * D + 2 * F * D;

    // ---- fork: CSR build on side stream, overlapped with conversions + qkv
    cudaEventRecord(evFork, 0);
    cudaStreamWaitEvent(s1, evFork, 0);
    cudaMemsetAsync(counts, 0, (size_t)N * sizeof(int), s1);
    hist_kernel<<<(E + 255) / 256, 256, 0, s1>>>(dst, counts, E);
    scan1_kernel<<<nb, 256, 0, s1>>>(counts, rowptr, bsums, N);
    scan2_kernel<<<1, 32, 0, s1>>>(bsums, nb);
    scan3_kernel<<<(N + 255) / 256, 256, 0, s1>>>(rowptr, wp, bsums, N, E);
    fill_kernel<<<(E + 255) / 256, 256, 0, s1>>>(src, dst, wp, srcl, E);
    cudaEventRecord(evCsr, s1);

    // ---- main stream: conversions then qkv
    cvt_feat16<<<(N * D / 8 + 255) / 256, 256>>>(feat, feat16, N * D);
    cvt_w_all<<<(wtot + 255) / 256, 256>>>(Wq, Wk, Wv, W1, W2, wtq, wtk, wtv, wt1, wt2);

    qkv_gemm<<<dim3(mgrid, 1, 3), 256, GEMM_SMEM>>>(feat16, wtq, wtk, wtv, bq, bk, bv, q16,
                                                    kv, N);

    // ---- join: node_attn needs CSR
    cudaStreamWaitEvent(0, evCsr, 0);
    node_attn_ln<<<(N + 7) / 8, 256>>>(q16, kv, rowptr, srcl, feat, ln_g, ln_b, rstln,
                                       rstln16, N);

    // ---- FFN: W1 (fp16, +PReLU), then W2 + residual + LN2 -> final output
    w1_gemm<<<dim3(mgrid, F / TBN), 256, GEMM_SMEM>>>(rstln16, wt1, b1, alpha, hb16, N);
    w2_ln_gemm<<<dim3(mgrid, 1), 256, W2_SMEM>>>(hb16, wt2, b2, rstln, ln_g, ln_b,
                                                 (float*)d_out, N);
}

// round 14
// speedup vs baseline: 5.3414x; 1.0001x over previous
#include <cuda_runtime.h>
#include <cuda_bf16.h>
#include <cuda_fp16.h>
#include <math.h>
#include <stdint.h>

#define NODES_MAX 100000
#define EDGES_MAX 1600000
#define D 128
#define H 8
#define F 512

// ---------------- scratch (static device globals; no allocation allowed) ----
__device__ __half g_feat16[NODES_MAX * D];
__device__ __nv_bfloat16 g_q16[NODES_MAX * D];
__device__ __nv_bfloat16 g_kv[NODES_MAX * 2 * D];  // interleaved k/v per 4-elem chunk
__device__ float g_rstln[NODES_MAX * D];
__device__ __half g_rstln16[NODES_MAX * D];
__device__ __half g_h16[NODES_MAX * F];
// fp16 transposed weights [N][K]
__device__ __half g_wtq[D * D];
__device__ __half g_wtk[D * D];
__device__ __half g_wtv[D * D];
__device__ __half g_wt1[F * D];
__device__ __half g_wt2[D * F];
// CSR build
__device__ int g_counts[NODES_MAX];
__device__ int g_rowptr[NODES_MAX + 1];
__device__ int g_wp[NODES_MAX];
__device__ int g_srcl[EDGES_MAX];
__device__ int g_bsums[256];

// ---------------- fp16 tensor-core GEMM core, cp.async double-buffered ------
#define TBM 128
#define TBN 128
#define TBK 32
#define STR 40                      // smem stride in halves (80B rows)
#define OP_BYTES (128 * STR * 2)    // 10240 per operand
#define STAGE (2 * OP_BYTES)        // 20480
#define GEMM_SMEM (2 * STAGE)       // 40960
#define LNSTRIDE 132
#define W2_SMEM (128 * LNSTRIDE * 4)  // 67584 (LN staging)

__device__ __forceinline__ void mma_f16(float* c, const uint32_t* a, const uint32_t* b) {
    asm volatile(
        "mma.sync.aligned.m16n8k16.row.col.f32.f16.f16.f32 "
        "{%0,%1,%2,%3}, {%4,%5,%6,%7}, {%8,%9}, {%0,%1,%2,%3};\n"
        : "+f"(c[0]), "+f"(c[1]), "+f"(c[2]), "+f"(c[3])
        : "r"(a[0]), "r"(a[1]), "r"(a[2]), "r"(a[3]), "r"(b[0]), "r"(b[1]));
}

__device__ __forceinline__ void cp16(void* s, const void* g, bool valid) {
    uint32_t sa = (uint32_t)__cvta_generic_to_shared(s);
    int sz = valid ? 16 : 0;
    asm volatile("cp.async.cg.shared.global [%0], [%1], 16, %2;" ::"r"(sa), "l"(g), "r"(sz));
}

// MODE: 0 = fp16 store (+PReLU), 1 = bf16 store (kvoff<0: plain; else kv-interleaved),
//       2 = fused residual+LayerNorm (fp32 out)
template <int MODE, bool PRELU>
__device__ __forceinline__ void gemm_body(const __half* __restrict__ A,
                                          const __half* __restrict__ Bt,
                                          const float* __restrict__ bias,
                                          const float* __restrict__ alpha,
                                          float* __restrict__ C,
                                          __nv_bfloat16* __restrict__ Cb, int kvoff,
                                          __half* __restrict__ Ch,
                                          const float* __restrict__ res,
                                          const float* __restrict__ lng,
                                          const float* __restrict__ lnb, int M, int N,
                                          int K) {
    extern __shared__ char smem[];
    const int tid = threadIdx.x;
    const int lane = tid & 31;
    const int wid = tid >> 5;
    const int wm = wid & 1;
    const int wn = wid >> 1;
    const int tg = lane >> 2;
    const int tc = lane & 3;

    const int row0 = blockIdx.x * TBM;
    const int col0 = blockIdx.y * TBN;
    const int T = K / TBK;

    float acc[4][4][4];
#pragma unroll
    for (int mt = 0; mt < 4; mt++)
#pragma unroll
        for (int nt = 0; nt < 4; nt++)
#pragma unroll
            for (int r = 0; r < 4; r++) acc[mt][nt][r] = 0.0f;

    auto fill = [&](int t) {
        char* st = smem + (t & 1) * STAGE;
        char* sb = st + OP_BYTES;
        const int k0 = t * TBK;
#pragma unroll
        for (int p = 0; p < 2; p++) {
            int idx = tid + p * 256;
            int r = idx >> 2, c8 = (idx & 3) * 8;
            int gr = row0 + r;
            cp16(st + r * 80 + c8 * 2, A + (size_t)gr * K + k0 + c8, gr < M);
            cp16(sb + r * 80 + c8 * 2, Bt + (size_t)(col0 + r) * K + k0 + c8, true);
        }
        asm volatile("cp.async.commit_group;");
    };

    fill(0);

    for (int t = 0; t < T; t++) {
        if (t + 1 < T) {
            fill(t + 1);
            asm volatile("cp.async.wait_group 1;");
        } else {
            asm volatile("cp.async.wait_group 0;");
        }
        __syncthreads();

        const char* st = smem + (t & 1) * STAGE;
        const __half* sA = (const __half*)st;
        const __half* sB = (const __half*)(st + OP_BYTES);

#pragma unroll
        for (int ks = 0; ks < 2; ks++) {
            const int kb = ks * 16;
            uint32_t af[4][4], bf[4][2];
#pragma unroll
            for (int mt = 0; mt < 4; mt++) {
                int mrow = wm * 64 + mt * 16;
                af[mt][0] = *(const uint32_t*)&sA[(mrow + tg) * STR + kb + 2 * tc];
                af[mt][1] = *(const uint32_t*)&sA[(mrow + tg + 8) * STR + kb + 2 * tc];
                af[mt][2] = *(const uint32_t*)&sA[(mrow + tg) * STR + kb + 2 * tc + 8];
                af[mt][3] = *(const uint32_t*)&sA[(mrow + tg + 8) * STR + kb + 2 * tc + 8];
            }
#pragma unroll
            for (int nt = 0; nt < 4; nt++) {
                int ncol = wn * 32 + nt * 8 + tg;
                bf[nt][0] = *(const uint32_t*)&sB[ncol * STR + kb + 2 * tc];
                bf[nt][1] = *(const uint32_t*)&sB[ncol * STR + kb + 2 * tc + 8];
            }
#pragma unroll
            for (int mt = 0; mt < 4; mt++)
#pragma unroll
                for (int nt = 0; nt < 4; nt++) mma_f16(acc[mt][nt], af[mt], bf[nt]);
        }
        __syncthreads();
    }

    if (MODE == 2) {
        float* se = (float*)smem;
#pragma unroll
        for (int mt = 0; mt < 4; mt++) {
#pragma unroll
            for (int nt = 0; nt < 4; nt++) {
                int lc = wn * 32 + nt * 8 + tc * 2;
                int gc = col0 + lc;
                float b0 = bias[gc], b1 = bias[gc + 1];
                int lr = wm * 64 + mt * 16 + tg;
                int gr = row0 + lr;
                if (gr < M) {
                    float2 rr = *(const float2*)(res + (size_t)gr * N + gc);
                    se[lr * LNSTRIDE + lc] = acc[mt][nt][0] + b0 + rr.x;
                    se[lr * LNSTRIDE + lc + 1] = acc[mt][nt][1] + b1 + rr.y;
                }
                if (gr + 8 < M) {
                    float2 rr = *(const float2*)(res + (size_t)(gr + 8) * N + gc);
                    se[(lr + 8) * LNSTRIDE + lc] = acc[mt][nt][2] + b0 + rr.x;
                    se[(lr + 8) * LNSTRIDE + lc + 1] = acc[mt][nt][3] + b1 + rr.y;
                }
            }
        }
        __syncthreads();
        float4 gv = *(const float4*)(lng + lane * 4);
        float4 bv = *(const float4*)(lnb + lane * 4);
#pragma unroll
        for (int r = 0; r < 16; r++) {
            int lrow = wid * 16 + r;
            int grow = row0 + lrow;
            if (grow >= M) continue;
            float4 vx = *(const float4*)&se[lrow * LNSTRIDE + lane * 4];
            float s = vx.x + vx.y + vx.z + vx.w;
            float s2 = vx.x * vx.x + vx.y * vx.y + vx.z * vx.z + vx.w * vx.w;
#pragma unroll
            for (int o = 16; o > 0; o >>= 1) {
                s += __shfl_xor_sync(0xffffffffu, s, o);
                s2 += __shfl_xor_sync(0xffffffffu, s2, o);
            }
            float mean = s * (1.0f / D);
            float var = s2 * (1.0f / D) - mean * mean;
            float rstd = rsqrtf(var + 1e-5f);
            float4 o;
            o.x = (vx.x - mean) * rstd * gv.x + bv.x;
            o.y = (vx.y - mean) * rstd * gv.y + bv.y;
            o.z = (vx.z - mean) * rstd * gv.z + bv.z;
            o.w = (vx.w - mean) * rstd * gv.w + bv.w;
            *(float4*)(C + (size_t)grow * N + lane * 4) = o;
        }
        return;
    }

#pragma unroll
    for (int mt = 0; mt < 4; mt++) {
#pragma unroll
        for (int nt = 0; nt < 4; nt++) {
            int gc = col0 + wn * 32 + nt * 8 + tc * 2;
            float b0 = bias[gc], b1 = bias[gc + 1];
            float v0 = acc[mt][nt][0] + b0;
            float v1 = acc[mt][nt][1] + b1;
            float v2 = acc[mt][nt][2] + b0;
            float v3 = acc[mt][nt][3] + b1;
            if (PRELU) {
                float a0 = alpha[gc], a1 = alpha[gc + 1];
                v0 = v0 > 0.f ? v0 : a0 * v0;
                v1 = v1 > 0.f ? v1 : a1 * v1;
                v2 = v2 > 0.f ? v2 : a0 * v2;
                v3 = v3 > 0.f ? v3 : a1 * v3;
            }
            int gr = row0 + wm * 64 + mt * 16 + tg;
            if (MODE == 1) {
                if (kvoff < 0) {
                    if (gr < M)
                        *(__nv_bfloat162*)(Cb + (size_t)gr * N + gc) =
                            __floats2bfloat162_rn(v0, v1);
                    if (gr + 8 < M)
                        *(__nv_bfloat162*)(Cb + (size_t)(gr + 8) * N + gc) =
                            __floats2bfloat162_rn(v2, v3);
                } else {
                    int cc = ((gc >> 2) << 3) + (gc & 3) + kvoff;
                    if (gr < M)
                        *(__nv_bfloat162*)(Cb + (size_t)gr * 2 * D + cc) =
                            __floats2bfloat162_rn(v0, v1);
                    if (gr + 8 < M)
                        *(__nv_bfloat162*)(Cb + (size_t)(gr + 8) * 2 * D + cc) =
                            __floats2bfloat162_rn(v2, v3);
                }
            } else {
                if (gr < M)
                    *(__half2*)(Ch + (size_t)gr * N + gc) = __floats2half2_rn(v0, v1);
                if (gr + 8 < M)
                    *(__half2*)(Ch + (size_t)(gr + 8) * N + gc) = __floats2half2_rn(v2, v3);
            }
        }
    }
}

// fused q/k/v projection: blockIdx.z selects weight/bias/output
__global__ __launch_bounds__(256, 2) void qkv_gemm(
    const __half* __restrict__ A, const __half* __restrict__ Wtq,
    const __half* __restrict__ Wtk, const __half* __restrict__ Wtv,
    const float* __restrict__ bq, const float* __restrict__ bk,
    const float* __restrict__ bv, __nv_bfloat16* __restrict__ q16,
    __nv_bfloat16* __restrict__ kv, int M) {
    const __half* Bt = (blockIdx.z == 0) ? Wtq : (blockIdx.z == 1) ? Wtk : Wtv;
    const float* bias = (blockIdx.z == 0) ? bq : (blockIdx.z == 1) ? bk : bv;
    __nv_bfloat16* Cb = (blockIdx.z == 0) ? q16 : kv;
    int kvoff = (blockIdx.z == 0) ? -1 : (blockIdx.z == 1) ? 0 : 4;
    gemm_body<1, false>(A, Bt, bias, nullptr, nullptr, Cb, kvoff, nullptr, nullptr, nullptr,
                        nullptr, M, D, D);
}

// W1: fp16 A (rstln16) -> fp16 out (hb16) + PReLU
__global__ __launch_bounds__(256, 2) void w1_gemm(
    const __half* __restrict__ A, const __half* __restrict__ Bt,
    const float* __restrict__ bias, const float* __restrict__ alpha,
    __half* __restrict__ C, int M) {
    gemm_body<0, true>(A, Bt, bias, alpha, nullptr, nullptr, -1, C, nullptr, nullptr,
                       nullptr, M, F, D);
}

// W2: fp16 A (hb16) + residual(fp32) + LN2 -> final output
__global__ __launch_bounds__(256, 2) void w2_ln_gemm(
    const __half* __restrict__ A, const __half* __restrict__ Bt,
    const float* __restrict__ bias, const float* __restrict__ res,
    const float* __restrict__ lng, const float* __restrict__ lnb, float* __restrict__ out,
    int M) {
    gemm_body<2, false>(A, Bt, bias, nullptr, out, nullptr, -1, nullptr, res, lng, lnb, M,
                        D, F);
}

// ---------------- conversions -------------------------------------------------
__global__ void cvt_feat16(const float* __restrict__ in, __half* __restrict__ out, int n) {
    int base = (blockIdx.x * 256 + threadIdx.x) * 8;
    if (base >= n) return;
    float4 a = *(const float4*)(in + base);
    float4 b = *(const float4*)(in + base + 4);
    __half2 h0 = __floats2half2_rn(a.x, a.y), h1 = __floats2half2_rn(a.z, a.w);
    __half2 h2 = __floats2half2_rn(b.x, b.y), h3 = __floats2half2_rn(b.z, b.w);
    *(uint4*)(out + base) =
        make_uint4(*reinterpret_cast<uint32_t*>(&h0), *reinterpret_cast<uint32_t*>(&h1),
                   *reinterpret_cast<uint32_t*>(&h2), *reinterpret_cast<uint32_t*>(&h3));
}

// all 5 weight transposes in one launch: out[n*K+k] = (half)in[k*N+n]
__global__ void cvt_w_all(const float* __restrict__ Wq, const float* __restrict__ Wk,
                          const float* __restrict__ Wv, const float* __restrict__ W1,
                          const float* __restrict__ W2, __half* __restrict__ wtq,
                          __half* __restrict__ wtk, __half* __restrict__ wtv,
                          __half* __restrict__ wt1, __half* __restrict__ wt2) {
    int idx = blockIdx.x * 256 + threadIdx.x;
    const int S = D * D;        // 16384
    const int SF = F * D;       // 65536
    const float* in;
    __half* out;
    int K, N, local;
    if (idx < S) {
        in = Wq; out = wtq; K = D; N = D; local = idx;
    } else if (idx < 2 * S) {
        in = Wk; out = wtk; K = D; N = D; local = idx - S;
    } else if (idx < 3 * S) {
        in = Wv; out = wtv; K = D; N = D; local = idx - 2 * S;
    } else if (idx < 3 * S + SF) {
        in = W1; out = wt1; K = D; N = F; local = idx - 3 * S;
    } else if (idx < 3 * S + 2 * SF) {
        in = W2; out = wt2; K = F; N = D; local = idx - 3 * S - SF;
    } else {
        return;
    }
    int n = local / K;
    int k = local - n * K;
    out[local] = __float2half(in[(size_t)k * N + n]);
}

// ---------------- CSR build --------------------------------------------------
__global__ void hist_kernel(const int* __restrict__ dst, int* __restrict__ counts, int E) {
    int i = blockIdx.x * blockDim.x + threadIdx.x;
    if (i < E) atomicAdd(&counts[dst[i]], 1);
}

__global__ void scan1_kernel(const int* __restrict__ counts, int* __restrict__ rowptr,
                             int* __restrict__ bsums, int n) {
    __shared__ int wsum[8];
    int base = blockIdx.x * 1024 + threadIdx.x * 4;
    int lane = threadIdx.x & 31, wid = threadIdx.x >> 5;
    int v[4];
#pragma unroll
    for (int i = 0; i < 4; i++) v[i] = (base + i < n) ? counts[base + i] : 0;
    int t = v[0] + v[1] + v[2] + v[3];
    int sc = t;
#pragma unroll
    for (int o = 1; o < 32; o <<= 1) {
        int x = __shfl_up_sync(0xffffffffu, sc, o);
        if (lane >= o) sc += x;
    }
    if (lane == 31) wsum[wid] = sc;
    __syncthreads();
    if (wid == 0) {
        int ws = (lane < 8) ? wsum[lane] : 0;
#pragma unroll
        for (int o = 1; o < 8; o <<= 1) {
            int x = __shfl_up_sync(0xffffffffu, ws, o);
            if (lane >= o) ws += x;
        }
        if (lane < 8) wsum[lane] = ws;
    }
    __syncthreads();
    int run = sc - t + (wid > 0 ? wsum[wid - 1] : 0);
#pragma unroll
    for (int i = 0; i < 4; i++) {
        if (base + i < n) rowptr[base + i] = run;
        run += v[i];
    }
    if (threadIdx.x == 0) bsums[blockIdx.x] = wsum[7];
}

__global__ void scan2_kernel(int* __restrict__ bsums, int nb) {
    if (threadIdx.x == 0 && blockIdx.x == 0) {
        int run = 0;
        for (int i = 0; i < nb; i++) {
            int t = bsums[i];
            bsums[i] = run;
            run += t;
        }
    }
}

__global__ void scan3_kernel(int* __restrict__ rowptr, int* __restrict__ wp,
                             const int* __restrict__ bsums, int n, int E) {
    int i = blockIdx.x * blockDim.x + threadIdx.x;
    if (i < n) {
        int v = rowptr[i] + bsums[i >> 10];
        rowptr[i] = v;
        wp[i] = v;
    }
    if (i == 0) rowptr[n] = E;
}

__global__ void fill_kernel(const int* __restrict__ src, const int* __restrict__ dst,
                            int* __restrict__ wp, int* __restrict__ srcl, int E) {
    int i = blockIdx.x * blockDim.x + threadIdx.x;
    if (i >= E) return;
    int pos = atomicAdd(&wp[dst[i]], 1);
    srcl[pos] = src[i];
}

// ---------------- fused per-node attention + LN1 ----------------------------
__device__ __forceinline__ float2 bf2f(uint32_t u) {
    return __bfloat1622float2(*reinterpret_cast<__nv_bfloat162*>(&u));
}

__global__ __launch_bounds__(256) void node_attn_ln(
    const __nv_bfloat16* __restrict__ q, const __nv_bfloat16* __restrict__ kv,
    const int* __restrict__ rowptr, const int* __restrict__ srcl,
    const float* __restrict__ feat, const float* __restrict__ g,
    const float* __restrict__ b, float* __restrict__ out, __half* __restrict__ out16,
    int n) {
    int node = blockIdx.x * 8 + (threadIdx.x >> 5);
    if (node >= n) return;
    int lane = threadIdx.x & 31;

    uint2 qraw = *(const uint2*)(q + (size_t)node * D + lane * 4);
    float2 q0 = bf2f(qraw.x);
    float2 q1 = bf2f(qraw.y);

    int start = rowptr[node], end = rowptr[node + 1];

    float a0 = 0.f, a1 = 0.f, a2 = 0.f, a3 = 0.f, den = 0.f;

    for (int eb = start; eb < end; eb += 32) {
        int me = eb + lane;
        int sid = (me < end) ? srcl[me] : 0;
        int cnt = min(32, end - eb);
        int j = 0;
        for (; j + 4 <= cnt; j += 4) {
            int s0 = __shfl_sync(0xffffffffu, sid, j);
            int s1 = __shfl_sync(0xffffffffu, sid, j + 1);
            int s2 = __shfl_sync(0xffffffffu, sid, j + 2);
            int s3 = __shfl_sync(0xffffffffu, sid, j + 3);
            uint4 x0 = *(const uint4*)(kv + (size_t)s0 * 2 * D + lane * 8);
            uint4 x1 = *(const uint4*)(kv + (size_t)s1 * 2 * D + lane * 8);
            uint4 x2 = *(const uint4*)(kv + (size_t)s2 * 2 * D + lane * 8);
            uint4 x3 = *(const uint4*)(kv + (size_t)s3 * 2 * D + lane * 8);
            float2 ka, kb2;
            float p0, p1, p2, p3;
            ka = bf2f(x0.x); kb2 = bf2f(x0.y);
            p0 = ka.x * q0.x + ka.y * q0.y + kb2.x * q1.x + kb2.y * q1.y;
            ka = bf2f(x1.x); kb2 = bf2f(x1.y);
            p1 = ka.x * q0.x + ka.y * q0.y + kb2.x * q1.x + kb2.y * q1.y;
            ka = bf2f(x2.x); kb2 = bf2f(x2.y);
            p2 = ka.x * q0.x + ka.y * q0.y + kb2.x * q1.x + kb2.y * q1.y;
            ka = bf2f(x3.x); kb2 = bf2f(x3.y);
            p3 = ka.x * q0.x + ka.y * q0.y + kb2.x * q1.x + kb2.y * q1.y;
            p0 += __shfl_xor_sync(0xffffffffu, p0, 1);
            p1 += __shfl_xor_sync(0xffffffffu, p1, 1);
            p2 += __shfl_xor_sync(0xffffffffu, p2, 1);
            p3 += __shfl_xor_sync(0xffffffffu, p3, 1);
            p0 += __shfl_xor_sync(0xffffffffu, p0, 2);
            p1 += __shfl_xor_sync(0xffffffffu, p1, 2);
            p2 += __shfl_xor_sync(0xffffffffu, p2, 2);
            p3 += __shfl_xor_sync(0xffffffffu, p3, 2);
            float e0 = __expf(p0 * 0.08838834764831843f);
            float e1 = __expf(p1 * 0.08838834764831843f);
            float e2 = __expf(p2 * 0.08838834764831843f);
            float e3 = __expf(p3 * 0.08838834764831843f);
            den += (e0 + e1) + (e2 + e3);
            float2 va, vb2;
            va = bf2f(x0.z); vb2 = bf2f(x0.w);
            a0 += va.x * e0; a1 += va.y * e0; a2 += vb2.x * e0; a3 += vb2.y * e0;
            va = bf2f(x1.z); vb2 = bf2f(x1.w);
            a0 += va.x * e1; a1 += va.y * e1; a2 += vb2.x * e1; a3 += vb2.y * e1;
            va = bf2f(x2.z); vb2 = bf2f(x2.w);
            a0 += va.x * e2; a1 += va.y * e2; a2 += vb2.x * e2; a3 += vb2.y * e2;
            va = bf2f(x3.z); vb2 = bf2f(x3.w);
            a0 += va.x * e3; a1 += va.y * e3; a2 += vb2.x * e3; a3 += vb2.y * e3;
        }
        for (; j < cnt; j++) {
            int s = __shfl_sync(0xffffffffu, sid, j);
            uint4 x = *(const uint4*)(kv + (size_t)s * 2 * D + lane * 8);
            float2 k0 = bf2f(x.x), k1 = bf2f(x.y);
            float p = k0.x * q0.x + k0.y * q0.y + k1.x * q1.x + k1.y * q1.y;
            p += __shfl_xor_sync(0xffffffffu, p, 1);
            p += __shfl_xor_sync(0xffffffffu, p, 2);
            float ex = __expf(p * 0.08838834764831843f);
            den += ex;
            float2 v0 = bf2f(x.z), v1 = bf2f(x.w);
            a0 += v0.x * ex;
            a1 += v0.y * ex;
            a2 += v1.x * ex;
            a3 += v1.y * ex;
        }
    }

    float inv = den > 0.f ? 1.0f / den : 0.0f;
    float4 fv = *(const float4*)(feat + (size_t)node * D + lane * 4);
    float r0 = a0 * inv + fv.x;
    float r1 = a1 * inv + fv.y;
    float r2 = a2 * inv + fv.z;
    float r3 = a3 * inv + fv.w;

    float s = r0 + r1 + r2 + r3;
    float s2 = r0 * r0 + r1 * r1 + r2 * r2 + r3 * r3;
#pragma unroll
    for (int o = 16; o > 0; o >>= 1) {
        s += __shfl_xor_sync(0xffffffffu, s, o);
        s2 += __shfl_xor_sync(0xffffffffu, s2, o);
    }
    float mean = s * (1.0f / D);
    float var = s2 * (1.0f / D) - mean * mean;
    float rstd = rsqrtf(var + 1e-5f);
    float4 gv = *(const float4*)(g + lane * 4);
    float4 bv = *(const float4*)(b + lane * 4);
    float4 o;
    o.x = (r0 - mean) * rstd * gv.x + bv.x;
    o.y = (r1 - mean) * rstd * gv.y + bv.y;
    o.z = (r2 - mean) * rstd * gv.z + bv.z;
    o.w = (r3 - mean) * rstd * gv.w + bv.w;
    *(float4*)(out + (size_t)node * D + lane * 4) = o;
    __half2 h0 = __floats2half2_rn(o.x, o.y);
    __half2 h1 = __floats2half2_rn(o.z, o.w);
    uint2 hp =
        make_uint2(*reinterpret_cast<uint32_t*>(&h0), *reinterpret_cast<uint32_t*>(&h1));
    *(uint2*)(out16 + (size_t)node * D + lane * 4) = hp;
}

// ---------------- launch ----------------------------------------------------
extern "C" void kernel_launch(void* const* d_in, const int* in_sizes, int n_in,
                              void* d_out, int out_size) {
    const float* feat = (const float*)d_in[0];
    const int* src = (const int*)d_in[1];
    const int* dst = (const int*)d_in[2];
    const float* Wq = (const float*)d_in[3];
    const float* bq = (const float*)d_in[4];
    const float* Wk = (const float*)d_in[5];
    const float* bk = (const float*)d_in[6];
    const float* Wv = (const float*)d_in[7];
    const float* bv = (const float*)d_in[8];
    const float* ln_g = (const float*)d_in[9];
    const float* ln_b = (const float*)d_in[10];
    const float* W1 = (const float*)d_in[11];
    const float* b1 = (const float*)d_in[12];
    const float* alpha = (const float*)d_in[13];
    const float* W2 = (const float*)d_in[14];
    const float* b2 = (const float*)d_in[15];

    const int N = in_sizes[0] / D;
    const int E = in_sizes[1];

    __nv_bfloat16 *q16, *kv;
    __half *feat16, *rstln16, *hb16, *wtq, *wtk, *wtv, *wt1, *wt2;
    float* rstln;
    int *counts, *rowptr, *wp, *srcl, *bsums;
    cudaGetSymbolAddress((void**)&feat16, g_feat16);
    cudaGetSymbolAddress((void**)&q16, g_q16);
    cudaGetSymbolAddress((void**)&kv, g_kv);
    cudaGetSymbolAddress((void**)&rstln, g_rstln);
    cudaGetSymbolAddress((void**)&rstln16, g_rstln16);
    cudaGetSymbolAddress((void**)&hb16, g_h16);
    cudaGetSymbolAddress((void**)&wtq, g_wtq);
    cudaGetSymbolAddress((void**)&wtk, g_wtk);
    cudaGetSymbolAddress((void**)&wtv, g_wtv);
    cudaGetSymbolAddress((void**)&wt1, g_wt1);
    cudaGetSymbolAddress((void**)&wt2, g_wt2);
    cudaGetSymbolAddress((void**)&counts, g_counts);
    cudaGetSymbolAddress((void**)&rowptr, g_rowptr);
    cudaGetSymbolAddress((void**)&wp, g_wp);
    cudaGetSymbolAddress((void**)&srcl, g_srcl);
    cudaGetSymbolAddress((void**)&bsums, g_bsums);

    static cudaStream_t s1 = nullptr;
    static cudaEvent_t evFork = nullptr, evCsr = nullptr;
    static int attr_set = 0;
    if (!attr_set) {
        cudaFuncSetAttribute(qkv_gemm, cudaFuncAttributeMaxDynamicSharedMemorySize,
                             GEMM_SMEM);
        cudaFuncSetAttribute(w1_gemm, cudaFuncAttributeMaxDynamicSharedMemorySize, GEMM_SMEM);
        cudaFuncSetAttribute(w2_ln_gemm, cudaFuncAttributeMaxDynamicSharedMemorySize,
                             W2_SMEM);
        cudaStreamCreateWithFlags(&s1, cudaStreamNonBlocking);
        cudaEventCreateWithFlags(&evFork, cudaEventDisableTiming);
        cudaEventCreateWithFlags(&evCsr, cudaEventDisableTiming);
        attr_set = 1;
    }

    const int mgrid = (N + TBM - 1) / TBM;
    const int nb = (N + 1023) / 1024;
    const int wtot = 3 * D * D + 2 * F * D;

    // ---- fork: CSR build on side stream, overlapped with conversions + qkv
    cudaEventRecord(evFork, 0);
    cudaStreamWaitEvent(s1, evFork, 0);
    cudaMemsetAsync(counts, 0, (size_t)N * sizeof(int), s1);
    hist_kernel<<<(E + 255) / 256, 256, 0, s1>>>(dst, counts, E);
    scan1_kernel<<<nb, 256, 0, s1>>>(counts, rowptr, bsums, N);
    scan2_kernel<<<1, 32, 0, s1>>>(bsums, nb);
    scan3_kernel<<<(N + 255) / 256, 256, 0, s1>>>(rowptr, wp, bsums, N, E);
    fill_kernel<<<(E + 255) / 256, 256, 0, s1>>>(src, dst, wp, srcl, E);
    cudaEventRecord(evCsr, s1);

    // ---- main stream: conversions then qkv
    cvt_feat16<<<(N * D / 8 + 255) / 256, 256>>>(feat, feat16, N * D);
    cvt_w_all<<<(wtot + 255) / 256, 256>>>(Wq, Wk, Wv, W1, W2, wtq, wtk, wtv, wt1, wt2);

    qkv_gemm<<<dim3(mgrid, 1, 3), 256, GEMM_SMEM>>>(feat16, wtq, wtk, wtv, bq, bk, bv, q16,
                                                    kv, N);

    // ---- join: node_attn needs CSR
    cudaStreamWaitEvent(0, evCsr, 0);
    node_attn_ln<<<(N + 7) / 8, 256>>>(q16, kv, rowptr, srcl, feat, ln_g, ln_b, rstln,
                                       rstln16, N);

    // ---- FFN: W1 (fp16, +PReLU), then W2 + residual + LN2 -> final output
    w1_gemm<<<dim3(mgrid, F / TBN), 256, GEMM_SMEM>>>(rstln16, wt1, b1, alpha, hb16, N);
    w2_ln_gemm<<<dim3(mgrid, 1), 256, W2_SMEM>>>(hb16, wt2, b2, rstln, ln_g, ln_b,
                                                 (float*)d_out, N);
}